// round 1
// baseline (speedup 1.0000x reference)
#include <cuda_runtime.h>
#include <math.h>

// Problem constants
#define BATCH 4
#define SEQ   2048
#define EMB   1024
#define HEADS 16
#define DHEAD 64
#define MROWS (BATCH*SEQ)   // 8192

// ---------- scratch (device globals per allocation rules) ----------
__device__ float g_Qt[BATCH*HEADS*DHEAD*SEQ];  // [bh][d][s]
__device__ float g_Kt[BATCH*HEADS*DHEAD*SEQ];  // [bh][d][s]
__device__ float g_Vb[BATCH*HEADS*SEQ*DHEAD];  // [bh][s][d]
__device__ float g_Ob[BATCH*SEQ*EMB];          // [b][s][e]

// ---------------------- SGEMM: C = A @ W^T + bias ----------------------
// A: [M,K] row-major, W: [N,K] row-major (nn.Linear weight), contraction over K.
#define BM 128
#define BN 128
#define BK 16
#define MODE_PLAIN 0   // C[m][n]
#define MODE_V     1   // C[((b*H+h)*S + s)*D + d]
#define MODE_T     2   // C[((b*H+h)*D + d)*S + s]

__global__ __launch_bounds__(256, 2)
void sgemm_nt(const float* __restrict__ A, const float* __restrict__ W,
              const float* __restrict__ bias, float* __restrict__ C,
              int M, int N, int K, int mode)
{
    __shared__ float As[BK][BM];
    __shared__ float Bs[BK][BN];

    const int t  = threadIdx.x;
    const int tx = t & 15;          // 0..15  -> 8 cols each
    const int ty = t >> 4;          // 0..15  -> 8 rows each
    const int bm = blockIdx.y * BM;
    const int bn = blockIdx.x * BN;

    const float* Ap = A + (size_t)bm * K;
    const float* Wp = W + (size_t)bn * K;

    float acc[8][8];
#pragma unroll
    for (int i = 0; i < 8; i++)
#pragma unroll
        for (int j = 0; j < 8; j++) acc[i][j] = 0.f;

    for (int k0 = 0; k0 < K; k0 += BK) {
        // Load 128x16 tiles of A and W, transposed into [k][m] layout.
#pragma unroll
        for (int i = 0; i < 2; i++) {
            int idx = t + i * 256;          // 0..511 (float4 index)
            int row = idx >> 2;             // 0..127
            int kc  = (idx & 3) << 2;       // 0,4,8,12
            float4 va = *(const float4*)(Ap + (size_t)row * K + k0 + kc);
            As[kc+0][row] = va.x; As[kc+1][row] = va.y;
            As[kc+2][row] = va.z; As[kc+3][row] = va.w;
            float4 vb = *(const float4*)(Wp + (size_t)row * K + k0 + kc);
            Bs[kc+0][row] = vb.x; Bs[kc+1][row] = vb.y;
            Bs[kc+2][row] = vb.z; Bs[kc+3][row] = vb.w;
        }
        __syncthreads();

#pragma unroll
        for (int k = 0; k < BK; k++) {
            float a[8], b[8];
            float4 a0 = *(const float4*)&As[k][ty*8];
            float4 a1 = *(const float4*)&As[k][ty*8+4];
            a[0]=a0.x; a[1]=a0.y; a[2]=a0.z; a[3]=a0.w;
            a[4]=a1.x; a[5]=a1.y; a[6]=a1.z; a[7]=a1.w;
            float4 b0 = *(const float4*)&Bs[k][tx*8];
            float4 b1 = *(const float4*)&Bs[k][tx*8+4];
            b[0]=b0.x; b[1]=b0.y; b[2]=b0.z; b[3]=b0.w;
            b[4]=b1.x; b[5]=b1.y; b[6]=b1.z; b[7]=b1.w;
#pragma unroll
            for (int i = 0; i < 8; i++)
#pragma unroll
                for (int j = 0; j < 8; j++)
                    acc[i][j] = fmaf(a[i], b[j], acc[i][j]);
        }
        __syncthreads();
    }

    // Epilogue
    const int row0 = bm + ty*8;
    const int col0 = bn + tx*8;
    float bv[8];
#pragma unroll
    for (int j = 0; j < 8; j++) bv[j] = bias[col0 + j];

    if (mode == MODE_PLAIN) {
#pragma unroll
        for (int i = 0; i < 8; i++) {
            float* out = C + (size_t)(row0 + i) * N + col0;
            float4 v0 = make_float4(acc[i][0]+bv[0], acc[i][1]+bv[1], acc[i][2]+bv[2], acc[i][3]+bv[3]);
            float4 v1 = make_float4(acc[i][4]+bv[4], acc[i][5]+bv[5], acc[i][6]+bv[6], acc[i][7]+bv[7]);
            *(float4*)(out)     = v0;
            *(float4*)(out + 4) = v1;
        }
    } else if (mode == MODE_V) {
        const int h  = col0 >> 6;       // 8-col chunk never crosses head boundary
        const int d0 = col0 & 63;
#pragma unroll
        for (int i = 0; i < 8; i++) {
            int m = row0 + i;
            int b = m >> 11, s = m & 2047;
            float* out = C + (((size_t)(b*HEADS + h) * SEQ + s) * DHEAD) + d0;
            float4 v0 = make_float4(acc[i][0]+bv[0], acc[i][1]+bv[1], acc[i][2]+bv[2], acc[i][3]+bv[3]);
            float4 v1 = make_float4(acc[i][4]+bv[4], acc[i][5]+bv[5], acc[i][6]+bv[6], acc[i][7]+bv[7]);
            *(float4*)(out)     = v0;
            *(float4*)(out + 4) = v1;
        }
    } else { // MODE_T: [bh][d][s]
#pragma unroll
        for (int i = 0; i < 8; i++) {
            int m = row0 + i;
            int b = m >> 11, s = m & 2047;
#pragma unroll
            for (int j = 0; j < 8; j++) {
                int n = col0 + j;
                int h = n >> 6, d = n & 63;
                C[(((size_t)(b*HEADS + h) * DHEAD + d) * SEQ) + s] = acc[i][j] + bv[j];
            }
        }
    }
}

// ---------------------- Flash attention (causal) ----------------------
// Qt,Kt: [bh][64][S] (d-major), V: [bh][S][64], O: [b][s][e]
// Grid: (SEQ/128, BATCH*HEADS). 256 threads: ty(16) x tx(16); 8 rows x 4 cols each.
#define AT_BM 128
#define AT_BN 64

__global__ __launch_bounds__(256, 2)
void attn_kernel(const float* __restrict__ Qt, const float* __restrict__ Kt,
                 const float* __restrict__ V,  float* __restrict__ O)
{
    extern __shared__ float sm[];
    float* Qs = sm;                      // [64][128]
    float* Ks = Qs + 64*AT_BM;           // [64][64]
    float* Vs = Ks + 64*AT_BN;           // [64][64]
    float* Ps = Vs + AT_BN*64;           // [128][64]

    const int t  = threadIdx.x;
    const int tx = t & 15;               // 4 cols: tx*4..+3
    const int ty = t >> 4;               // 8 rows: ty*8..+7
    const int qt = blockIdx.x;
    const int bh = blockIdx.y;

    const float* Qb = Qt + (size_t)bh * DHEAD * SEQ + qt * AT_BM;
    const float* Kb = Kt + (size_t)bh * DHEAD * SEQ;
    const float* Vb = V  + (size_t)bh * SEQ * DHEAD;

    // Load Q tile [64 d][128 r]
#pragma unroll
    for (int i = 0; i < 8; i++) {
        int idx = t + i*256;             // 0..2047 float4s
        int d   = idx >> 5;              // 0..63
        int r4  = (idx & 31) << 2;       // 0..124
        *(float4*)&Qs[d*AT_BM + r4] = *(const float4*)(Qb + (size_t)d * SEQ + r4);
    }

    float o[8][4];
    float m_run[8], l_run[8];
#pragma unroll
    for (int i = 0; i < 8; i++) {
        m_run[i] = -INFINITY; l_run[i] = 0.f;
#pragma unroll
        for (int j = 0; j < 4; j++) o[i][j] = 0.f;
    }

    const int jt_end = 2*qt + 1;
    for (int jt = 0; jt <= jt_end; jt++) {
        __syncthreads();   // prev iter's K/V/P consumed
        // Load K tile [64 d][64 c] and V tile [64 c][64 d]
#pragma unroll
        for (int i = 0; i < 4; i++) {
            int idx = t + i*256;         // 0..1023 float4s
            int a   = idx >> 4;          // 0..63
            int b4  = (idx & 15) << 2;   // 0..60
            *(float4*)&Ks[a*AT_BN + b4] = *(const float4*)(Kb + (size_t)a * SEQ + jt*AT_BN + b4);
            *(float4*)&Vs[a*DHEAD + b4] = *(const float4*)(Vb + (size_t)(jt*AT_BN + a) * DHEAD + b4);
        }
        __syncthreads();

        // S = Q K^T (scaled later)
        float s[8][4];
#pragma unroll
        for (int i = 0; i < 8; i++)
#pragma unroll
            for (int j = 0; j < 4; j++) s[i][j] = 0.f;

#pragma unroll 8
        for (int d = 0; d < 64; d++) {
            float4 q0 = *(const float4*)&Qs[d*AT_BM + ty*8];
            float4 q1 = *(const float4*)&Qs[d*AT_BM + ty*8 + 4];
            float4 kv = *(const float4*)&Ks[d*AT_BN + tx*4];
            float a[8] = {q0.x,q0.y,q0.z,q0.w,q1.x,q1.y,q1.z,q1.w};
            float b4[4] = {kv.x,kv.y,kv.z,kv.w};
#pragma unroll
            for (int i = 0; i < 8; i++)
#pragma unroll
                for (int j = 0; j < 4; j++)
                    s[i][j] = fmaf(a[i], b4[j], s[i][j]);
        }

        // scale + causal mask (only diagonal-adjacent tiles need it)
        if (jt >= 2*qt) {
#pragma unroll
            for (int i = 0; i < 8; i++) {
                int rg = qt*AT_BM + ty*8 + i;
#pragma unroll
                for (int j = 0; j < 4; j++) {
                    int cg = jt*AT_BN + tx*4 + j;
                    s[i][j] = (cg > rg) ? -INFINITY : s[i][j] * 0.125f;
                }
            }
        } else {
#pragma unroll
            for (int i = 0; i < 8; i++)
#pragma unroll
                for (int j = 0; j < 4; j++) s[i][j] *= 0.125f;
        }

        // online softmax per row (reduce across 16 lanes sharing ty)
#pragma unroll
        for (int i = 0; i < 8; i++) {
            float mx = fmaxf(fmaxf(s[i][0], s[i][1]), fmaxf(s[i][2], s[i][3]));
#pragma unroll
            for (int off = 8; off >= 1; off >>= 1)
                mx = fmaxf(mx, __shfl_xor_sync(0xffffffffu, mx, off));
            float m_new = fmaxf(m_run[i], mx);
            float alpha = __expf(m_run[i] - m_new);
            m_run[i] = m_new;
            float rs = 0.f;
#pragma unroll
            for (int j = 0; j < 4; j++) {
                float p = __expf(s[i][j] - m_new);
                s[i][j] = p;
                rs += p;
            }
#pragma unroll
            for (int off = 8; off >= 1; off >>= 1)
                rs += __shfl_xor_sync(0xffffffffu, rs, off);
            l_run[i] = l_run[i] * alpha + rs;
#pragma unroll
            for (int j = 0; j < 4; j++) o[i][j] *= alpha;
            *(float4*)&Ps[(ty*8+i)*AT_BN + tx*4] =
                make_float4(s[i][0], s[i][1], s[i][2], s[i][3]);
        }
        __syncthreads();

        // O += P V
#pragma unroll 8
        for (int c = 0; c < AT_BN; c++) {
            float4 vv = *(const float4*)&Vs[c*DHEAD + tx*4];
            float b4[4] = {vv.x, vv.y, vv.z, vv.w};
#pragma unroll
            for (int i = 0; i < 8; i++) {
                float p = Ps[(ty*8+i)*AT_BN + c];
                o[i][0] = fmaf(p, b4[0], o[i][0]);
                o[i][1] = fmaf(p, b4[1], o[i][1]);
                o[i][2] = fmaf(p, b4[2], o[i][2]);
                o[i][3] = fmaf(p, b4[3], o[i][3]);
            }
        }
    }

    // Epilogue: O[b][s][h*64+d], merge the [B,H,S,D]->[B,S,E] transpose
    const int b = bh >> 4, h = bh & 15;
#pragma unroll
    for (int i = 0; i < 8; i++) {
        int sg = qt*AT_BM + ty*8 + i;
        float inv = 1.f / l_run[i];
        float4 v = make_float4(o[i][0]*inv, o[i][1]*inv, o[i][2]*inv, o[i][3]*inv);
        *(float4*)&O[((size_t)(b*SEQ + sg)) * EMB + h*DHEAD + tx*4] = v;
    }
}

// ---------------------- launch ----------------------
extern "C" void kernel_launch(void* const* d_in, const int* in_sizes, int n_in,
                              void* d_out, int out_size)
{
    (void)in_sizes; (void)n_in; (void)out_size;
    const float* x  = (const float*)d_in[0];
    // d_in[1] = mask (int32) — causal structure is known; unused.
    const float* wq = (const float*)d_in[2];
    const float* bq = (const float*)d_in[3];
    const float* wk = (const float*)d_in[4];
    const float* bk = (const float*)d_in[5];
    const float* wv = (const float*)d_in[6];
    const float* bv = (const float*)d_in[7];
    const float* wo = (const float*)d_in[8];
    const float* bo = (const float*)d_in[9];
    float* out = (float*)d_out;

    float *qt, *kt, *vb, *ob;
    cudaGetSymbolAddress((void**)&qt, g_Qt);
    cudaGetSymbolAddress((void**)&kt, g_Kt);
    cudaGetSymbolAddress((void**)&vb, g_Vb);
    cudaGetSymbolAddress((void**)&ob, g_Ob);

    const dim3 gGrid(EMB/BN, MROWS/BM);   // (8, 64)

    sgemm_nt<<<gGrid, 256>>>(x, wq, bq, qt, MROWS, EMB, EMB, MODE_T);
    sgemm_nt<<<gGrid, 256>>>(x, wk, bk, kt, MROWS, EMB, EMB, MODE_T);
    sgemm_nt<<<gGrid, 256>>>(x, wv, bv, vb, MROWS, EMB, EMB, MODE_V);

    const int smem_bytes = (64*AT_BM + 64*AT_BN + AT_BN*64 + AT_BM*AT_BN) * sizeof(float); // 96 KB
    cudaFuncSetAttribute(attn_kernel, cudaFuncAttributeMaxDynamicSharedMemorySize, smem_bytes);
    attn_kernel<<<dim3(SEQ/AT_BM, BATCH*HEADS), 256, smem_bytes>>>(qt, kt, vb, ob);

    sgemm_nt<<<gGrid, 256>>>(ob, wo, bo, out, MROWS, EMB, EMB, MODE_PLAIN);
}

// round 3
// speedup vs baseline: 2.1499x; 2.1499x over previous
#include <cuda_runtime.h>
#include <cuda_bf16.h>
#include <mma.h>
#include <math.h>
#include <stdint.h>

using namespace nvcuda;

// Problem constants
#define BATCH 4
#define SEQ   2048
#define EMB   1024
#define HEADS 16
#define DHEAD 64
#define MROWS (BATCH*SEQ)   // 8192
#define KDIM  1024
#define NDIM  1024

#define MODE_PLAIN 0
#define MODE_V     1
#define MODE_T     2

// ---------------- scratch (device globals per allocation rules) ----------------
__device__ float g_Qt[BATCH*HEADS*DHEAD*SEQ];  // [bh][d][s]
__device__ float g_Kt[BATCH*HEADS*DHEAD*SEQ];  // [bh][d][s]
__device__ float g_Vb[BATCH*HEADS*SEQ*DHEAD];  // [bh][s][d]
__device__ float g_Ob[BATCH*SEQ*EMB];          // [b][s][e]
__device__ __nv_bfloat16 g_xh[MROWS*EMB];
__device__ __nv_bfloat16 g_xl[MROWS*EMB];
__device__ __nv_bfloat16 g_oh[MROWS*EMB];
__device__ __nv_bfloat16 g_ol[MROWS*EMB];
__device__ __nv_bfloat16 g_wh[4][EMB*EMB];
__device__ __nv_bfloat16 g_wl[4][EMB*EMB];

// ---------------- generic helpers ----------------
__device__ __forceinline__ uint32_t smem_to_u32(const void* p) {
    uint32_t a;
    asm("{ .reg .u64 tmp; cvta.to.shared.u64 tmp, %1; cvt.u32.u64 %0, tmp; }"
        : "=r"(a) : "l"(p));
    return a;
}

__device__ __forceinline__ void cp_async16(uint32_t dst, const void* src) {
    asm volatile("cp.async.cg.shared.global [%0], [%1], 16;" :: "r"(dst), "l"(src));
}
#define CP_COMMIT() asm volatile("cp.async.commit_group;" ::: "memory")
#define CP_WAIT0()  asm volatile("cp.async.wait_group 0;" ::: "memory")
#define CP_WAIT1()  asm volatile("cp.async.wait_group 1;" ::: "memory")

// ---------------- tcgen05 helpers (only compiled for *a feature targets) ----------------
#if defined(__CUDA_ARCH_FEAT_SM103_ALL) || defined(__CUDA_ARCH_FEAT_SM100_ALL)
#define HAVE_TCGEN05 1

__device__ __forceinline__ uint32_t elect_one_pred() {
    uint32_t pred;
    asm volatile(
        "{\n\t.reg .pred p;\n\t"
        "elect.sync _|p, 0xFFFFFFFF;\n\t"
        "selp.b32 %0, 1, 0, p;\n\t}"
        : "=r"(pred));
    return pred;
}

#define MBARRIER_INIT(addr, count) \
    asm volatile("mbarrier.init.shared.b64 [%0], %1;" :: "r"((uint32_t)(addr)), "r"((uint32_t)(count)) : "memory")

#define MBARRIER_WAIT_PARITY(mbar_smem_addr, phase_parity) do { \
    uint32_t _mbar = (uint32_t)(mbar_smem_addr); \
    uint32_t _parity = (uint32_t)(phase_parity); \
    uint32_t _done; \
    asm volatile( \
        "{\n\t.reg .pred p;\n\t" \
        "mbarrier.try_wait.parity.acquire.cta.shared::cta.b64 p, [%1], %2;\n\t" \
        "selp.b32 %0, 1, 0, p;\n\t}" \
        : "=r"(_done) : "r"(_mbar), "r"(_parity) : "memory"); \
    if (!_done) { \
        asm volatile( \
            "{\n\t.reg .pred P1;\n\t" \
            "WAIT_LOOP_%=:\n\t" \
            "mbarrier.try_wait.parity.acquire.cta.shared::cta.b64 P1, [%0], %1, 0x989680;\n\t" \
            "@P1 bra.uni WAIT_DONE_%=;\n\t" \
            "bra.uni WAIT_LOOP_%=;\n\t" \
            "WAIT_DONE_%=:\n\t}" \
            :: "r"(_mbar), "r"(_parity) : "memory"); \
    } \
} while(0)

#define TCGEN05_ALLOC(smem_result_addr, nCols) \
    asm volatile("tcgen05.alloc.cta_group::1.sync.aligned.shared::cta.b32 [%0], %1;" \
        :: "r"((uint32_t)(smem_result_addr)), "r"((uint32_t)(nCols)) : "memory")
#define TCGEN05_DEALLOC(tmem_addr, nCols) \
    asm volatile("tcgen05.dealloc.cta_group::1.sync.aligned.b32 %0, %1;" :: "r"(tmem_addr), "r"(nCols))
#define TCGEN05_RELINQUISH_ALLOC_PERMIT() \
    asm volatile("tcgen05.relinquish_alloc_permit.cta_group::1.sync.aligned;")
#define TCGEN05_COMMIT(mbar_smem_addr) \
    asm volatile("tcgen05.commit.cta_group::1.mbarrier::arrive::one.shared::cluster.b64 [%0];" \
        :: "r"((uint32_t)(mbar_smem_addr)) : "memory")
#define TCGEN05_FENCE_AFTER() \
    asm volatile("tcgen05.fence::after_thread_sync;" ::: "memory")
#define TCGEN05_WAIT_LD() \
    asm volatile("tcgen05.wait::ld.sync.aligned;" ::: "memory")
#define FENCE_PROXY_ASYNC_SHARED_CTA() \
    asm volatile("fence.proxy.async.shared::cta;" ::: "memory")

#define TCGEN05_LD_32X32B_X32(r, tmem_addr) \
    asm volatile( \
        "tcgen05.ld.sync.aligned.32x32b.x32.b32 " \
        "{%0, %1, %2, %3, %4, %5, %6, %7, " \
        " %8, %9, %10, %11, %12, %13, %14, %15, " \
        " %16, %17, %18, %19, %20, %21, %22, %23, " \
        " %24, %25, %26, %27, %28, %29, %30, %31}, [%32];" \
        : "=r"((r)[0]),  "=r"((r)[1]),  "=r"((r)[2]),  "=r"((r)[3]), \
          "=r"((r)[4]),  "=r"((r)[5]),  "=r"((r)[6]),  "=r"((r)[7]), \
          "=r"((r)[8]),  "=r"((r)[9]),  "=r"((r)[10]), "=r"((r)[11]), \
          "=r"((r)[12]), "=r"((r)[13]), "=r"((r)[14]), "=r"((r)[15]), \
          "=r"((r)[16]), "=r"((r)[17]), "=r"((r)[18]), "=r"((r)[19]), \
          "=r"((r)[20]), "=r"((r)[21]), "=r"((r)[22]), "=r"((r)[23]), \
          "=r"((r)[24]), "=r"((r)[25]), "=r"((r)[26]), "=r"((r)[27]), \
          "=r"((r)[28]), "=r"((r)[29]), "=r"((r)[30]), "=r"((r)[31]) \
        : "r"(tmem_addr))

static constexpr uint64_t SMEM_DESC_BASE_SW128 =
    (uint64_t(2)  << 61) | (uint64_t(1) << 46) | (uint64_t(64) << 32) | (uint64_t(1) << 16);
#define MAKE_SMEM_DESC(base_addr) \
    (SMEM_DESC_BASE_SW128 | ((uint64_t)((base_addr) >> 4) & 0x3FFF))

__device__ __forceinline__ void mma_f16_ss(uint32_t d_tmem, uint64_t a_desc, uint64_t b_desc,
                                           uint32_t idesc, bool enable_d) {
    uint32_t en = enable_d ? 1u : 0u;
    asm volatile(
        "{\n\t.reg .pred p;\n\t"
        "setp.ne.u32 p, %4, 0;\n\t"
        "tcgen05.mma.cta_group::1.kind::f16 [%0], %1, %2, %3, {%5, %5, %5, %5}, p;\n\t}"
        :: "r"(d_tmem), "l"(a_desc), "l"(b_desc), "r"(idesc), "r"(en), "r"(0u)
        : "memory");
}

// idesc: c=F32, a=BF16, b=BF16, M=128, N=128
#define MMA_IDESC ((1u<<4) | (1u<<7) | (1u<<10) | ((128u/8u)<<17) | ((128u/16u)<<24))
#endif  // tcgen05 feature

// ---------------- fp32 -> bf16 hi/lo split ----------------
__global__ void split_bf16(const float* __restrict__ in, __nv_bfloat16* __restrict__ hi,
                           __nv_bfloat16* __restrict__ lo, int n4)
{
    int i = blockIdx.x * blockDim.x + threadIdx.x;
    if (i >= n4) return;
    float4 v = ((const float4*)in)[i];
    __nv_bfloat16 h0 = __float2bfloat16(v.x);
    __nv_bfloat16 h1 = __float2bfloat16(v.y);
    __nv_bfloat16 h2 = __float2bfloat16(v.z);
    __nv_bfloat16 h3 = __float2bfloat16(v.w);
    __nv_bfloat16 l0 = __float2bfloat16(v.x - __bfloat162float(h0));
    __nv_bfloat16 l1 = __float2bfloat16(v.y - __bfloat162float(h1));
    __nv_bfloat16 l2 = __float2bfloat16(v.z - __bfloat162float(h2));
    __nv_bfloat16 l3 = __float2bfloat16(v.w - __bfloat162float(h3));
    ((__nv_bfloat162*)hi)[2*i]   = __nv_bfloat162(h0, h1);
    ((__nv_bfloat162*)hi)[2*i+1] = __nv_bfloat162(h2, h3);
    ((__nv_bfloat162*)lo)[2*i]   = __nv_bfloat162(l0, l1);
    ((__nv_bfloat162*)lo)[2*i+1] = __nv_bfloat162(l2, l3);
}

// ---------------- GEMM: C = (Ah+Al) @ (Bh+Bl)^T + bias (drop lo*lo) ----------------
// A: [8192,1024] bf16 hi/lo, B: [1024,1024] bf16 hi/lo. CTA tile 128x128, K-chunk 64.
//
// Fallback (wmma/HMMA) smem: [0,1024) unused ctrl | 2 stages x 4 tiles x (128 rows x 72 bf16)
// tcgen05 smem:              [0,1024) ctrl        | 2 stages x 4 tiles x (128 rows x 64 bf16, SW128)

#define LDP        72                      // padded row length (bf16 elems), 144B stride
#define TILE_P     (128*LDP*2)             // 18432 B
#define STAGE_P    (4*TILE_P)              // 73728 B
#define GEMM_SMEM_DYN (1024 + 2*STAGE_P)   // 148480 B

__global__ void __launch_bounds__(256, 1)
mma_gemm(const __nv_bfloat16* __restrict__ Ah, const __nv_bfloat16* __restrict__ Al,
         const __nv_bfloat16* __restrict__ Bh, const __nv_bfloat16* __restrict__ Bl,
         const float* __restrict__ bias, float* __restrict__ C, int mode)
{
    extern __shared__ __align__(1024) char smem[];
    const uint32_t smem_u = smem_to_u32(smem);
    const int t   = threadIdx.x;
    const int bm  = blockIdx.y * 128;
    const int bn  = blockIdx.x * 128;

#if defined(HAVE_TCGEN05)
    // ================= tcgen05 path (only if an 'a' arch pass exists) =================
    const int wid = t >> 5;
    if (wid == 0) TCGEN05_ALLOC(smem_u + 0, 128);
    if (t == 0) { MBARRIER_INIT(smem_u + 8, 1); MBARRIER_INIT(smem_u + 16, 1); }
    __syncthreads();
    uint32_t tmem;
    asm volatile("ld.shared.b32 %0, [%1];" : "=r"(tmem) : "r"(smem_u));

    for (int ic = 0; ic < 16; ic++) {
        const int s = ic & 1;
        const uint32_t tb = 1024 + s * 65536;
        if (ic >= 2)
            MBARRIER_WAIT_PARITY(smem_u + 8 + s * 8, ((ic >> 1) - 1) & 1);
        const int kc = ic * 64;
        const __nv_bfloat16* srcs[4] = {Ah, Al, Bh, Bl};
        const int r0s[4] = {bm, bm, bn, bn};
#pragma unroll
        for (int tl = 0; tl < 4; tl++) {
#pragma unroll
            for (int j = 0; j < 4; j++) {
                int idx = t + j * 256;
                int r   = idx >> 3;
                int c   = (idx & 7) * 8;
                uint32_t off = (uint32_t)(r * 128 + c * 2);
                uint32_t sw  = off ^ ((off >> 3) & 0x70);
                *(float4*)(smem + tb + tl*16384 + sw) =
                    *(const float4*)(srcs[tl] + (size_t)(r0s[tl] + r) * KDIM + kc + c);
            }
        }
        FENCE_PROXY_ASYNC_SHARED_CTA();
        __syncthreads();
        if (wid == 0 && elect_one_pred()) {
            uint64_t dah = MAKE_SMEM_DESC(smem_u + tb);
            uint64_t dal = MAKE_SMEM_DESC(smem_u + tb + 16384);
            uint64_t dbh = MAKE_SMEM_DESC(smem_u + tb + 2*16384);
            uint64_t dbl = MAKE_SMEM_DESC(smem_u + tb + 3*16384);
#pragma unroll
            for (int k = 0; k < 4; k++) {
                mma_f16_ss(tmem, dah + k*2, dbh + k*2, MMA_IDESC, !(ic == 0 && k == 0));
                mma_f16_ss(tmem, dah + k*2, dbl + k*2, MMA_IDESC, true);
                mma_f16_ss(tmem, dal + k*2, dbh + k*2, MMA_IDESC, true);
            }
            TCGEN05_COMMIT(smem_u + 8 + s * 8);
        }
    }
    MBARRIER_WAIT_PARITY(smem_u + 8, 1);
    MBARRIER_WAIT_PARITY(smem_u + 16, 1);
    TCGEN05_FENCE_AFTER();

    if (t < 128) {
        const int gm = bm + t;
        const int b  = gm >> 11, sq = gm & 2047;
#pragma unroll 1
        for (int p = 0; p < 4; p++) {
            uint32_t r[32];
            TCGEN05_LD_32X32B_X32(r, tmem + p * 32);
            TCGEN05_WAIT_LD();
            const int c0 = bn + p * 32;
            if (mode == MODE_PLAIN) {
                float* out = C + (size_t)gm * NDIM + c0;
#pragma unroll
                for (int j = 0; j < 32; j += 4)
                    *(float4*)(out + j) = make_float4(
                        __uint_as_float(r[j])   + bias[c0+j],
                        __uint_as_float(r[j+1]) + bias[c0+j+1],
                        __uint_as_float(r[j+2]) + bias[c0+j+2],
                        __uint_as_float(r[j+3]) + bias[c0+j+3]);
            } else if (mode == MODE_V) {
                const int h = c0 >> 6, d0 = c0 & 63;
                float* out = C + (((size_t)(b*HEADS + h) * SEQ + sq) * DHEAD) + d0;
#pragma unroll
                for (int j = 0; j < 32; j += 4)
                    *(float4*)(out + j) = make_float4(
                        __uint_as_float(r[j])   + bias[c0+j],
                        __uint_as_float(r[j+1]) + bias[c0+j+1],
                        __uint_as_float(r[j+2]) + bias[c0+j+2],
                        __uint_as_float(r[j+3]) + bias[c0+j+3]);
            } else {
#pragma unroll
                for (int j = 0; j < 32; j++) {
                    const int n = c0 + j, h = n >> 6, d = n & 63;
                    C[(((size_t)(b*HEADS + h) * DHEAD + d) * SEQ) + sq] =
                        __uint_as_float(r[j]) + bias[n];
                }
            }
        }
    }
    __syncthreads();
    if (wid == 0) {
        TCGEN05_RELINQUISH_ALLOC_PERMIT();
        TCGEN05_DEALLOC(tmem, 128);
    }
#else
    // ================= wmma / HMMA fallback (arch-generic PTX) =================
    const int wid = t >> 5;
    const int wm  = wid >> 2;        // 0..1 -> 64 rows
    const int wn  = wid & 3;         // 0..3 -> 32 cols
    const int m0  = wm * 64;
    const int n0  = wn * 32;

    wmma::fragment<wmma::accumulator, 16, 16, 16, float> acc[4][2];
#pragma unroll
    for (int i = 0; i < 4; i++)
#pragma unroll
        for (int j = 0; j < 2; j++) wmma::fill_fragment(acc[i][j], 0.f);

    const __nv_bfloat16* srcs[4] = {Ah, Al, Bh, Bl};
    const int r0s[4] = {bm, bm, bn, bn};

    // async-load one K-chunk stage: 4 tiles of 128x64 bf16 into padded rows
    auto load_stage = [&](int s, int ic) {
        const uint32_t sb = smem_u + 1024 + (uint32_t)s * STAGE_P;
        const int kc = ic * 64;
#pragma unroll
        for (int tl = 0; tl < 4; tl++) {
            const __nv_bfloat16* g = srcs[tl] + (size_t)r0s[tl] * KDIM + kc;
#pragma unroll
            for (int j = 0; j < 4; j++) {
                int idx = t + j * 256;            // 0..1023
                int r   = idx >> 3;               // 0..127
                int c16 = idx & 7;                // 16B chunk within 128B row
                cp_async16(sb + (uint32_t)(tl*TILE_P + r*144 + c16*16),
                           g + (size_t)r * KDIM + c16*8);
            }
        }
        CP_COMMIT();
    };

    load_stage(0, 0);

    for (int ic = 0; ic < 16; ic++) {
        if (ic + 1 < 16) load_stage((ic + 1) & 1, ic + 1);
        if (ic + 1 < 16) { CP_WAIT1(); } else { CP_WAIT0(); }
        __syncthreads();

        const char* sb = smem + 1024 + (size_t)(ic & 1) * STAGE_P;
        const __nv_bfloat16* Ahs = (const __nv_bfloat16*)(sb);
        const __nv_bfloat16* Als = (const __nv_bfloat16*)(sb + TILE_P);
        const __nv_bfloat16* Bhs = (const __nv_bfloat16*)(sb + 2*TILE_P);
        const __nv_bfloat16* Bls = (const __nv_bfloat16*)(sb + 3*TILE_P);

#pragma unroll
        for (int k0 = 0; k0 < 64; k0 += 16) {
            wmma::fragment<wmma::matrix_a, 16, 16, 16, __nv_bfloat16, wmma::row_major> aH[4], aL[4];
            wmma::fragment<wmma::matrix_b, 16, 16, 16, __nv_bfloat16, wmma::col_major> bF[2];
#pragma unroll
            for (int i = 0; i < 4; i++)
                wmma::load_matrix_sync(aH[i], Ahs + (m0 + 16*i) * LDP + k0, LDP);
#pragma unroll
            for (int j = 0; j < 2; j++)
                wmma::load_matrix_sync(bF[j], Bhs + (n0 + 16*j) * LDP + k0, LDP);
            // hi * hi
#pragma unroll
            for (int i = 0; i < 4; i++)
#pragma unroll
                for (int j = 0; j < 2; j++)
                    wmma::mma_sync(acc[i][j], aH[i], bF[j], acc[i][j]);
            // lo * hi
#pragma unroll
            for (int i = 0; i < 4; i++)
                wmma::load_matrix_sync(aL[i], Als + (m0 + 16*i) * LDP + k0, LDP);
#pragma unroll
            for (int i = 0; i < 4; i++)
#pragma unroll
                for (int j = 0; j < 2; j++)
                    wmma::mma_sync(acc[i][j], aL[i], bF[j], acc[i][j]);
            // hi * lo
#pragma unroll
            for (int j = 0; j < 2; j++)
                wmma::load_matrix_sync(bF[j], Bls + (n0 + 16*j) * LDP + k0, LDP);
#pragma unroll
            for (int i = 0; i < 4; i++)
#pragma unroll
                for (int j = 0; j < 2; j++)
                    wmma::mma_sync(acc[i][j], aH[i], bF[j], acc[i][j]);
        }
        __syncthreads();
    }

    // Epilogue: stage the 128x128 fp32 tile through smem (ld = 132), then scatter
    float* Cs = (float*)smem;
#pragma unroll
    for (int i = 0; i < 4; i++)
#pragma unroll
        for (int j = 0; j < 2; j++)
            wmma::store_matrix_sync(Cs + (m0 + 16*i) * 132 + n0 + 16*j, acc[i][j],
                                    132, wmma::mem_row_major);
    __syncthreads();

    if (mode == MODE_T) {
        const int n  = t >> 1;                 // tile-local col 0..127
        const int s0 = (t & 1) * 64;           // row half
        const int gn = bn + n, h = gn >> 6, d = gn & 63;
        const float bv = bias[gn];
        const int gm0 = bm + s0;
        const int b = gm0 >> 11, sq0 = gm0 & 2047;
        float* out = C + (((size_t)(b*HEADS + h) * DHEAD + d) * SEQ) + sq0;
#pragma unroll 8
        for (int r = 0; r < 64; r++)
            out[r] = Cs[(s0 + r) * 132 + n] + bv;
    } else {
        const int r  = t >> 1;
        const int c0 = (t & 1) * 64;
        const int gm = bm + r;
        const int b = gm >> 11, sq = gm & 2047;
        float* out;
        if (mode == MODE_PLAIN) {
            out = C + (size_t)gm * NDIM + bn + c0;
        } else { // MODE_V: 64-col half = exactly one head
            const int h = (bn + c0) >> 6;
            out = C + (((size_t)(b*HEADS + h) * SEQ + sq) * DHEAD);
        }
        const float* row = Cs + r * 132 + c0;
        const float* bp  = bias + bn + c0;
#pragma unroll
        for (int j = 0; j < 64; j += 4)
            *(float4*)(out + j) = make_float4(row[j]   + bp[j],
                                              row[j+1] + bp[j+1],
                                              row[j+2] + bp[j+2],
                                              row[j+3] + bp[j+3]);
    }
#endif
}

// ---------------- Flash attention (causal, fp32) — unchanged ----------------
#define AT_BM 128
#define AT_BN 64

__global__ __launch_bounds__(256, 2)
void attn_kernel(const float* __restrict__ Qt, const float* __restrict__ Kt,
                 const float* __restrict__ V,  float* __restrict__ O)
{
    extern __shared__ float sm[];
    float* Qs = sm;
    float* Ks = Qs + 64*AT_BM;
    float* Vs = Ks + 64*AT_BN;
    float* Ps = Vs + AT_BN*64;

    const int t  = threadIdx.x;
    const int tx = t & 15;
    const int ty = t >> 4;
    const int qt = blockIdx.x;
    const int bh = blockIdx.y;

    const float* Qb = Qt + (size_t)bh * DHEAD * SEQ + qt * AT_BM;
    const float* Kb = Kt + (size_t)bh * DHEAD * SEQ;
    const float* Vb = V  + (size_t)bh * SEQ * DHEAD;

#pragma unroll
    for (int i = 0; i < 8; i++) {
        int idx = t + i*256;
        int d   = idx >> 5;
        int r4  = (idx & 31) << 2;
        *(float4*)&Qs[d*AT_BM + r4] = *(const float4*)(Qb + (size_t)d * SEQ + r4);
    }

    float o[8][4];
    float m_run[8], l_run[8];
#pragma unroll
    for (int i = 0; i < 8; i++) {
        m_run[i] = -INFINITY; l_run[i] = 0.f;
#pragma unroll
        for (int j = 0; j < 4; j++) o[i][j] = 0.f;
    }

    const int jt_end = 2*qt + 1;
    for (int jt = 0; jt <= jt_end; jt++) {
        __syncthreads();
#pragma unroll
        for (int i = 0; i < 4; i++) {
            int idx = t + i*256;
            int a   = idx >> 4;
            int b4  = (idx & 15) << 2;
            *(float4*)&Ks[a*AT_BN + b4] = *(const float4*)(Kb + (size_t)a * SEQ + jt*AT_BN + b4);
            *(float4*)&Vs[a*DHEAD + b4] = *(const float4*)(Vb + (size_t)(jt*AT_BN + a) * DHEAD + b4);
        }
        __syncthreads();

        float s[8][4];
#pragma unroll
        for (int i = 0; i < 8; i++)
#pragma unroll
            for (int j = 0; j < 4; j++) s[i][j] = 0.f;

#pragma unroll 8
        for (int d = 0; d < 64; d++) {
            float4 q0 = *(const float4*)&Qs[d*AT_BM + ty*8];
            float4 q1 = *(const float4*)&Qs[d*AT_BM + ty*8 + 4];
            float4 kv = *(const float4*)&Ks[d*AT_BN + tx*4];
            float a[8] = {q0.x,q0.y,q0.z,q0.w,q1.x,q1.y,q1.z,q1.w};
            float b4[4] = {kv.x,kv.y,kv.z,kv.w};
#pragma unroll
            for (int i = 0; i < 8; i++)
#pragma unroll
                for (int j = 0; j < 4; j++)
                    s[i][j] = fmaf(a[i], b4[j], s[i][j]);
        }

        if (jt >= 2*qt) {
#pragma unroll
            for (int i = 0; i < 8; i++) {
                int rg = qt*AT_BM + ty*8 + i;
#pragma unroll
                for (int j = 0; j < 4; j++) {
                    int cg = jt*AT_BN + tx*4 + j;
                    s[i][j] = (cg > rg) ? -INFINITY : s[i][j] * 0.125f;
                }
            }
        } else {
#pragma unroll
            for (int i = 0; i < 8; i++)
#pragma unroll
                for (int j = 0; j < 4; j++) s[i][j] *= 0.125f;
        }

#pragma unroll
        for (int i = 0; i < 8; i++) {
            float mx = fmaxf(fmaxf(s[i][0], s[i][1]), fmaxf(s[i][2], s[i][3]));
#pragma unroll
            for (int off = 8; off >= 1; off >>= 1)
                mx = fmaxf(mx, __shfl_xor_sync(0xffffffffu, mx, off));
            float m_new = fmaxf(m_run[i], mx);
            float alpha = __expf(m_run[i] - m_new);
            m_run[i] = m_new;
            float rs = 0.f;
#pragma unroll
            for (int j = 0; j < 4; j++) {
                float p = __expf(s[i][j] - m_new);
                s[i][j] = p;
                rs += p;
            }
#pragma unroll
            for (int off = 8; off >= 1; off >>= 1)
                rs += __shfl_xor_sync(0xffffffffu, rs, off);
            l_run[i] = l_run[i] * alpha + rs;
#pragma unroll
            for (int j = 0; j < 4; j++) o[i][j] *= alpha;
            *(float4*)&Ps[(ty*8+i)*AT_BN + tx*4] =
                make_float4(s[i][0], s[i][1], s[i][2], s[i][3]);
        }
        __syncthreads();

#pragma unroll 8
        for (int c = 0; c < AT_BN; c++) {
            float4 vv = *(const float4*)&Vs[c*DHEAD + tx*4];
            float b4[4] = {vv.x, vv.y, vv.z, vv.w};
#pragma unroll
            for (int i = 0; i < 8; i++) {
                float p = Ps[(ty*8+i)*AT_BN + c];
                o[i][0] = fmaf(p, b4[0], o[i][0]);
                o[i][1] = fmaf(p, b4[1], o[i][1]);
                o[i][2] = fmaf(p, b4[2], o[i][2]);
                o[i][3] = fmaf(p, b4[3], o[i][3]);
            }
        }
    }

    const int b = bh >> 4, h = bh & 15;
#pragma unroll
    for (int i = 0; i < 8; i++) {
        int sg = qt*AT_BM + ty*8 + i;
        float inv = 1.f / l_run[i];
        float4 v = make_float4(o[i][0]*inv, o[i][1]*inv, o[i][2]*inv, o[i][3]*inv);
        *(float4*)&O[((size_t)(b*SEQ + sg)) * EMB + h*DHEAD + tx*4] = v;
    }
}

// ---------------- launch ----------------
extern "C" void kernel_launch(void* const* d_in, const int* in_sizes, int n_in,
                              void* d_out, int out_size)
{
    (void)in_sizes; (void)n_in; (void)out_size;
    const float* x  = (const float*)d_in[0];
    const float* wq = (const float*)d_in[2];
    const float* bq = (const float*)d_in[3];
    const float* wk = (const float*)d_in[4];
    const float* bk = (const float*)d_in[5];
    const float* wv = (const float*)d_in[6];
    const float* bv = (const float*)d_in[7];
    const float* wo = (const float*)d_in[8];
    const float* bo = (const float*)d_in[9];
    float* out = (float*)d_out;

    float *qt, *kt, *vb, *ob;
    cudaGetSymbolAddress((void**)&qt, g_Qt);
    cudaGetSymbolAddress((void**)&kt, g_Kt);
    cudaGetSymbolAddress((void**)&vb, g_Vb);
    cudaGetSymbolAddress((void**)&ob, g_Ob);
    __nv_bfloat16 *xh, *xl, *oh, *ol, *wh, *wl;
    cudaGetSymbolAddress((void**)&xh, g_xh);
    cudaGetSymbolAddress((void**)&xl, g_xl);
    cudaGetSymbolAddress((void**)&oh, g_oh);
    cudaGetSymbolAddress((void**)&ol, g_ol);
    cudaGetSymbolAddress((void**)&wh, g_wh);
    cudaGetSymbolAddress((void**)&wl, g_wl);

    const int W = EMB*EMB;

    split_bf16<<<(MROWS*EMB/4)/256, 256>>>(x,  xh, xl, MROWS*EMB/4);
    split_bf16<<<(W/4)/256, 256>>>(wq, wh + 0*W, wl + 0*W, W/4);
    split_bf16<<<(W/4)/256, 256>>>(wk, wh + 1*W, wl + 1*W, W/4);
    split_bf16<<<(W/4)/256, 256>>>(wv, wh + 2*W, wl + 2*W, W/4);
    split_bf16<<<(W/4)/256, 256>>>(wo, wh + 3*W, wl + 3*W, W/4);

    cudaFuncSetAttribute(mma_gemm, cudaFuncAttributeMaxDynamicSharedMemorySize, GEMM_SMEM_DYN);
    const dim3 gGrid(NDIM/128, MROWS/128);   // (8, 64)

    mma_gemm<<<gGrid, 256, GEMM_SMEM_DYN>>>(xh, xl, wh + 0*W, wl + 0*W, bq, qt, MODE_T);
    mma_gemm<<<gGrid, 256, GEMM_SMEM_DYN>>>(xh, xl, wh + 1*W, wl + 1*W, bk, kt, MODE_T);
    mma_gemm<<<gGrid, 256, GEMM_SMEM_DYN>>>(xh, xl, wh + 2*W, wl + 2*W, bv, vb, MODE_V);

    const int smem_attn = (64*AT_BM + 64*AT_BN + AT_BN*64 + AT_BM*AT_BN) * sizeof(float);
    cudaFuncSetAttribute(attn_kernel, cudaFuncAttributeMaxDynamicSharedMemorySize, smem_attn);
    attn_kernel<<<dim3(SEQ/AT_BM, BATCH*HEADS), 256, smem_attn>>>(qt, kt, vb, ob);

    split_bf16<<<(MROWS*EMB/4)/256, 256>>>(ob, oh, ol, MROWS*EMB/4);
    mma_gemm<<<gGrid, 256, GEMM_SMEM_DYN>>>(oh, ol, wh + 3*W, wl + 3*W, bo, out, MODE_PLAIN);
}

// round 4
// speedup vs baseline: 2.2115x; 1.0287x over previous
#include <cuda_runtime.h>
#include <cuda_bf16.h>
#include <mma.h>
#include <math.h>
#include <stdint.h>

using namespace nvcuda;

// Problem constants
#define BATCH 4
#define SEQ   2048
#define EMB   1024
#define HEADS 16
#define DHEAD 64
#define MROWS (BATCH*SEQ)   // 8192
#define KDIM  1024
#define NDIM  1024

#define MODE_PLAIN 0   // fp32 [m][n]
#define MODE_QKBF  1   // bf16 hi/lo, [bh][s][d]
#define MODE_VTBF  2   // bf16 hi/lo, [bh][d][s]

// 0.125 (1/sqrt(D)) * log2(e): folded into Q so softmax uses ex2 directly
#define QSCALE 0.18033688011112042f

// ---------------- scratch (device globals per allocation rules) ----------------
__device__ __nv_bfloat16 g_xh[MROWS*EMB];
__device__ __nv_bfloat16 g_xl[MROWS*EMB];
__device__ __nv_bfloat16 g_oh[MROWS*EMB];
__device__ __nv_bfloat16 g_ol[MROWS*EMB];
__device__ __nv_bfloat16 g_wh[4][EMB*EMB];
__device__ __nv_bfloat16 g_wl[4][EMB*EMB];
__device__ __nv_bfloat16 g_qh[MROWS*EMB];  // [bh][s][d]
__device__ __nv_bfloat16 g_ql[MROWS*EMB];
__device__ __nv_bfloat16 g_kh[MROWS*EMB];  // [bh][s][d]
__device__ __nv_bfloat16 g_kl[MROWS*EMB];
__device__ __nv_bfloat16 g_vh[MROWS*EMB];  // [bh][d][s]
__device__ __nv_bfloat16 g_vl[MROWS*EMB];

// ---------------- helpers ----------------
__device__ __forceinline__ uint32_t smem_to_u32(const void* p) {
    uint32_t a;
    asm("{ .reg .u64 tmp; cvta.to.shared.u64 tmp, %1; cvt.u32.u64 %0, tmp; }"
        : "=r"(a) : "l"(p));
    return a;
}
__device__ __forceinline__ void cp_async16(uint32_t dst, const void* src) {
    asm volatile("cp.async.cg.shared.global [%0], [%1], 16;" :: "r"(dst), "l"(src));
}
#define CP_COMMIT() asm volatile("cp.async.commit_group;" ::: "memory")
#define CP_WAIT0()  asm volatile("cp.async.wait_group 0;" ::: "memory")
#define CP_WAIT1()  asm volatile("cp.async.wait_group 1;" ::: "memory")

__device__ __forceinline__ float fast_ex2(float x) {
    float y;
    asm("ex2.approx.ftz.f32 %0, %1;" : "=f"(y) : "f"(x));
    return y;
}

// mma.sync m16n8k16 row.col f32.bf16.bf16.f32, accumulating
__device__ __forceinline__ void mma_bf16(float* c, const uint32_t* a, uint32_t b0, uint32_t b1) {
    asm volatile(
        "mma.sync.aligned.m16n8k16.row.col.f32.bf16.bf16.f32 "
        "{%0,%1,%2,%3},{%4,%5,%6,%7},{%8,%9},{%0,%1,%2,%3};"
        : "+f"(c[0]), "+f"(c[1]), "+f"(c[2]), "+f"(c[3])
        : "r"(a[0]), "r"(a[1]), "r"(a[2]), "r"(a[3]), "r"(b0), "r"(b1));
}

// fp32 pair -> bf16 hi pair + bf16 lo pair (packed u32, first element in low half)
__device__ __forceinline__ void pack_hl(float x, float y, uint32_t* h, uint32_t* l) {
    __nv_bfloat162 hh = __floats2bfloat162_rn(x, y);
    float rx = x - __bfloat162float(hh.x);
    float ry = y - __bfloat162float(hh.y);
    __nv_bfloat162 ll = __floats2bfloat162_rn(rx, ry);
    *h = *(uint32_t*)&hh;
    *l = *(uint32_t*)&ll;
}

// ---------------- fp32 -> bf16 hi/lo split ----------------
__global__ void split_bf16(const float* __restrict__ in, __nv_bfloat16* __restrict__ hi,
                           __nv_bfloat16* __restrict__ lo, int n4)
{
    int i = blockIdx.x * blockDim.x + threadIdx.x;
    if (i >= n4) return;
    float4 v = ((const float4*)in)[i];
    uint32_t h0, l0, h1, l1;
    pack_hl(v.x, v.y, &h0, &l0);
    pack_hl(v.z, v.w, &h1, &l1);
    ((uint32_t*)hi)[2*i]   = h0; ((uint32_t*)hi)[2*i+1] = h1;
    ((uint32_t*)lo)[2*i]   = l0; ((uint32_t*)lo)[2*i+1] = l1;
}

// ---------------- GEMM: C = ((Ah+Al) @ (Bh+Bl)^T + bias) * cscale ----------------
// wmma/HMMA, CTA 128x128, K-chunk 64, double-buffered cp.async, 3-term split.
#define LDP        72
#define TILE_P     (128*LDP*2)             // 18432 B
#define STAGE_P    (4*TILE_P)              // 73728 B
#define GEMM_SMEM_DYN (1024 + 2*STAGE_P)   // 148480 B

__global__ void __launch_bounds__(256, 1)
mma_gemm(const __nv_bfloat16* __restrict__ Ah, const __nv_bfloat16* __restrict__ Al,
         const __nv_bfloat16* __restrict__ Bh, const __nv_bfloat16* __restrict__ Bl,
         const float* __restrict__ bias, void* __restrict__ C0, void* __restrict__ C1,
         float cscale, int mode)
{
    extern __shared__ __align__(1024) char smem[];
    const uint32_t smem_u = smem_to_u32(smem);
    const int t   = threadIdx.x;
    const int bm  = blockIdx.y * 128;
    const int bn  = blockIdx.x * 128;

    const int wid = t >> 5;
    const int wm  = wid >> 2;
    const int wn  = wid & 3;
    const int m0  = wm * 64;
    const int n0  = wn * 32;

    wmma::fragment<wmma::accumulator, 16, 16, 16, float> acc[4][2];
#pragma unroll
    for (int i = 0; i < 4; i++)
#pragma unroll
        for (int j = 0; j < 2; j++) wmma::fill_fragment(acc[i][j], 0.f);

    const __nv_bfloat16* srcs[4] = {Ah, Al, Bh, Bl};
    const int r0s[4] = {bm, bm, bn, bn};

    auto load_stage = [&](int s, int ic) {
        const uint32_t sb = smem_u + 1024 + (uint32_t)s * STAGE_P;
        const int kc = ic * 64;
#pragma unroll
        for (int tl = 0; tl < 4; tl++) {
            const __nv_bfloat16* g = srcs[tl] + (size_t)r0s[tl] * KDIM + kc;
#pragma unroll
            for (int j = 0; j < 4; j++) {
                int idx = t + j * 256;
                int r   = idx >> 3;
                int c16 = idx & 7;
                cp_async16(sb + (uint32_t)(tl*TILE_P + r*144 + c16*16),
                           g + (size_t)r * KDIM + c16*8);
            }
        }
        CP_COMMIT();
    };

    load_stage(0, 0);

    for (int ic = 0; ic < 16; ic++) {
        if (ic + 1 < 16) load_stage((ic + 1) & 1, ic + 1);
        if (ic + 1 < 16) { CP_WAIT1(); } else { CP_WAIT0(); }
        __syncthreads();

        const char* sb = smem + 1024 + (size_t)(ic & 1) * STAGE_P;
        const __nv_bfloat16* Ahs = (const __nv_bfloat16*)(sb);
        const __nv_bfloat16* Als = (const __nv_bfloat16*)(sb + TILE_P);
        const __nv_bfloat16* Bhs = (const __nv_bfloat16*)(sb + 2*TILE_P);
        const __nv_bfloat16* Bls = (const __nv_bfloat16*)(sb + 3*TILE_P);

#pragma unroll
        for (int k0 = 0; k0 < 64; k0 += 16) {
            wmma::fragment<wmma::matrix_a, 16, 16, 16, __nv_bfloat16, wmma::row_major> aH[4], aL[4];
            wmma::fragment<wmma::matrix_b, 16, 16, 16, __nv_bfloat16, wmma::col_major> bF[2];
#pragma unroll
            for (int i = 0; i < 4; i++)
                wmma::load_matrix_sync(aH[i], Ahs + (m0 + 16*i) * LDP + k0, LDP);
#pragma unroll
            for (int j = 0; j < 2; j++)
                wmma::load_matrix_sync(bF[j], Bhs + (n0 + 16*j) * LDP + k0, LDP);
#pragma unroll
            for (int i = 0; i < 4; i++)
#pragma unroll
                for (int j = 0; j < 2; j++)
                    wmma::mma_sync(acc[i][j], aH[i], bF[j], acc[i][j]);
#pragma unroll
            for (int i = 0; i < 4; i++)
                wmma::load_matrix_sync(aL[i], Als + (m0 + 16*i) * LDP + k0, LDP);
#pragma unroll
            for (int i = 0; i < 4; i++)
#pragma unroll
                for (int j = 0; j < 2; j++)
                    wmma::mma_sync(acc[i][j], aL[i], bF[j], acc[i][j]);
#pragma unroll
            for (int j = 0; j < 2; j++)
                wmma::load_matrix_sync(bF[j], Bls + (n0 + 16*j) * LDP + k0, LDP);
#pragma unroll
            for (int i = 0; i < 4; i++)
#pragma unroll
                for (int j = 0; j < 2; j++)
                    wmma::mma_sync(acc[i][j], aH[i], bF[j], acc[i][j]);
        }
        __syncthreads();
    }

    // Stage full fp32 tile through smem, then scatter per mode
    float* Cs = (float*)smem;
#pragma unroll
    for (int i = 0; i < 4; i++)
#pragma unroll
        for (int j = 0; j < 2; j++)
            wmma::store_matrix_sync(Cs + (m0 + 16*i) * 132 + n0 + 16*j, acc[i][j],
                                    132, wmma::mem_row_major);
    __syncthreads();

    if (mode == MODE_PLAIN) {
        const int r  = t >> 1;
        const int c0 = (t & 1) * 64;
        const int gm = bm + r;
        float* out = (float*)C0 + (size_t)gm * NDIM + bn + c0;
        const float* row = Cs + r * 132 + c0;
        const float* bp  = bias + bn + c0;
#pragma unroll
        for (int j = 0; j < 64; j += 4)
            *(float4*)(out + j) = make_float4(row[j]   + bp[j],
                                              row[j+1] + bp[j+1],
                                              row[j+2] + bp[j+2],
                                              row[j+3] + bp[j+3]);
    } else if (mode == MODE_QKBF) {
        const int r  = t >> 1;
        const int c0 = (t & 1) * 64;          // 64-col half = one head
        const int gm = bm + r;
        const int b  = gm >> 11, sq = gm & 2047;
        const int h  = (bn + c0) >> 6;
        __nv_bfloat16* Oh = (__nv_bfloat16*)C0 + (((size_t)(b*HEADS + h) * SEQ + sq) * DHEAD);
        __nv_bfloat16* Ol = (__nv_bfloat16*)C1 + (((size_t)(b*HEADS + h) * SEQ + sq) * DHEAD);
        const float* row = Cs + r * 132 + c0;
        const float* bp  = bias + bn + c0;
#pragma unroll
        for (int j = 0; j < 64; j += 2) {
            float v0 = (row[j]   + bp[j])   * cscale;
            float v1 = (row[j+1] + bp[j+1]) * cscale;
            uint32_t hh, ll;
            pack_hl(v0, v1, &hh, &ll);
            *(uint32_t*)(Oh + j) = hh;
            *(uint32_t*)(Ol + j) = ll;
        }
    } else { // MODE_VTBF: [bh][d][s]
        const int n  = t >> 1;                 // tile-local col = global head-dim idx
        const int s0 = (t & 1) * 64;
        const int gn = bn + n, h = gn >> 6, d = gn & 63;
        const int gm0 = bm + s0;
        const int b = gm0 >> 11, sq0 = gm0 & 2047;
        const float bv = bias[gn];
        __nv_bfloat16* Oh = (__nv_bfloat16*)C0 + (((size_t)(b*HEADS + h) * DHEAD + d) * SEQ) + sq0;
        __nv_bfloat16* Ol = (__nv_bfloat16*)C1 + (((size_t)(b*HEADS + h) * DHEAD + d) * SEQ) + sq0;
#pragma unroll 4
        for (int r = 0; r < 64; r += 2) {
            float v0 = Cs[(s0 + r)     * 132 + n] + bv;
            float v1 = Cs[(s0 + r + 1) * 132 + n] + bv;
            uint32_t hh, ll;
            pack_hl(v0, v1, &hh, &ll);
            *(uint32_t*)(Oh + r) = hh;
            *(uint32_t*)(Ol + r) = ll;
        }
    }
}

// ---------------- Flash attention, mma.sync bf16 3-term split ----------------
// Q,K: [bh][s][d] hi/lo.  V: [bh][d][s] hi/lo.  O -> g_oh/g_ol [b][s][e] hi/lo.
// BM=128 (8 warps x 16 rows), BN=64. smem rows padded to 72 bf16 (144 B).
// smem: Qh[128][72] Ql[128][72] | stage{0,1}: Kh,Kl[64][72] Vh,Vl[64][72]
#define ATT_QSZ   (128*72*2)    // 18432 B per Q buffer
#define ATT_TSZ   (64*72*2)     // 9216 B per K/V tile
#define ATT_STAGE (4*ATT_TSZ)   // 36864 B
#define ATT_SMEM  (2*ATT_QSZ + 2*ATT_STAGE)  // 110592 B

__global__ void __launch_bounds__(256, 1)
attn_mma(const __nv_bfloat16* __restrict__ Qh_g, const __nv_bfloat16* __restrict__ Ql_g,
         const __nv_bfloat16* __restrict__ Kh_g, const __nv_bfloat16* __restrict__ Kl_g,
         const __nv_bfloat16* __restrict__ Vh_g, const __nv_bfloat16* __restrict__ Vl_g,
         __nv_bfloat16* __restrict__ Oh_g, __nv_bfloat16* __restrict__ Ol_g)
{
    extern __shared__ __align__(128) char sm_[];
    const uint32_t su = smem_to_u32(sm_);
    const int t    = threadIdx.x;
    const int w    = t >> 5;
    const int lane = t & 31;
    const int gid  = lane >> 2;
    const int tig  = lane & 3;
    const int qt   = (gridDim.x - 1) - blockIdx.x;   // big tiles first
    const int bh   = blockIdx.y;
    const int bq   = bh >> 4, hq = bh & 15;

    const __nv_bfloat16* Qhg = Qh_g + ((size_t)bh * SEQ + qt * 128) * DHEAD;
    const __nv_bfloat16* Qlg = Ql_g + ((size_t)bh * SEQ + qt * 128) * DHEAD;

    // issue Q loads (group 0, together with K/V stage 0)
#pragma unroll
    for (int j = 0; j < 4; j++) {
        int idx = t + j * 256;          // 0..1023
        int r   = idx >> 3;
        int c   = idx & 7;
        cp_async16(su + r*144 + c*16,            Qhg + r*DHEAD + c*8);
        cp_async16(su + ATT_QSZ + r*144 + c*16,  Qlg + r*DHEAD + c*8);
    }

    auto load_kv = [&](int stg, int jt) {
        const uint32_t sb = su + 2*ATT_QSZ + (uint32_t)stg * ATT_STAGE;
#pragma unroll
        for (int j = 0; j < 2; j++) {
            int idx = t + j * 256;      // 0..511
            int r   = idx >> 3;
            int c   = idx & 7;
            const size_t ko = ((size_t)bh * SEQ + jt*64 + r) * DHEAD + c*8;
            cp_async16(sb +             r*144 + c*16, Kh_g + ko);
            cp_async16(sb + ATT_TSZ   + r*144 + c*16, Kl_g + ko);
            const size_t vo = ((size_t)bh * DHEAD + r) * SEQ + jt*64 + c*8;
            cp_async16(sb + 2*ATT_TSZ + r*144 + c*16, Vh_g + vo);
            cp_async16(sb + 3*ATT_TSZ + r*144 + c*16, Vl_g + vo);
        }
    };

    load_kv(0, 0);
    CP_COMMIT();

    float Of[8][4];
#pragma unroll
    for (int i = 0; i < 8; i++)
#pragma unroll
        for (int j = 0; j < 4; j++) Of[i][j] = 0.f;
    float m_a = -1e30f, m_b = -1e30f, l_a = 0.f, l_b = 0.f;

    uint32_t qh[4][4], ql[4][4];

    const int jt_end = 2*qt + 1;
    const int rga = qt*128 + w*16 + gid;   // global q row (low)
    const int rgb = rga + 8;

    for (int jt = 0; jt <= jt_end; jt++) {
        if (jt < jt_end) { load_kv((jt + 1) & 1, jt + 1); CP_COMMIT(); CP_WAIT1(); }
        else             { CP_WAIT0(); }
        __syncthreads();

        if (jt == 0) {
            // load Q A-frags once (rows w*16+gid, w*16+gid+8)
            const __nv_bfloat16* Qsh = (const __nv_bfloat16*)sm_;
            const __nv_bfloat16* Qsl = Qsh + 128*72;
            const int ra = w*16 + gid, rb = ra + 8;
#pragma unroll
            for (int kk = 0; kk < 4; kk++) {
                qh[kk][0] = *(const uint32_t*)&Qsh[ra*72 + kk*16 + 2*tig];
                qh[kk][1] = *(const uint32_t*)&Qsh[rb*72 + kk*16 + 2*tig];
                qh[kk][2] = *(const uint32_t*)&Qsh[ra*72 + kk*16 + 2*tig + 8];
                qh[kk][3] = *(const uint32_t*)&Qsh[rb*72 + kk*16 + 2*tig + 8];
                ql[kk][0] = *(const uint32_t*)&Qsl[ra*72 + kk*16 + 2*tig];
                ql[kk][1] = *(const uint32_t*)&Qsl[rb*72 + kk*16 + 2*tig];
                ql[kk][2] = *(const uint32_t*)&Qsl[ra*72 + kk*16 + 2*tig + 8];
                ql[kk][3] = *(const uint32_t*)&Qsl[rb*72 + kk*16 + 2*tig + 8];
            }
        }

        const __nv_bfloat16* Ksh = (const __nv_bfloat16*)(sm_ + 2*ATT_QSZ + (size_t)(jt & 1) * ATT_STAGE);
        const __nv_bfloat16* Ksl = Ksh + 64*72;
        const __nv_bfloat16* Vsh = Ksh + 2*64*72;
        const __nv_bfloat16* Vsl = Ksh + 3*64*72;

        // ---- S = Q K^T (logits already scaled via Q) ----
        float Sf[8][4];
#pragma unroll
        for (int i = 0; i < 8; i++)
#pragma unroll
            for (int j = 0; j < 4; j++) Sf[i][j] = 0.f;

#pragma unroll
        for (int kk = 0; kk < 4; kk++) {
#pragma unroll
            for (int nt = 0; nt < 8; nt++) {
                const int rowk = nt*8 + gid;
                uint32_t kh0 = *(const uint32_t*)&Ksh[rowk*72 + kk*16 + 2*tig];
                uint32_t kh1 = *(const uint32_t*)&Ksh[rowk*72 + kk*16 + 2*tig + 8];
                uint32_t kl0 = *(const uint32_t*)&Ksl[rowk*72 + kk*16 + 2*tig];
                uint32_t kl1 = *(const uint32_t*)&Ksl[rowk*72 + kk*16 + 2*tig + 8];
                mma_bf16(Sf[nt], qh[kk], kh0, kh1);
                mma_bf16(Sf[nt], qh[kk], kl0, kl1);
                mma_bf16(Sf[nt], ql[kk], kh0, kh1);
            }
        }

        // ---- causal mask (diagonal-adjacent tiles only) ----
        if (jt >= 2*qt) {
#pragma unroll
            for (int nt = 0; nt < 8; nt++) {
                const int cg = jt*64 + nt*8 + 2*tig;
                if (cg     > rga) Sf[nt][0] = -1e30f;
                if (cg + 1 > rga) Sf[nt][1] = -1e30f;
                if (cg     > rgb) Sf[nt][2] = -1e30f;
                if (cg + 1 > rgb) Sf[nt][3] = -1e30f;
            }
        }

        // ---- online softmax (base-2) ----
        float va = -1e30f, vb = -1e30f;
#pragma unroll
        for (int nt = 0; nt < 8; nt++) {
            va = fmaxf(va, fmaxf(Sf[nt][0], Sf[nt][1]));
            vb = fmaxf(vb, fmaxf(Sf[nt][2], Sf[nt][3]));
        }
        va = fmaxf(va, __shfl_xor_sync(0xffffffffu, va, 1));
        va = fmaxf(va, __shfl_xor_sync(0xffffffffu, va, 2));
        vb = fmaxf(vb, __shfl_xor_sync(0xffffffffu, vb, 1));
        vb = fmaxf(vb, __shfl_xor_sync(0xffffffffu, vb, 2));

        const float mna = fmaxf(m_a, va), mnb = fmaxf(m_b, vb);
        const float aa = fast_ex2(m_a - mna), ab = fast_ex2(m_b - mnb);
        float sa = 0.f, sb = 0.f;
#pragma unroll
        for (int nt = 0; nt < 8; nt++) {
            Sf[nt][0] = fast_ex2(Sf[nt][0] - mna);
            Sf[nt][1] = fast_ex2(Sf[nt][1] - mna);
            Sf[nt][2] = fast_ex2(Sf[nt][2] - mnb);
            Sf[nt][3] = fast_ex2(Sf[nt][3] - mnb);
            sa += Sf[nt][0] + Sf[nt][1];
            sb += Sf[nt][2] + Sf[nt][3];
        }
        sa += __shfl_xor_sync(0xffffffffu, sa, 1);
        sa += __shfl_xor_sync(0xffffffffu, sa, 2);
        sb += __shfl_xor_sync(0xffffffffu, sb, 1);
        sb += __shfl_xor_sync(0xffffffffu, sb, 2);
        l_a = l_a * aa + sa;
        l_b = l_b * ab + sb;
        m_a = mna; m_b = mnb;
#pragma unroll
        for (int nt = 0; nt < 8; nt++) {
            Of[nt][0] *= aa; Of[nt][1] *= aa;
            Of[nt][2] *= ab; Of[nt][3] *= ab;
        }

        // ---- O += P V  (P repacked in registers) ----
#pragma unroll
        for (int kk2 = 0; kk2 < 4; kk2++) {
            uint32_t pah[4], pal[4];
            pack_hl(Sf[2*kk2][0],   Sf[2*kk2][1],   &pah[0], &pal[0]);
            pack_hl(Sf[2*kk2][2],   Sf[2*kk2][3],   &pah[1], &pal[1]);
            pack_hl(Sf[2*kk2+1][0], Sf[2*kk2+1][1], &pah[2], &pal[2]);
            pack_hl(Sf[2*kk2+1][2], Sf[2*kk2+1][3], &pah[3], &pal[3]);
#pragma unroll
            for (int nt = 0; nt < 8; nt++) {
                const int rowv = nt*8 + gid;
                uint32_t vh0 = *(const uint32_t*)&Vsh[rowv*72 + kk2*16 + 2*tig];
                uint32_t vh1 = *(const uint32_t*)&Vsh[rowv*72 + kk2*16 + 2*tig + 8];
                uint32_t vl0 = *(const uint32_t*)&Vsl[rowv*72 + kk2*16 + 2*tig];
                uint32_t vl1 = *(const uint32_t*)&Vsl[rowv*72 + kk2*16 + 2*tig + 8];
                mma_bf16(Of[nt], pah, vh0, vh1);
                mma_bf16(Of[nt], pah, vl0, vl1);
                mma_bf16(Of[nt], pal, vh0, vh1);
            }
        }
        __syncthreads();
    }

    // ---- epilogue: O/l -> bf16 hi/lo at [b][s][h*64+d] ----
    const float inva = 1.f / l_a, invb = 1.f / l_b;
    const int sa_row = qt*128 + w*16 + gid;
    const size_t base_a = ((size_t)(bq*SEQ + sa_row)) * EMB + hq*DHEAD + 2*tig;
    const size_t base_b = base_a + (size_t)8 * EMB;
#pragma unroll
    for (int nt = 0; nt < 8; nt++) {
        uint32_t hh, ll;
        pack_hl(Of[nt][0]*inva, Of[nt][1]*inva, &hh, &ll);
        *(uint32_t*)&Oh_g[base_a + nt*8] = hh;
        *(uint32_t*)&Ol_g[base_a + nt*8] = ll;
        pack_hl(Of[nt][2]*invb, Of[nt][3]*invb, &hh, &ll);
        *(uint32_t*)&Oh_g[base_b + nt*8] = hh;
        *(uint32_t*)&Ol_g[base_b + nt*8] = ll;
    }
}

// ---------------- launch ----------------
extern "C" void kernel_launch(void* const* d_in, const int* in_sizes, int n_in,
                              void* d_out, int out_size)
{
    (void)in_sizes; (void)n_in; (void)out_size;
    const float* x  = (const float*)d_in[0];
    const float* wq = (const float*)d_in[2];
    const float* bq = (const float*)d_in[3];
    const float* wk = (const float*)d_in[4];
    const float* bk = (const float*)d_in[5];
    const float* wv = (const float*)d_in[6];
    const float* bv = (const float*)d_in[7];
    const float* wo = (const float*)d_in[8];
    const float* bo = (const float*)d_in[9];
    float* out = (float*)d_out;

    __nv_bfloat16 *xh, *xl, *oh, *ol, *wh, *wl, *qh, *ql, *kh, *kl, *vh, *vl;
    cudaGetSymbolAddress((void**)&xh, g_xh);
    cudaGetSymbolAddress((void**)&xl, g_xl);
    cudaGetSymbolAddress((void**)&oh, g_oh);
    cudaGetSymbolAddress((void**)&ol, g_ol);
    cudaGetSymbolAddress((void**)&wh, g_wh);
    cudaGetSymbolAddress((void**)&wl, g_wl);
    cudaGetSymbolAddress((void**)&qh, g_qh);
    cudaGetSymbolAddress((void**)&ql, g_ql);
    cudaGetSymbolAddress((void**)&kh, g_kh);
    cudaGetSymbolAddress((void**)&kl, g_kl);
    cudaGetSymbolAddress((void**)&vh, g_vh);
    cudaGetSymbolAddress((void**)&vl, g_vl);

    const int W = EMB*EMB;

    split_bf16<<<(MROWS*EMB/4)/256, 256>>>(x,  xh, xl, MROWS*EMB/4);
    split_bf16<<<(W/4)/256, 256>>>(wq, wh + 0*W, wl + 0*W, W/4);
    split_bf16<<<(W/4)/256, 256>>>(wk, wh + 1*W, wl + 1*W, W/4);
    split_bf16<<<(W/4)/256, 256>>>(wv, wh + 2*W, wl + 2*W, W/4);
    split_bf16<<<(W/4)/256, 256>>>(wo, wh + 3*W, wl + 3*W, W/4);

    cudaFuncSetAttribute(mma_gemm, cudaFuncAttributeMaxDynamicSharedMemorySize, GEMM_SMEM_DYN);
    const dim3 gGrid(NDIM/128, MROWS/128);   // (8, 64)

    mma_gemm<<<gGrid, 256, GEMM_SMEM_DYN>>>(xh, xl, wh + 0*W, wl + 0*W, bq, qh, ql, QSCALE, MODE_QKBF);
    mma_gemm<<<gGrid, 256, GEMM_SMEM_DYN>>>(xh, xl, wh + 1*W, wl + 1*W, bk, kh, kl, 1.0f,   MODE_QKBF);
    mma_gemm<<<gGrid, 256, GEMM_SMEM_DYN>>>(xh, xl, wh + 2*W, wl + 2*W, bv, vh, vl, 1.0f,   MODE_VTBF);

    cudaFuncSetAttribute(attn_mma, cudaFuncAttributeMaxDynamicSharedMemorySize, ATT_SMEM);
    attn_mma<<<dim3(SEQ/128, BATCH*HEADS), 256, ATT_SMEM>>>(qh, ql, kh, kl, vh, vl, oh, ol);

    mma_gemm<<<gGrid, 256, GEMM_SMEM_DYN>>>(oh, ol, wh + 3*W, wl + 3*W, bo, out, nullptr, 1.0f, MODE_PLAIN);
}

// round 5
// speedup vs baseline: 2.2244x; 1.0058x over previous
#include <cuda_runtime.h>
#include <cuda_bf16.h>
#include <mma.h>
#include <math.h>
#include <stdint.h>

using namespace nvcuda;

// Problem constants
#define BATCH 4
#define SEQ   2048
#define EMB   1024
#define HEADS 16
#define DHEAD 64
#define MROWS (BATCH*SEQ)   // 8192
#define KDIM  1024
#define NDIM  1024

#define MODE_PLAIN 0   // fp32 [m][n]
#define MODE_QKBF  1   // bf16 hi/lo, [bh][s][d]
#define MODE_VTBF  2   // bf16 hi/lo, [bh][d][s]

// 0.125 (1/sqrt(D)) * log2(e): folded into Q so softmax uses ex2 directly
#define QSCALE 0.18033688011112042f

// ---------------- scratch (device globals per allocation rules) ----------------
__device__ __nv_bfloat16 g_xh[MROWS*EMB];
__device__ __nv_bfloat16 g_xl[MROWS*EMB];
__device__ __nv_bfloat16 g_oh[MROWS*EMB];
__device__ __nv_bfloat16 g_ol[MROWS*EMB];
__device__ __nv_bfloat16 g_wh[4][EMB*EMB];
__device__ __nv_bfloat16 g_wl[4][EMB*EMB];
__device__ __nv_bfloat16 g_qh[MROWS*EMB];  // [bh][s][d]
__device__ __nv_bfloat16 g_ql[MROWS*EMB];
__device__ __nv_bfloat16 g_kh[MROWS*EMB];  // [bh][s][d]
__device__ __nv_bfloat16 g_kl[MROWS*EMB];
__device__ __nv_bfloat16 g_vh[MROWS*EMB];  // [bh][d][s]
__device__ __nv_bfloat16 g_vl[MROWS*EMB];

// ---------------- helpers ----------------
__device__ __forceinline__ uint32_t smem_to_u32(const void* p) {
    uint32_t a;
    asm("{ .reg .u64 tmp; cvta.to.shared.u64 tmp, %1; cvt.u32.u64 %0, tmp; }"
        : "=r"(a) : "l"(p));
    return a;
}
__device__ __forceinline__ void cp_async16(uint32_t dst, const void* src) {
    asm volatile("cp.async.cg.shared.global [%0], [%1], 16;" :: "r"(dst), "l"(src));
}
#define CP_COMMIT() asm volatile("cp.async.commit_group;" ::: "memory")
#define CP_WAIT0()  asm volatile("cp.async.wait_group 0;" ::: "memory")
#define CP_WAIT1()  asm volatile("cp.async.wait_group 1;" ::: "memory")

__device__ __forceinline__ float fast_ex2(float x) {
    float y;
    asm("ex2.approx.ftz.f32 %0, %1;" : "=f"(y) : "f"(x));
    return y;
}

// ldmatrix x4: loads 4 8x8 b16 matrices; lane 8i..8i+7 provide row addresses of matrix i
__device__ __forceinline__ void ldsm_x4(uint32_t* r, uint32_t addr) {
    asm volatile("ldmatrix.sync.aligned.m8n8.x4.shared.b16 {%0,%1,%2,%3}, [%4];"
        : "=r"(r[0]), "=r"(r[1]), "=r"(r[2]), "=r"(r[3]) : "r"(addr));
}

// mma.sync m16n8k16 row.col f32.bf16.bf16.f32, accumulating
__device__ __forceinline__ void mma_bf16(float* c, const uint32_t* a, uint32_t b0, uint32_t b1) {
    asm volatile(
        "mma.sync.aligned.m16n8k16.row.col.f32.bf16.bf16.f32 "
        "{%0,%1,%2,%3},{%4,%5,%6,%7},{%8,%9},{%0,%1,%2,%3};"
        : "+f"(c[0]), "+f"(c[1]), "+f"(c[2]), "+f"(c[3])
        : "r"(a[0]), "r"(a[1]), "r"(a[2]), "r"(a[3]), "r"(b0), "r"(b1));
}

// fp32 pair -> bf16 hi pair + bf16 lo pair (packed u32, first element in low half)
__device__ __forceinline__ void pack_hl(float x, float y, uint32_t* h, uint32_t* l) {
    __nv_bfloat162 hh = __floats2bfloat162_rn(x, y);
    float rx = x - __bfloat162float(hh.x);
    float ry = y - __bfloat162float(hh.y);
    __nv_bfloat162 ll = __floats2bfloat162_rn(rx, ry);
    *h = *(uint32_t*)&hh;
    *l = *(uint32_t*)&ll;
}

// ---------------- fp32 -> bf16 hi/lo splits ----------------
__global__ void split_bf16(const float* __restrict__ in, __nv_bfloat16* __restrict__ hi,
                           __nv_bfloat16* __restrict__ lo, int n4)
{
    int i = blockIdx.x * blockDim.x + threadIdx.x;
    if (i >= n4) return;
    float4 v = ((const float4*)in)[i];
    uint32_t h0, l0, h1, l1;
    pack_hl(v.x, v.y, &h0, &l0);
    pack_hl(v.z, v.w, &h1, &l1);
    ((uint32_t*)hi)[2*i]   = h0; ((uint32_t*)hi)[2*i+1] = h1;
    ((uint32_t*)lo)[2*i]   = l0; ((uint32_t*)lo)[2*i+1] = l1;
}

// 4 weight matrices in one launch (blockIdx.y selects)
__global__ void split_bf16_w(const float* __restrict__ w0, const float* __restrict__ w1,
                             const float* __restrict__ w2, const float* __restrict__ w3,
                             __nv_bfloat16* __restrict__ hi, __nv_bfloat16* __restrict__ lo)
{
    const float* srcs[4] = {w0, w1, w2, w3};
    const int ws = blockIdx.y;
    const float* in = srcs[ws];
    const size_t base = (size_t)ws * (EMB*EMB);
    int i = blockIdx.x * blockDim.x + threadIdx.x;   // float4 index within one matrix
    float4 v = ((const float4*)in)[i];
    uint32_t h0, l0, h1, l1;
    pack_hl(v.x, v.y, &h0, &l0);
    pack_hl(v.z, v.w, &h1, &l1);
    ((uint32_t*)(hi + base))[2*i]   = h0; ((uint32_t*)(hi + base))[2*i+1] = h1;
    ((uint32_t*)(lo + base))[2*i]   = l0; ((uint32_t*)(lo + base))[2*i+1] = l1;
}

// ---------------- GEMM: C = ((Ah+Al) @ (Bh+Bl)^T + bias) * cscale ----------------
#define LDP        72
#define TILE_P     (128*LDP*2)             // 18432 B
#define STAGE_P    (4*TILE_P)              // 73728 B
#define GEMM_SMEM_DYN (1024 + 2*STAGE_P)   // 148480 B

__global__ void __launch_bounds__(256, 1)
mma_gemm(const __nv_bfloat16* __restrict__ Ah, const __nv_bfloat16* __restrict__ Al,
         const __nv_bfloat16* __restrict__ Bh, const __nv_bfloat16* __restrict__ Bl,
         const float* __restrict__ bias, void* __restrict__ C0, void* __restrict__ C1,
         float cscale, int mode)
{
    extern __shared__ __align__(1024) char smem[];
    const uint32_t smem_u = smem_to_u32(smem);
    const int t   = threadIdx.x;
    const int bm  = blockIdx.y * 128;
    const int bn  = blockIdx.x * 128;

    const int wid = t >> 5;
    const int wm  = wid >> 2;
    const int wn  = wid & 3;
    const int m0  = wm * 64;
    const int n0  = wn * 32;

    wmma::fragment<wmma::accumulator, 16, 16, 16, float> acc[4][2];
#pragma unroll
    for (int i = 0; i < 4; i++)
#pragma unroll
        for (int j = 0; j < 2; j++) wmma::fill_fragment(acc[i][j], 0.f);

    const __nv_bfloat16* srcs[4] = {Ah, Al, Bh, Bl};
    const int r0s[4] = {bm, bm, bn, bn};

    auto load_stage = [&](int s, int ic) {
        const uint32_t sb = smem_u + 1024 + (uint32_t)s * STAGE_P;
        const int kc = ic * 64;
#pragma unroll
        for (int tl = 0; tl < 4; tl++) {
            const __nv_bfloat16* g = srcs[tl] + (size_t)r0s[tl] * KDIM + kc;
#pragma unroll
            for (int j = 0; j < 4; j++) {
                int idx = t + j * 256;
                int r   = idx >> 3;
                int c16 = idx & 7;
                cp_async16(sb + (uint32_t)(tl*TILE_P + r*144 + c16*16),
                           g + (size_t)r * KDIM + c16*8);
            }
        }
        CP_COMMIT();
    };

    load_stage(0, 0);

    for (int ic = 0; ic < 16; ic++) {
        if (ic + 1 < 16) load_stage((ic + 1) & 1, ic + 1);
        if (ic + 1 < 16) { CP_WAIT1(); } else { CP_WAIT0(); }
        __syncthreads();

        const char* sb = smem + 1024 + (size_t)(ic & 1) * STAGE_P;
        const __nv_bfloat16* Ahs = (const __nv_bfloat16*)(sb);
        const __nv_bfloat16* Als = (const __nv_bfloat16*)(sb + TILE_P);
        const __nv_bfloat16* Bhs = (const __nv_bfloat16*)(sb + 2*TILE_P);
        const __nv_bfloat16* Bls = (const __nv_bfloat16*)(sb + 3*TILE_P);

#pragma unroll
        for (int k0 = 0; k0 < 64; k0 += 16) {
            wmma::fragment<wmma::matrix_a, 16, 16, 16, __nv_bfloat16, wmma::row_major> aH[4], aL[4];
            wmma::fragment<wmma::matrix_b, 16, 16, 16, __nv_bfloat16, wmma::col_major> bF[2];
#pragma unroll
            for (int i = 0; i < 4; i++)
                wmma::load_matrix_sync(aH[i], Ahs + (m0 + 16*i) * LDP + k0, LDP);
#pragma unroll
            for (int j = 0; j < 2; j++)
                wmma::load_matrix_sync(bF[j], Bhs + (n0 + 16*j) * LDP + k0, LDP);
#pragma unroll
            for (int i = 0; i < 4; i++)
#pragma unroll
                for (int j = 0; j < 2; j++)
                    wmma::mma_sync(acc[i][j], aH[i], bF[j], acc[i][j]);
#pragma unroll
            for (int i = 0; i < 4; i++)
                wmma::load_matrix_sync(aL[i], Als + (m0 + 16*i) * LDP + k0, LDP);
#pragma unroll
            for (int i = 0; i < 4; i++)
#pragma unroll
                for (int j = 0; j < 2; j++)
                    wmma::mma_sync(acc[i][j], aL[i], bF[j], acc[i][j]);
#pragma unroll
            for (int j = 0; j < 2; j++)
                wmma::load_matrix_sync(bF[j], Bls + (n0 + 16*j) * LDP + k0, LDP);
#pragma unroll
            for (int i = 0; i < 4; i++)
#pragma unroll
                for (int j = 0; j < 2; j++)
                    wmma::mma_sync(acc[i][j], aH[i], bF[j], acc[i][j]);
        }
        __syncthreads();
    }

    // Stage full fp32 tile through smem, then scatter per mode
    float* Cs = (float*)smem;
#pragma unroll
    for (int i = 0; i < 4; i++)
#pragma unroll
        for (int j = 0; j < 2; j++)
            wmma::store_matrix_sync(Cs + (m0 + 16*i) * 132 + n0 + 16*j, acc[i][j],
                                    132, wmma::mem_row_major);
    __syncthreads();

    if (mode == MODE_PLAIN) {
        const int r  = t >> 1;
        const int c0 = (t & 1) * 64;
        const int gm = bm + r;
        float* out = (float*)C0 + (size_t)gm * NDIM + bn + c0;
        const float* row = Cs + r * 132 + c0;
        const float* bp  = bias + bn + c0;
#pragma unroll
        for (int j = 0; j < 64; j += 4)
            *(float4*)(out + j) = make_float4(row[j]   + bp[j],
                                              row[j+1] + bp[j+1],
                                              row[j+2] + bp[j+2],
                                              row[j+3] + bp[j+3]);
    } else if (mode == MODE_QKBF) {
        const int r  = t >> 1;
        const int c0 = (t & 1) * 64;
        const int gm = bm + r;
        const int b  = gm >> 11, sq = gm & 2047;
        const int h  = (bn + c0) >> 6;
        __nv_bfloat16* Oh = (__nv_bfloat16*)C0 + (((size_t)(b*HEADS + h) * SEQ + sq) * DHEAD);
        __nv_bfloat16* Ol = (__nv_bfloat16*)C1 + (((size_t)(b*HEADS + h) * SEQ + sq) * DHEAD);
        const float* row = Cs + r * 132 + c0;
        const float* bp  = bias + bn + c0;
#pragma unroll
        for (int j = 0; j < 64; j += 2) {
            float v0 = (row[j]   + bp[j])   * cscale;
            float v1 = (row[j+1] + bp[j+1]) * cscale;
            uint32_t hh, ll;
            pack_hl(v0, v1, &hh, &ll);
            *(uint32_t*)(Oh + j) = hh;
            *(uint32_t*)(Ol + j) = ll;
        }
    } else { // MODE_VTBF: [bh][d][s]
        const int n  = t >> 1;
        const int s0 = (t & 1) * 64;
        const int gn = bn + n, h = gn >> 6, d = gn & 63;
        const int gm0 = bm + s0;
        const int b = gm0 >> 11, sq0 = gm0 & 2047;
        const float bv = bias[gn];
        __nv_bfloat16* Oh = (__nv_bfloat16*)C0 + (((size_t)(b*HEADS + h) * DHEAD + d) * SEQ) + sq0;
        __nv_bfloat16* Ol = (__nv_bfloat16*)C1 + (((size_t)(b*HEADS + h) * DHEAD + d) * SEQ) + sq0;
#pragma unroll 4
        for (int r = 0; r < 64; r += 2) {
            float v0 = Cs[(s0 + r)     * 132 + n] + bv;
            float v1 = Cs[(s0 + r + 1) * 132 + n] + bv;
            uint32_t hh, ll;
            pack_hl(v0, v1, &hh, &ll);
            *(uint32_t*)(Oh + r) = hh;
            *(uint32_t*)(Ol + r) = ll;
        }
    }
}

// ---------------- Flash attention, mma.sync bf16 3-term split, ldmatrix loads ----------------
// Q,K: [bh][s][d] hi/lo.  V: [bh][d][s] hi/lo.  O -> g_oh/g_ol [b][s][e] hi/lo.
// BM=128 (8 warps x 16 rows), BN=64. smem rows padded to 72 bf16 (144 B).
#define ATT_QSZ   (128*72*2)    // 18432 B per Q buffer
#define ATT_TSZ   (64*72*2)     // 9216 B per K/V tile
#define ATT_STAGE (4*ATT_TSZ)   // 36864 B
#define ATT_SMEM  (2*ATT_QSZ + 2*ATT_STAGE)  // 110592 B

__global__ void __launch_bounds__(256, 1)
attn_mma(const __nv_bfloat16* __restrict__ Qh_g, const __nv_bfloat16* __restrict__ Ql_g,
         const __nv_bfloat16* __restrict__ Kh_g, const __nv_bfloat16* __restrict__ Kl_g,
         const __nv_bfloat16* __restrict__ Vh_g, const __nv_bfloat16* __restrict__ Vl_g,
         __nv_bfloat16* __restrict__ Oh_g, __nv_bfloat16* __restrict__ Ol_g)
{
    extern __shared__ __align__(128) char sm_[];
    const uint32_t su = smem_to_u32(sm_);
    const int t    = threadIdx.x;
    const int w    = t >> 5;
    const int lane = t & 31;
    const int gid  = lane >> 2;
    const int tig  = lane & 3;
    const int qt   = (gridDim.x - 1) - blockIdx.x;   // big tiles first
    const int bh   = blockIdx.y;
    const int bq   = bh >> 4, hq = bh & 15;

    // per-lane ldmatrix address constants
    // A-frag (Q): lanes 0-15 -> rows ra+(l&15) @k0 ; 16-31 -> same rows @k+8
    const uint32_t aq_off = (uint32_t)((w*16 + (lane & 15))*144 + ((lane >> 4) * 16));
    // B-frag (K/V): m0 rows 0-7 k0 | m1 rows 0-7 k8 | m2 rows 8-15 k0 | m3 rows 8-15 k8
    const uint32_t offb = (uint32_t)((((lane & 7) + ((lane >> 4) << 3)) * 144) + (((lane >> 3) & 1) * 16));

    const __nv_bfloat16* Qhg = Qh_g + ((size_t)bh * SEQ + qt * 128) * DHEAD;
    const __nv_bfloat16* Qlg = Ql_g + ((size_t)bh * SEQ + qt * 128) * DHEAD;

#pragma unroll
    for (int j = 0; j < 4; j++) {
        int idx = t + j * 256;
        int r   = idx >> 3;
        int c   = idx & 7;
        cp_async16(su + r*144 + c*16,            Qhg + r*DHEAD + c*8);
        cp_async16(su + ATT_QSZ + r*144 + c*16,  Qlg + r*DHEAD + c*8);
    }

    auto load_kv = [&](int stg, int jt) {
        const uint32_t sb = su + 2*ATT_QSZ + (uint32_t)stg * ATT_STAGE;
#pragma unroll
        for (int j = 0; j < 2; j++) {
            int idx = t + j * 256;
            int r   = idx >> 3;
            int c   = idx & 7;
            const size_t ko = ((size_t)bh * SEQ + jt*64 + r) * DHEAD + c*8;
            cp_async16(sb +             r*144 + c*16, Kh_g + ko);
            cp_async16(sb + ATT_TSZ   + r*144 + c*16, Kl_g + ko);
            const size_t vo = ((size_t)bh * DHEAD + r) * SEQ + jt*64 + c*8;
            cp_async16(sb + 2*ATT_TSZ + r*144 + c*16, Vh_g + vo);
            cp_async16(sb + 3*ATT_TSZ + r*144 + c*16, Vl_g + vo);
        }
    };

    load_kv(0, 0);
    CP_COMMIT();

    float Of[8][4];
#pragma unroll
    for (int i = 0; i < 8; i++)
#pragma unroll
        for (int j = 0; j < 4; j++) Of[i][j] = 0.f;
    float m_a = -1e30f, m_b = -1e30f, l_a = 0.f, l_b = 0.f;

    uint32_t qh[4][4], ql[4][4];

    const int jt_end = 2*qt + 1;
    const int rga = qt*128 + w*16 + gid;
    const int rgb = rga + 8;

    for (int jt = 0; jt <= jt_end; jt++) {
        if (jt < jt_end) { load_kv((jt + 1) & 1, jt + 1); CP_COMMIT(); CP_WAIT1(); }
        else             { CP_WAIT0(); }
        __syncthreads();

        if (jt == 0) {
            // Q A-frags via ldmatrix (hi and lo), kept in registers
#pragma unroll
            for (int kk = 0; kk < 4; kk++) {
                ldsm_x4(qh[kk], su + aq_off + kk*32);
                ldsm_x4(ql[kk], su + ATT_QSZ + aq_off + kk*32);
            }
        }

        const uint32_t kb = su + 2*ATT_QSZ + (uint32_t)(jt & 1) * ATT_STAGE;

        // ---- S = Q K^T ----
        float Sf[8][4];
#pragma unroll
        for (int i = 0; i < 8; i++)
#pragma unroll
            for (int j = 0; j < 4; j++) Sf[i][j] = 0.f;

#pragma unroll
        for (int kk = 0; kk < 4; kk++) {
            uint32_t KH[16], KL[16];   // 4 nt-pairs x {b0,b1 even nt, b0,b1 odd nt}
#pragma unroll
            for (int ntp = 0; ntp < 4; ntp++) {
                ldsm_x4(KH + 4*ntp, kb + offb + (uint32_t)(ntp*2304 + kk*32));
                ldsm_x4(KL + 4*ntp, kb + ATT_TSZ + offb + (uint32_t)(ntp*2304 + kk*32));
            }
#pragma unroll
            for (int nt = 0; nt < 8; nt++)
                mma_bf16(Sf[nt], qh[kk], KH[2*nt], KH[2*nt+1]);
#pragma unroll
            for (int nt = 0; nt < 8; nt++)
                mma_bf16(Sf[nt], qh[kk], KL[2*nt], KL[2*nt+1]);
#pragma unroll
            for (int nt = 0; nt < 8; nt++)
                mma_bf16(Sf[nt], ql[kk], KH[2*nt], KH[2*nt+1]);
        }

        // ---- causal mask (diagonal-adjacent tiles only) ----
        if (jt >= 2*qt) {
#pragma unroll
            for (int nt = 0; nt < 8; nt++) {
                const int cg = jt*64 + nt*8 + 2*tig;
                if (cg     > rga) Sf[nt][0] = -1e30f;
                if (cg + 1 > rga) Sf[nt][1] = -1e30f;
                if (cg     > rgb) Sf[nt][2] = -1e30f;
                if (cg + 1 > rgb) Sf[nt][3] = -1e30f;
            }
        }

        // ---- online softmax (base-2) ----
        float va = -1e30f, vb = -1e30f;
#pragma unroll
        for (int nt = 0; nt < 8; nt++) {
            va = fmaxf(va, fmaxf(Sf[nt][0], Sf[nt][1]));
            vb = fmaxf(vb, fmaxf(Sf[nt][2], Sf[nt][3]));
        }
        va = fmaxf(va, __shfl_xor_sync(0xffffffffu, va, 1));
        va = fmaxf(va, __shfl_xor_sync(0xffffffffu, va, 2));
        vb = fmaxf(vb, __shfl_xor_sync(0xffffffffu, vb, 1));
        vb = fmaxf(vb, __shfl_xor_sync(0xffffffffu, vb, 2));

        const float mna = fmaxf(m_a, va), mnb = fmaxf(m_b, vb);
        const float aa = fast_ex2(m_a - mna), ab = fast_ex2(m_b - mnb);
        float sa = 0.f, sb = 0.f;
#pragma unroll
        for (int nt = 0; nt < 8; nt++) {
            Sf[nt][0] = fast_ex2(Sf[nt][0] - mna);
            Sf[nt][1] = fast_ex2(Sf[nt][1] - mna);
            Sf[nt][2] = fast_ex2(Sf[nt][2] - mnb);
            Sf[nt][3] = fast_ex2(Sf[nt][3] - mnb);
            sa += Sf[nt][0] + Sf[nt][1];
            sb += Sf[nt][2] + Sf[nt][3];
        }
        sa += __shfl_xor_sync(0xffffffffu, sa, 1);
        sa += __shfl_xor_sync(0xffffffffu, sa, 2);
        sb += __shfl_xor_sync(0xffffffffu, sb, 1);
        sb += __shfl_xor_sync(0xffffffffu, sb, 2);
        l_a = l_a * aa + sa;
        l_b = l_b * ab + sb;
        m_a = mna; m_b = mnb;
#pragma unroll
        for (int nt = 0; nt < 8; nt++) {
            Of[nt][0] *= aa; Of[nt][1] *= aa;
            Of[nt][2] *= ab; Of[nt][3] *= ab;
        }

        // ---- O += P V ----
#pragma unroll
        for (int kk2 = 0; kk2 < 4; kk2++) {
            uint32_t pah[4], pal[4];
            pack_hl(Sf[2*kk2][0],   Sf[2*kk2][1],   &pah[0], &pal[0]);
            pack_hl(Sf[2*kk2][2],   Sf[2*kk2][3],   &pah[1], &pal[1]);
            pack_hl(Sf[2*kk2+1][0], Sf[2*kk2+1][1], &pah[2], &pal[2]);
            pack_hl(Sf[2*kk2+1][2], Sf[2*kk2+1][3], &pah[3], &pal[3]);

            uint32_t VH[16], VL[16];
#pragma unroll
            for (int ntp = 0; ntp < 4; ntp++) {
                ldsm_x4(VH + 4*ntp, kb + 2*ATT_TSZ + offb + (uint32_t)(ntp*2304 + kk2*32));
                ldsm_x4(VL + 4*ntp, kb + 3*ATT_TSZ + offb + (uint32_t)(ntp*2304 + kk2*32));
            }
#pragma unroll
            for (int nt = 0; nt < 8; nt++)
                mma_bf16(Of[nt], pah, VH[2*nt], VH[2*nt+1]);
#pragma unroll
            for (int nt = 0; nt < 8; nt++)
                mma_bf16(Of[nt], pah, VL[2*nt], VL[2*nt+1]);
#pragma unroll
            for (int nt = 0; nt < 8; nt++)
                mma_bf16(Of[nt], pal, VH[2*nt], VH[2*nt+1]);
        }
        __syncthreads();
    }

    // ---- epilogue: O/l -> bf16 hi/lo at [b][s][h*64+d] ----
    const float inva = 1.f / l_a, invb = 1.f / l_b;
    const int sa_row = qt*128 + w*16 + gid;
    const size_t base_a = ((size_t)(bq*SEQ + sa_row)) * EMB + hq*DHEAD + 2*tig;
    const size_t base_b = base_a + (size_t)8 * EMB;
#pragma unroll
    for (int nt = 0; nt < 8; nt++) {
        uint32_t hh, ll;
        pack_hl(Of[nt][0]*inva, Of[nt][1]*inva, &hh, &ll);
        *(uint32_t*)&Oh_g[base_a + nt*8] = hh;
        *(uint32_t*)&Ol_g[base_a + nt*8] = ll;
        pack_hl(Of[nt][2]*invb, Of[nt][3]*invb, &hh, &ll);
        *(uint32_t*)&Oh_g[base_b + nt*8] = hh;
        *(uint32_t*)&Ol_g[base_b + nt*8] = ll;
    }
}

// ---------------- launch ----------------
extern "C" void kernel_launch(void* const* d_in, const int* in_sizes, int n_in,
                              void* d_out, int out_size)
{
    (void)in_sizes; (void)n_in; (void)out_size;
    const float* x  = (const float*)d_in[0];
    const float* wq = (const float*)d_in[2];
    const float* bq = (const float*)d_in[3];
    const float* wk = (const float*)d_in[4];
    const float* bk = (const float*)d_in[5];
    const float* wv = (const float*)d_in[6];
    const float* bv = (const float*)d_in[7];
    const float* wo = (const float*)d_in[8];
    const float* bo = (const float*)d_in[9];
    float* out = (float*)d_out;

    __nv_bfloat16 *xh, *xl, *oh, *ol, *wh, *wl, *qh, *ql, *kh, *kl, *vh, *vl;
    cudaGetSymbolAddress((void**)&xh, g_xh);
    cudaGetSymbolAddress((void**)&xl, g_xl);
    cudaGetSymbolAddress((void**)&oh, g_oh);
    cudaGetSymbolAddress((void**)&ol, g_ol);
    cudaGetSymbolAddress((void**)&wh, g_wh);
    cudaGetSymbolAddress((void**)&wl, g_wl);
    cudaGetSymbolAddress((void**)&qh, g_qh);
    cudaGetSymbolAddress((void**)&ql, g_ql);
    cudaGetSymbolAddress((void**)&kh, g_kh);
    cudaGetSymbolAddress((void**)&kl, g_kl);
    cudaGetSymbolAddress((void**)&vh, g_vh);
    cudaGetSymbolAddress((void**)&vl, g_vl);

    const int W = EMB*EMB;

    split_bf16<<<(MROWS*EMB/4)/256, 256>>>(x, xh, xl, MROWS*EMB/4);
    split_bf16_w<<<dim3((W/4)/256, 4), 256>>>(wq, wk, wv, wo, wh, wl);

    cudaFuncSetAttribute(mma_gemm, cudaFuncAttributeMaxDynamicSharedMemorySize, GEMM_SMEM_DYN);
    const dim3 gGrid(NDIM/128, MROWS/128);   // (8, 64)

    mma_gemm<<<gGrid, 256, GEMM_SMEM_DYN>>>(xh, xl, wh + 0*W, wl + 0*W, bq, qh, ql, QSCALE, MODE_QKBF);
    mma_gemm<<<gGrid, 256, GEMM_SMEM_DYN>>>(xh, xl, wh + 1*W, wl + 1*W, bk, kh, kl, 1.0f,   MODE_QKBF);
    mma_gemm<<<gGrid, 256, GEMM_SMEM_DYN>>>(xh, xl, wh + 2*W, wl + 2*W, bv, vh, vl, 1.0f,   MODE_VTBF);

    cudaFuncSetAttribute(attn_mma, cudaFuncAttributeMaxDynamicSharedMemorySize, ATT_SMEM);
    attn_mma<<<dim3(SEQ/128, BATCH*HEADS), 256, ATT_SMEM>>>(qh, ql, kh, kl, vh, vl, oh, ol);

    mma_gemm<<<gGrid, 256, GEMM_SMEM_DYN>>>(oh, ol, wh + 3*W, wl + 3*W, bo, out, nullptr, 1.0f, MODE_PLAIN);
}

// round 6
// speedup vs baseline: 2.2394x; 1.0068x over previous
#include <cuda_runtime.h>
#include <cuda_bf16.h>
#include <mma.h>
#include <math.h>
#include <stdint.h>

using namespace nvcuda;

// Problem constants
#define BATCH 4
#define SEQ   2048
#define EMB   1024
#define HEADS 16
#define DHEAD 64
#define MROWS (BATCH*SEQ)   // 8192
#define KDIM  1024
#define NDIM  1024

#define MODE_PLAIN 0   // fp32 [m][n]
#define MODE_QKBF  1   // bf16 hi/lo, [bh][s][d]
#define MODE_VTBF  2   // bf16 hi/lo, [bh][d][s]

// 0.125 (1/sqrt(D)) * log2(e): folded into Q so softmax uses ex2 directly
#define QSCALE 0.18033688011112042f

// ---------------- scratch (device globals per allocation rules) ----------------
__device__ __nv_bfloat16 g_xh[MROWS*EMB];
__device__ __nv_bfloat16 g_xl[MROWS*EMB];
__device__ __nv_bfloat16 g_oh[MROWS*EMB];
__device__ __nv_bfloat16 g_ol[MROWS*EMB];
__device__ __nv_bfloat16 g_wh[4][EMB*EMB];
__device__ __nv_bfloat16 g_wl[4][EMB*EMB];
__device__ __nv_bfloat16 g_qh[MROWS*EMB];  // [bh][s][d]
__device__ __nv_bfloat16 g_ql[MROWS*EMB];
__device__ __nv_bfloat16 g_kh[MROWS*EMB];  // [bh][s][d]
__device__ __nv_bfloat16 g_kl[MROWS*EMB];
__device__ __nv_bfloat16 g_vh[MROWS*EMB];  // [bh][d][s]
__device__ __nv_bfloat16 g_vl[MROWS*EMB];

// ---------------- helpers ----------------
__device__ __forceinline__ uint32_t smem_to_u32(const void* p) {
    uint32_t a;
    asm("{ .reg .u64 tmp; cvta.to.shared.u64 tmp, %1; cvt.u32.u64 %0, tmp; }"
        : "=r"(a) : "l"(p));
    return a;
}
__device__ __forceinline__ void cp_async16(uint32_t dst, const void* src) {
    asm volatile("cp.async.cg.shared.global [%0], [%1], 16;" :: "r"(dst), "l"(src));
}
#define CP_COMMIT() asm volatile("cp.async.commit_group;" ::: "memory")
#define CP_WAIT0()  asm volatile("cp.async.wait_group 0;" ::: "memory")
#define CP_WAIT1()  asm volatile("cp.async.wait_group 1;" ::: "memory")

__device__ __forceinline__ float fast_ex2(float x) {
    float y;
    asm("ex2.approx.ftz.f32 %0, %1;" : "=f"(y) : "f"(x));
    return y;
}

// ldmatrix x4: loads 4 8x8 b16 matrices; lane 8i..8i+7 provide row addresses of matrix i
__device__ __forceinline__ void ldsm_x4(uint32_t* r, uint32_t addr) {
    asm volatile("ldmatrix.sync.aligned.m8n8.x4.shared.b16 {%0,%1,%2,%3}, [%4];"
        : "=r"(r[0]), "=r"(r[1]), "=r"(r[2]), "=r"(r[3]) : "r"(addr));
}

// mma.sync m16n8k16 row.col f32.bf16.bf16.f32, accumulating
__device__ __forceinline__ void mma_bf16(float* c, const uint32_t* a, uint32_t b0, uint32_t b1) {
    asm volatile(
        "mma.sync.aligned.m16n8k16.row.col.f32.bf16.bf16.f32 "
        "{%0,%1,%2,%3},{%4,%5,%6,%7},{%8,%9},{%0,%1,%2,%3};"
        : "+f"(c[0]), "+f"(c[1]), "+f"(c[2]), "+f"(c[3])
        : "r"(a[0]), "r"(a[1]), "r"(a[2]), "r"(a[3]), "r"(b0), "r"(b1));
}

// fp32 pair -> bf16 hi pair + bf16 lo pair (packed u32, first element in low half)
__device__ __forceinline__ void pack_hl(float x, float y, uint32_t* h, uint32_t* l) {
    __nv_bfloat162 hh = __floats2bfloat162_rn(x, y);
    float rx = x - __bfloat162float(hh.x);
    float ry = y - __bfloat162float(hh.y);
    __nv_bfloat162 ll = __floats2bfloat162_rn(rx, ry);
    *h = *(uint32_t*)&hh;
    *l = *(uint32_t*)&ll;
}

// ---------------- fp32 -> bf16 hi/lo splits ----------------
__global__ void split_bf16(const float* __restrict__ in, __nv_bfloat16* __restrict__ hi,
                           __nv_bfloat16* __restrict__ lo, int n4)
{
    int i = blockIdx.x * blockDim.x + threadIdx.x;
    if (i >= n4) return;
    float4 v = ((const float4*)in)[i];
    uint32_t h0, l0, h1, l1;
    pack_hl(v.x, v.y, &h0, &l0);
    pack_hl(v.z, v.w, &h1, &l1);
    ((uint32_t*)hi)[2*i]   = h0; ((uint32_t*)hi)[2*i+1] = h1;
    ((uint32_t*)lo)[2*i]   = l0; ((uint32_t*)lo)[2*i+1] = l1;
}

__global__ void split_bf16_w(const float* __restrict__ w0, const float* __restrict__ w1,
                             const float* __restrict__ w2, const float* __restrict__ w3,
                             __nv_bfloat16* __restrict__ hi, __nv_bfloat16* __restrict__ lo)
{
    const float* srcs[4] = {w0, w1, w2, w3};
    const int ws = blockIdx.y;
    const float* in = srcs[ws];
    const size_t base = (size_t)ws * (EMB*EMB);
    int i = blockIdx.x * blockDim.x + threadIdx.x;
    float4 v = ((const float4*)in)[i];
    uint32_t h0, l0, h1, l1;
    pack_hl(v.x, v.y, &h0, &l0);
    pack_hl(v.z, v.w, &h1, &l1);
    ((uint32_t*)(hi + base))[2*i]   = h0; ((uint32_t*)(hi + base))[2*i+1] = h1;
    ((uint32_t*)(lo + base))[2*i]   = l0; ((uint32_t*)(lo + base))[2*i+1] = l1;
}

// ---------------- GEMM: C = ((Ah+Al) @ (Bh+Bl)^T + bias) * cscale ----------------
// 512 threads, 16 warps, each warp owns a 32x32 output tile (2x2 wmma frags).
#define LDP        72
#define TILE_P     (128*LDP*2)             // 18432 B
#define STAGE_P    (4*TILE_P)              // 73728 B
#define GEMM_SMEM_DYN (1024 + 2*STAGE_P)   // 148480 B

__global__ void __launch_bounds__(512, 1)
mma_gemm(const __nv_bfloat16* __restrict__ Ah, const __nv_bfloat16* __restrict__ Al,
         const __nv_bfloat16* __restrict__ Bh, const __nv_bfloat16* __restrict__ Bl,
         const float* __restrict__ bias, void* __restrict__ C0, void* __restrict__ C1,
         float cscale, int mode)
{
    extern __shared__ __align__(1024) char smem[];
    const uint32_t smem_u = smem_to_u32(smem);
    const int t   = threadIdx.x;
    const int bm  = blockIdx.y * 128;
    const int bn  = blockIdx.x * 128;

    const int wid = t >> 5;          // 0..15
    const int m0  = (wid >> 2) * 32; // 4 warp-rows
    const int n0  = (wid & 3) * 32;  // 4 warp-cols

    wmma::fragment<wmma::accumulator, 16, 16, 16, float> acc[2][2];
#pragma unroll
    for (int i = 0; i < 2; i++)
#pragma unroll
        for (int j = 0; j < 2; j++) wmma::fill_fragment(acc[i][j], 0.f);

    const __nv_bfloat16* srcs[4] = {Ah, Al, Bh, Bl};
    const int r0s[4] = {bm, bm, bn, bn};

    auto load_stage = [&](int s, int ic) {
        const uint32_t sb = smem_u + 1024 + (uint32_t)s * STAGE_P;
        const int kc = ic * 64;
#pragma unroll
        for (int tl = 0; tl < 4; tl++) {
            const __nv_bfloat16* g = srcs[tl] + (size_t)r0s[tl] * KDIM + kc;
#pragma unroll
            for (int j = 0; j < 2; j++) {
                int idx = t + j * 512;            // 0..1023
                int r   = idx >> 3;               // 0..127
                int c16 = idx & 7;                // 16B chunk within 128B row
                cp_async16(sb + (uint32_t)(tl*TILE_P + r*144 + c16*16),
                           g + (size_t)r * KDIM + c16*8);
            }
        }
        CP_COMMIT();
    };

    load_stage(0, 0);

    for (int ic = 0; ic < 16; ic++) {
        if (ic + 1 < 16) load_stage((ic + 1) & 1, ic + 1);
        if (ic + 1 < 16) { CP_WAIT1(); } else { CP_WAIT0(); }
        __syncthreads();

        const char* sb = smem + 1024 + (size_t)(ic & 1) * STAGE_P;
        const __nv_bfloat16* Ahs = (const __nv_bfloat16*)(sb);
        const __nv_bfloat16* Als = (const __nv_bfloat16*)(sb + TILE_P);
        const __nv_bfloat16* Bhs = (const __nv_bfloat16*)(sb + 2*TILE_P);
        const __nv_bfloat16* Bls = (const __nv_bfloat16*)(sb + 3*TILE_P);

#pragma unroll
        for (int k0 = 0; k0 < 64; k0 += 16) {
            wmma::fragment<wmma::matrix_a, 16, 16, 16, __nv_bfloat16, wmma::row_major> aH[2], aL[2];
            wmma::fragment<wmma::matrix_b, 16, 16, 16, __nv_bfloat16, wmma::col_major> bF[2];
#pragma unroll
            for (int i = 0; i < 2; i++)
                wmma::load_matrix_sync(aH[i], Ahs + (m0 + 16*i) * LDP + k0, LDP);
#pragma unroll
            for (int j = 0; j < 2; j++)
                wmma::load_matrix_sync(bF[j], Bhs + (n0 + 16*j) * LDP + k0, LDP);
#pragma unroll
            for (int i = 0; i < 2; i++)
#pragma unroll
                for (int j = 0; j < 2; j++)
                    wmma::mma_sync(acc[i][j], aH[i], bF[j], acc[i][j]);
#pragma unroll
            for (int i = 0; i < 2; i++)
                wmma::load_matrix_sync(aL[i], Als + (m0 + 16*i) * LDP + k0, LDP);
#pragma unroll
            for (int i = 0; i < 2; i++)
#pragma unroll
                for (int j = 0; j < 2; j++)
                    wmma::mma_sync(acc[i][j], aL[i], bF[j], acc[i][j]);
#pragma unroll
            for (int j = 0; j < 2; j++)
                wmma::load_matrix_sync(bF[j], Bls + (n0 + 16*j) * LDP + k0, LDP);
#pragma unroll
            for (int i = 0; i < 2; i++)
#pragma unroll
                for (int j = 0; j < 2; j++)
                    wmma::mma_sync(acc[i][j], aH[i], bF[j], acc[i][j]);
        }
        __syncthreads();
    }

    // Stage full fp32 tile through smem (ld=132), then scatter per mode
    float* Cs = (float*)smem;
#pragma unroll
    for (int i = 0; i < 2; i++)
#pragma unroll
        for (int j = 0; j < 2; j++)
            wmma::store_matrix_sync(Cs + (m0 + 16*i) * 132 + n0 + 16*j, acc[i][j],
                                    132, wmma::mem_row_major);
    __syncthreads();

    if (mode == MODE_PLAIN) {
        const int r  = t >> 2;              // 0..127
        const int c0 = (t & 3) * 32;        // 0..96
        const int gm = bm + r;
        float* out = (float*)C0 + (size_t)gm * NDIM + bn + c0;
        const float* row = Cs + r * 132 + c0;
        const float* bp  = bias + bn + c0;
#pragma unroll
        for (int j = 0; j < 32; j += 4)
            *(float4*)(out + j) = make_float4(row[j]   + bp[j],
                                              row[j+1] + bp[j+1],
                                              row[j+2] + bp[j+2],
                                              row[j+3] + bp[j+3]);
    } else if (mode == MODE_QKBF) {
        const int r  = t >> 2;
        const int c0 = (t & 3) * 32;
        const int gm = bm + r;
        const int b  = gm >> 11, sq = gm & 2047;
        const int gc = bn + c0;
        const int h  = gc >> 6, d0 = gc & 63;   // 32-col chunk: d0 in {0,32}
        __nv_bfloat16* Oh = (__nv_bfloat16*)C0 + (((size_t)(b*HEADS + h) * SEQ + sq) * DHEAD) + d0;
        __nv_bfloat16* Ol = (__nv_bfloat16*)C1 + (((size_t)(b*HEADS + h) * SEQ + sq) * DHEAD) + d0;
        const float* row = Cs + r * 132 + c0;
        const float* bp  = bias + gc;
#pragma unroll
        for (int j = 0; j < 32; j += 2) {
            float v0 = (row[j]   + bp[j])   * cscale;
            float v1 = (row[j+1] + bp[j+1]) * cscale;
            uint32_t hh, ll;
            pack_hl(v0, v1, &hh, &ll);
            *(uint32_t*)(Oh + j) = hh;
            *(uint32_t*)(Ol + j) = ll;
        }
    } else { // MODE_VTBF: [bh][d][s]
        const int n  = t >> 2;               // tile-local col (head-dim idx)
        const int s0 = (t & 3) * 32;         // 32-row strip
        const int gn = bn + n, h = gn >> 6, d = gn & 63;
        const int gm0 = bm + s0;
        const int b = gm0 >> 11, sq0 = gm0 & 2047;
        const float bv = bias[gn];
        __nv_bfloat16* Oh = (__nv_bfloat16*)C0 + (((size_t)(b*HEADS + h) * DHEAD + d) * SEQ) + sq0;
        __nv_bfloat16* Ol = (__nv_bfloat16*)C1 + (((size_t)(b*HEADS + h) * DHEAD + d) * SEQ) + sq0;
#pragma unroll 4
        for (int r = 0; r < 32; r += 2) {
            float v0 = Cs[(s0 + r)     * 132 + n] + bv;
            float v1 = Cs[(s0 + r + 1) * 132 + n] + bv;
            uint32_t hh, ll;
            pack_hl(v0, v1, &hh, &ll);
            *(uint32_t*)(Oh + r) = hh;
            *(uint32_t*)(Ol + r) = ll;
        }
    }
}

// ---------------- Flash attention, mma.sync bf16 3-term split, ldmatrix loads ----------------
// Q,K: [bh][s][d] hi/lo.  V: [bh][d][s] hi/lo.  O -> g_oh/g_ol [b][s][e] hi/lo.
#define ATT_QSZ   (128*72*2)    // 18432 B per Q buffer
#define ATT_TSZ   (64*72*2)     // 9216 B per K/V tile
#define ATT_STAGE (4*ATT_TSZ)   // 36864 B
#define ATT_SMEM  (2*ATT_QSZ + 2*ATT_STAGE)  // 110592 B

__global__ void __launch_bounds__(256, 1)
attn_mma(const __nv_bfloat16* __restrict__ Qh_g, const __nv_bfloat16* __restrict__ Ql_g,
         const __nv_bfloat16* __restrict__ Kh_g, const __nv_bfloat16* __restrict__ Kl_g,
         const __nv_bfloat16* __restrict__ Vh_g, const __nv_bfloat16* __restrict__ Vl_g,
         __nv_bfloat16* __restrict__ Oh_g, __nv_bfloat16* __restrict__ Ol_g)
{
    extern __shared__ __align__(128) char sm_[];
    const uint32_t su = smem_to_u32(sm_);
    const int t    = threadIdx.x;
    const int w    = t >> 5;
    const int lane = t & 31;
    const int gid  = lane >> 2;
    const int tig  = lane & 3;
    const int qt   = (gridDim.x - 1) - blockIdx.x;   // big tiles first
    const int bh   = blockIdx.y;
    const int bq   = bh >> 4, hq = bh & 15;

    const uint32_t aq_off = (uint32_t)((w*16 + (lane & 15))*144 + ((lane >> 4) * 16));
    const uint32_t offb = (uint32_t)((((lane & 7) + ((lane >> 4) << 3)) * 144) + (((lane >> 3) & 1) * 16));

    const __nv_bfloat16* Qhg = Qh_g + ((size_t)bh * SEQ + qt * 128) * DHEAD;
    const __nv_bfloat16* Qlg = Ql_g + ((size_t)bh * SEQ + qt * 128) * DHEAD;

#pragma unroll
    for (int j = 0; j < 4; j++) {
        int idx = t + j * 256;
        int r   = idx >> 3;
        int c   = idx & 7;
        cp_async16(su + r*144 + c*16,            Qhg + r*DHEAD + c*8);
        cp_async16(su + ATT_QSZ + r*144 + c*16,  Qlg + r*DHEAD + c*8);
    }

    auto load_kv = [&](int stg, int jt) {
        const uint32_t sb = su + 2*ATT_QSZ + (uint32_t)stg * ATT_STAGE;
#pragma unroll
        for (int j = 0; j < 2; j++) {
            int idx = t + j * 256;
            int r   = idx >> 3;
            int c   = idx & 7;
            const size_t ko = ((size_t)bh * SEQ + jt*64 + r) * DHEAD + c*8;
            cp_async16(sb +             r*144 + c*16, Kh_g + ko);
            cp_async16(sb + ATT_TSZ   + r*144 + c*16, Kl_g + ko);
            const size_t vo = ((size_t)bh * DHEAD + r) * SEQ + jt*64 + c*8;
            cp_async16(sb + 2*ATT_TSZ + r*144 + c*16, Vh_g + vo);
            cp_async16(sb + 3*ATT_TSZ + r*144 + c*16, Vl_g + vo);
        }
    };

    load_kv(0, 0);
    CP_COMMIT();

    float Of[8][4];
#pragma unroll
    for (int i = 0; i < 8; i++)
#pragma unroll
        for (int j = 0; j < 4; j++) Of[i][j] = 0.f;
    float m_a = -1e30f, m_b = -1e30f, l_a = 0.f, l_b = 0.f;

    uint32_t qh[4][4], ql[4][4];

    const int jt_end = 2*qt + 1;
    const int rga = qt*128 + w*16 + gid;
    const int rgb = rga + 8;

    for (int jt = 0; jt <= jt_end; jt++) {
        if (jt < jt_end) { load_kv((jt + 1) & 1, jt + 1); CP_COMMIT(); CP_WAIT1(); }
        else             { CP_WAIT0(); }
        __syncthreads();

        if (jt == 0) {
#pragma unroll
            for (int kk = 0; kk < 4; kk++) {
                ldsm_x4(qh[kk], su + aq_off + kk*32);
                ldsm_x4(ql[kk], su + ATT_QSZ + aq_off + kk*32);
            }
        }

        const uint32_t kb = su + 2*ATT_QSZ + (uint32_t)(jt & 1) * ATT_STAGE;

        // ---- S = Q K^T ----
        float Sf[8][4];
#pragma unroll
        for (int i = 0; i < 8; i++)
#pragma unroll
            for (int j = 0; j < 4; j++) Sf[i][j] = 0.f;

#pragma unroll
        for (int kk = 0; kk < 4; kk++) {
            uint32_t KH[16], KL[16];
#pragma unroll
            for (int ntp = 0; ntp < 4; ntp++) {
                ldsm_x4(KH + 4*ntp, kb + offb + (uint32_t)(ntp*2304 + kk*32));
                ldsm_x4(KL + 4*ntp, kb + ATT_TSZ + offb + (uint32_t)(ntp*2304 + kk*32));
            }
#pragma unroll
            for (int nt = 0; nt < 8; nt++)
                mma_bf16(Sf[nt], qh[kk], KH[2*nt], KH[2*nt+1]);
#pragma unroll
            for (int nt = 0; nt < 8; nt++)
                mma_bf16(Sf[nt], qh[kk], KL[2*nt], KL[2*nt+1]);
#pragma unroll
            for (int nt = 0; nt < 8; nt++)
                mma_bf16(Sf[nt], ql[kk], KH[2*nt], KH[2*nt+1]);
        }

        // ---- causal mask ----
        if (jt >= 2*qt) {
#pragma unroll
            for (int nt = 0; nt < 8; nt++) {
                const int cg = jt*64 + nt*8 + 2*tig;
                if (cg     > rga) Sf[nt][0] = -1e30f;
                if (cg + 1 > rga) Sf[nt][1] = -1e30f;
                if (cg     > rgb) Sf[nt][2] = -1e30f;
                if (cg + 1 > rgb) Sf[nt][3] = -1e30f;
            }
        }

        // ---- online softmax (base-2) ----
        float va = -1e30f, vb = -1e30f;
#pragma unroll
        for (int nt = 0; nt < 8; nt++) {
            va = fmaxf(va, fmaxf(Sf[nt][0], Sf[nt][1]));
            vb = fmaxf(vb, fmaxf(Sf[nt][2], Sf[nt][3]));
        }
        va = fmaxf(va, __shfl_xor_sync(0xffffffffu, va, 1));
        va = fmaxf(va, __shfl_xor_sync(0xffffffffu, va, 2));
        vb = fmaxf(vb, __shfl_xor_sync(0xffffffffu, vb, 1));
        vb = fmaxf(vb, __shfl_xor_sync(0xffffffffu, vb, 2));

        const float mna = fmaxf(m_a, va), mnb = fmaxf(m_b, vb);
        const float aa = fast_ex2(m_a - mna), ab = fast_ex2(m_b - mnb);
        float sa = 0.f, sb = 0.f;
#pragma unroll
        for (int nt = 0; nt < 8; nt++) {
            Sf[nt][0] = fast_ex2(Sf[nt][0] - mna);
            Sf[nt][1] = fast_ex2(Sf[nt][1] - mna);
            Sf[nt][2] = fast_ex2(Sf[nt][2] - mnb);
            Sf[nt][3] = fast_ex2(Sf[nt][3] - mnb);
            sa += Sf[nt][0] + Sf[nt][1];
            sb += Sf[nt][2] + Sf[nt][3];
        }
        sa += __shfl_xor_sync(0xffffffffu, sa, 1);
        sa += __shfl_xor_sync(0xffffffffu, sa, 2);
        sb += __shfl_xor_sync(0xffffffffu, sb, 1);
        sb += __shfl_xor_sync(0xffffffffu, sb, 2);
        l_a = l_a * aa + sa;
        l_b = l_b * ab + sb;
        m_a = mna; m_b = mnb;
#pragma unroll
        for (int nt = 0; nt < 8; nt++) {
            Of[nt][0] *= aa; Of[nt][1] *= aa;
            Of[nt][2] *= ab; Of[nt][3] *= ab;
        }

        // ---- O += P V ----
#pragma unroll
        for (int kk2 = 0; kk2 < 4; kk2++) {
            uint32_t pah[4], pal[4];
            pack_hl(Sf[2*kk2][0],   Sf[2*kk2][1],   &pah[0], &pal[0]);
            pack_hl(Sf[2*kk2][2],   Sf[2*kk2][3],   &pah[1], &pal[1]);
            pack_hl(Sf[2*kk2+1][0], Sf[2*kk2+1][1], &pah[2], &pal[2]);
            pack_hl(Sf[2*kk2+1][2], Sf[2*kk2+1][3], &pah[3], &pal[3]);

            uint32_t VH[16], VL[16];
#pragma unroll
            for (int ntp = 0; ntp < 4; ntp++) {
                ldsm_x4(VH + 4*ntp, kb + 2*ATT_TSZ + offb + (uint32_t)(ntp*2304 + kk2*32));
                ldsm_x4(VL + 4*ntp, kb + 3*ATT_TSZ + offb + (uint32_t)(ntp*2304 + kk2*32));
            }
#pragma unroll
            for (int nt = 0; nt < 8; nt++)
                mma_bf16(Of[nt], pah, VH[2*nt], VH[2*nt+1]);
#pragma unroll
            for (int nt = 0; nt < 8; nt++)
                mma_bf16(Of[nt], pah, VL[2*nt], VL[2*nt+1]);
#pragma unroll
            for (int nt = 0; nt < 8; nt++)
                mma_bf16(Of[nt], pal, VH[2*nt], VH[2*nt+1]);
        }
        __syncthreads();
    }

    // ---- epilogue ----
    const float inva = 1.f / l_a, invb = 1.f / l_b;
    const int sa_row = qt*128 + w*16 + gid;
    const size_t base_a = ((size_t)(bq*SEQ + sa_row)) * EMB + hq*DHEAD + 2*tig;
    const size_t base_b = base_a + (size_t)8 * EMB;
#pragma unroll
    for (int nt = 0; nt < 8; nt++) {
        uint32_t hh, ll;
        pack_hl(Of[nt][0]*inva, Of[nt][1]*inva, &hh, &ll);
        *(uint32_t*)&Oh_g[base_a + nt*8] = hh;
        *(uint32_t*)&Ol_g[base_a + nt*8] = ll;
        pack_hl(Of[nt][2]*invb, Of[nt][3]*invb, &hh, &ll);
        *(uint32_t*)&Oh_g[base_b + nt*8] = hh;
        *(uint32_t*)&Ol_g[base_b + nt*8] = ll;
    }
}

// ---------------- launch ----------------
extern "C" void kernel_launch(void* const* d_in, const int* in_sizes, int n_in,
                              void* d_out, int out_size)
{
    (void)in_sizes; (void)n_in; (void)out_size;
    const float* x  = (const float*)d_in[0];
    const float* wq = (const float*)d_in[2];
    const float* bq = (const float*)d_in[3];
    const float* wk = (const float*)d_in[4];
    const float* bk = (const float*)d_in[5];
    const float* wv = (const float*)d_in[6];
    const float* bv = (const float*)d_in[7];
    const float* wo = (const float*)d_in[8];
    const float* bo = (const float*)d_in[9];
    float* out = (float*)d_out;

    __nv_bfloat16 *xh, *xl, *oh, *ol, *wh, *wl, *qh, *ql, *kh, *kl, *vh, *vl;
    cudaGetSymbolAddress((void**)&xh, g_xh);
    cudaGetSymbolAddress((void**)&xl, g_xl);
    cudaGetSymbolAddress((void**)&oh, g_oh);
    cudaGetSymbolAddress((void**)&ol, g_ol);
    cudaGetSymbolAddress((void**)&wh, g_wh);
    cudaGetSymbolAddress((void**)&wl, g_wl);
    cudaGetSymbolAddress((void**)&qh, g_qh);
    cudaGetSymbolAddress((void**)&ql, g_ql);
    cudaGetSymbolAddress((void**)&kh, g_kh);
    cudaGetSymbolAddress((void**)&kl, g_kl);
    cudaGetSymbolAddress((void**)&vh, g_vh);
    cudaGetSymbolAddress((void**)&vl, g_vl);

    const int W = EMB*EMB;

    split_bf16<<<(MROWS*EMB/4)/256, 256>>>(x, xh, xl, MROWS*EMB/4);
    split_bf16_w<<<dim3((W/4)/256, 4), 256>>>(wq, wk, wv, wo, wh, wl);

    cudaFuncSetAttribute(mma_gemm, cudaFuncAttributeMaxDynamicSharedMemorySize, GEMM_SMEM_DYN);
    const dim3 gGrid(NDIM/128, MROWS/128);   // (8, 64)

    mma_gemm<<<gGrid, 512, GEMM_SMEM_DYN>>>(xh, xl, wh + 0*W, wl + 0*W, bq, qh, ql, QSCALE, MODE_QKBF);
    mma_gemm<<<gGrid, 512, GEMM_SMEM_DYN>>>(xh, xl, wh + 1*W, wl + 1*W, bk, kh, kl, 1.0f,   MODE_QKBF);
    mma_gemm<<<gGrid, 512, GEMM_SMEM_DYN>>>(xh, xl, wh + 2*W, wl + 2*W, bv, vh, vl, 1.0f,   MODE_VTBF);

    cudaFuncSetAttribute(attn_mma, cudaFuncAttributeMaxDynamicSharedMemorySize, ATT_SMEM);
    attn_mma<<<dim3(SEQ/128, BATCH*HEADS), 256, ATT_SMEM>>>(qh, ql, kh, kl, vh, vl, oh, ol);

    mma_gemm<<<gGrid, 512, GEMM_SMEM_DYN>>>(oh, ol, wh + 3*W, wl + 3*W, bo, out, nullptr, 1.0f, MODE_PLAIN);
}

// round 7
// speedup vs baseline: 2.3083x; 1.0308x over previous
#include <cuda_runtime.h>
#include <cuda_bf16.h>
#include <mma.h>
#include <math.h>
#include <stdint.h>

using namespace nvcuda;

// Problem constants
#define BATCH 4
#define SEQ   2048
#define EMB   1024
#define HEADS 16
#define DHEAD 64
#define MROWS (BATCH*SEQ)   // 8192
#define KDIM  1024
#define NDIM  1024

#define MODE_PLAIN 0   // fp32 [m][n]
#define MODE_QKBF  1   // bf16 hi/lo, [bh][s][d]
#define MODE_VTBF  2   // bf16 hi/lo, [bh][d][s]

// 0.125 (1/sqrt(D)) * log2(e): folded into Q so softmax uses ex2 directly
#define QSCALE 0.18033688011112042f

// ---------------- scratch (device globals per allocation rules) ----------------
__device__ __nv_bfloat16 g_xh[MROWS*EMB];
__device__ __nv_bfloat16 g_xl[MROWS*EMB];
__device__ __nv_bfloat16 g_oh[MROWS*EMB];
__device__ __nv_bfloat16 g_ol[MROWS*EMB];
__device__ __nv_bfloat16 g_wh[4][EMB*EMB];
__device__ __nv_bfloat16 g_wl[4][EMB*EMB];
__device__ __nv_bfloat16 g_qh[MROWS*EMB];  // [bh][s][d]
__device__ __nv_bfloat16 g_ql[MROWS*EMB];
__device__ __nv_bfloat16 g_kh[MROWS*EMB];  // [bh][s][d]
__device__ __nv_bfloat16 g_kl[MROWS*EMB];
__device__ __nv_bfloat16 g_vh[MROWS*EMB];  // [bh][d][s]
__device__ __nv_bfloat16 g_vl[MROWS*EMB];

// ---------------- helpers ----------------
__device__ __forceinline__ uint32_t smem_to_u32(const void* p) {
    uint32_t a;
    asm("{ .reg .u64 tmp; cvta.to.shared.u64 tmp, %1; cvt.u32.u64 %0, tmp; }"
        : "=r"(a) : "l"(p));
    return a;
}
__device__ __forceinline__ void cp_async16(uint32_t dst, const void* src) {
    asm volatile("cp.async.cg.shared.global [%0], [%1], 16;" :: "r"(dst), "l"(src));
}
#define CP_COMMIT() asm volatile("cp.async.commit_group;" ::: "memory")
#define CP_WAIT0()  asm volatile("cp.async.wait_group 0;" ::: "memory")
#define CP_WAIT1()  asm volatile("cp.async.wait_group 1;" ::: "memory")

__device__ __forceinline__ float fast_ex2(float x) {
    float y;
    asm("ex2.approx.ftz.f32 %0, %1;" : "=f"(y) : "f"(x));
    return y;
}

// ldmatrix x4
__device__ __forceinline__ void ldsm_x4(uint32_t* r, uint32_t addr) {
    asm volatile("ldmatrix.sync.aligned.m8n8.x4.shared.b16 {%0,%1,%2,%3}, [%4];"
        : "=r"(r[0]), "=r"(r[1]), "=r"(r[2]), "=r"(r[3]) : "r"(addr));
}

// mma.sync m16n8k16 row.col f32.bf16.bf16.f32, accumulating
__device__ __forceinline__ void mma_bf16(float* c, const uint32_t* a, uint32_t b0, uint32_t b1) {
    asm volatile(
        "mma.sync.aligned.m16n8k16.row.col.f32.bf16.bf16.f32 "
        "{%0,%1,%2,%3},{%4,%5,%6,%7},{%8,%9},{%0,%1,%2,%3};"
        : "+f"(c[0]), "+f"(c[1]), "+f"(c[2]), "+f"(c[3])
        : "r"(a[0]), "r"(a[1]), "r"(a[2]), "r"(a[3]), "r"(b0), "r"(b1));
}

// fp32 pair -> bf16 hi pair + bf16 lo pair
__device__ __forceinline__ void pack_hl(float x, float y, uint32_t* h, uint32_t* l) {
    __nv_bfloat162 hh = __floats2bfloat162_rn(x, y);
    float rx = x - __bfloat162float(hh.x);
    float ry = y - __bfloat162float(hh.y);
    __nv_bfloat162 ll = __floats2bfloat162_rn(rx, ry);
    *h = *(uint32_t*)&hh;
    *l = *(uint32_t*)&ll;
}

// ---------------- fp32 -> bf16 hi/lo splits ----------------
__global__ void split_bf16(const float* __restrict__ in, __nv_bfloat16* __restrict__ hi,
                           __nv_bfloat16* __restrict__ lo, int n4)
{
    int i = blockIdx.x * blockDim.x + threadIdx.x;
    if (i >= n4) return;
    float4 v = ((const float4*)in)[i];
    uint32_t h0, l0, h1, l1;
    pack_hl(v.x, v.y, &h0, &l0);
    pack_hl(v.z, v.w, &h1, &l1);
    ((uint32_t*)hi)[2*i]   = h0; ((uint32_t*)hi)[2*i+1] = h1;
    ((uint32_t*)lo)[2*i]   = l0; ((uint32_t*)lo)[2*i+1] = l1;
}

__global__ void split_bf16_w(const float* __restrict__ w0, const float* __restrict__ w1,
                             const float* __restrict__ w2, const float* __restrict__ w3,
                             __nv_bfloat16* __restrict__ hi, __nv_bfloat16* __restrict__ lo)
{
    const float* srcs[4] = {w0, w1, w2, w3};
    const int ws = blockIdx.y;
    const float* in = srcs[ws];
    const size_t base = (size_t)ws * (EMB*EMB);
    int i = blockIdx.x * blockDim.x + threadIdx.x;
    float4 v = ((const float4*)in)[i];
    uint32_t h0, l0, h1, l1;
    pack_hl(v.x, v.y, &h0, &l0);
    pack_hl(v.z, v.w, &h1, &l1);
    ((uint32_t*)(hi + base))[2*i]   = h0; ((uint32_t*)(hi + base))[2*i+1] = h1;
    ((uint32_t*)(lo + base))[2*i]   = l0; ((uint32_t*)(lo + base))[2*i+1] = l1;
}

// ---------------- GEMM: C = ((Ah+Al) @ (Bh+Bl)^T + bias) * cscale ----------------
// 256 threads (8 warps, warp tile 64x32), K-chunk 32, 2 CTAs/SM.
#define LDP        40                      // padded row length (bf16), 80 B stride
#define TILE_P     (128*LDP*2)             // 10240 B
#define STAGE_P    (4*TILE_P)              // 40960 B
#define GEMM_SMEM_DYN (1024 + 2*STAGE_P)   // 82944 B  -> 2 CTAs per SM

__global__ void __launch_bounds__(256, 2)
mma_gemm(const __nv_bfloat16* __restrict__ Ah, const __nv_bfloat16* __restrict__ Al,
         const __nv_bfloat16* __restrict__ Bh, const __nv_bfloat16* __restrict__ Bl,
         const float* __restrict__ bias, void* __restrict__ C0, void* __restrict__ C1,
         float cscale, int mode)
{
    extern __shared__ __align__(1024) char smem[];
    const uint32_t smem_u = smem_to_u32(smem);
    const int t   = threadIdx.x;
    const int bm  = blockIdx.y * 128;
    const int bn  = blockIdx.x * 128;

    const int wid = t >> 5;          // 0..7
    const int m0  = (wid >> 2) * 64; // 2 warp-rows
    const int n0  = (wid & 3) * 32;  // 4 warp-cols

    wmma::fragment<wmma::accumulator, 16, 16, 16, float> acc[4][2];
#pragma unroll
    for (int i = 0; i < 4; i++)
#pragma unroll
        for (int j = 0; j < 2; j++) wmma::fill_fragment(acc[i][j], 0.f);

    const __nv_bfloat16* srcs[4] = {Ah, Al, Bh, Bl};
    const int r0s[4] = {bm, bm, bn, bn};

    // load one K-chunk (32 wide): 4 tiles of 128x32 bf16 -> rows padded to 80 B
    auto load_stage = [&](int s, int ic) {
        const uint32_t sb = smem_u + 1024 + (uint32_t)s * STAGE_P;
        const int kc = ic * 32;
#pragma unroll
        for (int tl = 0; tl < 4; tl++) {
            const __nv_bfloat16* g = srcs[tl] + (size_t)r0s[tl] * KDIM + kc;
#pragma unroll
            for (int j = 0; j < 2; j++) {
                int idx = t + j * 256;            // 0..511
                int r   = idx >> 2;               // 0..127
                int c16 = idx & 3;                // 16B chunk within 64B row
                cp_async16(sb + (uint32_t)(tl*TILE_P + r*80 + c16*16),
                           g + (size_t)r * KDIM + c16*8);
            }
        }
        CP_COMMIT();
    };

    load_stage(0, 0);

    for (int ic = 0; ic < 32; ic++) {
        if (ic + 1 < 32) load_stage((ic + 1) & 1, ic + 1);
        if (ic + 1 < 32) { CP_WAIT1(); } else { CP_WAIT0(); }
        __syncthreads();

        const char* sb = smem + 1024 + (size_t)(ic & 1) * STAGE_P;
        const __nv_bfloat16* Ahs = (const __nv_bfloat16*)(sb);
        const __nv_bfloat16* Als = (const __nv_bfloat16*)(sb + TILE_P);
        const __nv_bfloat16* Bhs = (const __nv_bfloat16*)(sb + 2*TILE_P);
        const __nv_bfloat16* Bls = (const __nv_bfloat16*)(sb + 3*TILE_P);

#pragma unroll
        for (int k0 = 0; k0 < 32; k0 += 16) {
            wmma::fragment<wmma::matrix_a, 16, 16, 16, __nv_bfloat16, wmma::row_major> aH[4], aL[4];
            wmma::fragment<wmma::matrix_b, 16, 16, 16, __nv_bfloat16, wmma::col_major> bF[2];
#pragma unroll
            for (int i = 0; i < 4; i++)
                wmma::load_matrix_sync(aH[i], Ahs + (m0 + 16*i) * LDP + k0, LDP);
#pragma unroll
            for (int j = 0; j < 2; j++)
                wmma::load_matrix_sync(bF[j], Bhs + (n0 + 16*j) * LDP + k0, LDP);
            // hi * hi
#pragma unroll
            for (int i = 0; i < 4; i++)
#pragma unroll
                for (int j = 0; j < 2; j++)
                    wmma::mma_sync(acc[i][j], aH[i], bF[j], acc[i][j]);
            // lo * hi
#pragma unroll
            for (int i = 0; i < 4; i++)
                wmma::load_matrix_sync(aL[i], Als + (m0 + 16*i) * LDP + k0, LDP);
#pragma unroll
            for (int i = 0; i < 4; i++)
#pragma unroll
                for (int j = 0; j < 2; j++)
                    wmma::mma_sync(acc[i][j], aL[i], bF[j], acc[i][j]);
            // hi * lo
#pragma unroll
            for (int j = 0; j < 2; j++)
                wmma::load_matrix_sync(bF[j], Bls + (n0 + 16*j) * LDP + k0, LDP);
#pragma unroll
            for (int i = 0; i < 4; i++)
#pragma unroll
                for (int j = 0; j < 2; j++)
                    wmma::mma_sync(acc[i][j], aH[i], bF[j], acc[i][j]);
        }
        __syncthreads();
    }

    // Stage full fp32 tile through smem (ld=132), then scatter per mode
    float* Cs = (float*)smem;
#pragma unroll
    for (int i = 0; i < 4; i++)
#pragma unroll
        for (int j = 0; j < 2; j++)
            wmma::store_matrix_sync(Cs + (m0 + 16*i) * 132 + n0 + 16*j, acc[i][j],
                                    132, wmma::mem_row_major);
    __syncthreads();

    if (mode == MODE_PLAIN) {
        const int r  = t >> 1;
        const int c0 = (t & 1) * 64;
        const int gm = bm + r;
        float* out = (float*)C0 + (size_t)gm * NDIM + bn + c0;
        const float* row = Cs + r * 132 + c0;
        const float* bp  = bias + bn + c0;
#pragma unroll
        for (int j = 0; j < 64; j += 4)
            *(float4*)(out + j) = make_float4(row[j]   + bp[j],
                                              row[j+1] + bp[j+1],
                                              row[j+2] + bp[j+2],
                                              row[j+3] + bp[j+3]);
    } else if (mode == MODE_QKBF) {
        const int r  = t >> 1;
        const int c0 = (t & 1) * 64;          // 64-col half = one head
        const int gm = bm + r;
        const int b  = gm >> 11, sq = gm & 2047;
        const int h  = (bn + c0) >> 6;
        __nv_bfloat16* Oh = (__nv_bfloat16*)C0 + (((size_t)(b*HEADS + h) * SEQ + sq) * DHEAD);
        __nv_bfloat16* Ol = (__nv_bfloat16*)C1 + (((size_t)(b*HEADS + h) * SEQ + sq) * DHEAD);
        const float* row = Cs + r * 132 + c0;
        const float* bp  = bias + bn + c0;
#pragma unroll
        for (int j = 0; j < 64; j += 2) {
            float v0 = (row[j]   + bp[j])   * cscale;
            float v1 = (row[j+1] + bp[j+1]) * cscale;
            uint32_t hh, ll;
            pack_hl(v0, v1, &hh, &ll);
            *(uint32_t*)(Oh + j) = hh;
            *(uint32_t*)(Ol + j) = ll;
        }
    } else { // MODE_VTBF: [bh][d][s]
        const int n  = t >> 1;                 // tile-local col (head-dim idx)
        const int s0 = (t & 1) * 64;
        const int gn = bn + n, h = gn >> 6, d = gn & 63;
        const int gm0 = bm + s0;
        const int b = gm0 >> 11, sq0 = gm0 & 2047;
        const float bv = bias[gn];
        __nv_bfloat16* Oh = (__nv_bfloat16*)C0 + (((size_t)(b*HEADS + h) * DHEAD + d) * SEQ) + sq0;
        __nv_bfloat16* Ol = (__nv_bfloat16*)C1 + (((size_t)(b*HEADS + h) * DHEAD + d) * SEQ) + sq0;
#pragma unroll 4
        for (int r = 0; r < 64; r += 2) {
            float v0 = Cs[(s0 + r)     * 132 + n] + bv;
            float v1 = Cs[(s0 + r + 1) * 132 + n] + bv;
            uint32_t hh, ll;
            pack_hl(v0, v1, &hh, &ll);
            *(uint32_t*)(Oh + r) = hh;
            *(uint32_t*)(Ol + r) = ll;
        }
    }
}

// ---------------- Flash attention, mma.sync bf16 3-term split, ldmatrix loads ----------------
#define ATT_QSZ   (128*72*2)    // 18432 B per Q buffer
#define ATT_TSZ   (64*72*2)     // 9216 B per K/V tile
#define ATT_STAGE (4*ATT_TSZ)   // 36864 B
#define ATT_SMEM  (2*ATT_QSZ + 2*ATT_STAGE)  // 110592 B

__global__ void __launch_bounds__(256, 1)
attn_mma(const __nv_bfloat16* __restrict__ Qh_g, const __nv_bfloat16* __restrict__ Ql_g,
         const __nv_bfloat16* __restrict__ Kh_g, const __nv_bfloat16* __restrict__ Kl_g,
         const __nv_bfloat16* __restrict__ Vh_g, const __nv_bfloat16* __restrict__ Vl_g,
         __nv_bfloat16* __restrict__ Oh_g, __nv_bfloat16* __restrict__ Ol_g)
{
    extern __shared__ __align__(128) char sm_[];
    const uint32_t su = smem_to_u32(sm_);
    const int t    = threadIdx.x;
    const int w    = t >> 5;
    const int lane = t & 31;
    const int gid  = lane >> 2;
    const int tig  = lane & 3;
    const int qt   = (gridDim.x - 1) - blockIdx.x;
    const int bh   = blockIdx.y;
    const int bq   = bh >> 4, hq = bh & 15;

    const uint32_t aq_off = (uint32_t)((w*16 + (lane & 15))*144 + ((lane >> 4) * 16));
    const uint32_t offb = (uint32_t)((((lane & 7) + ((lane >> 4) << 3)) * 144) + (((lane >> 3) & 1) * 16));

    const __nv_bfloat16* Qhg = Qh_g + ((size_t)bh * SEQ + qt * 128) * DHEAD;
    const __nv_bfloat16* Qlg = Ql_g + ((size_t)bh * SEQ + qt * 128) * DHEAD;

#pragma unroll
    for (int j = 0; j < 4; j++) {
        int idx = t + j * 256;
        int r   = idx >> 3;
        int c   = idx & 7;
        cp_async16(su + r*144 + c*16,            Qhg + r*DHEAD + c*8);
        cp_async16(su + ATT_QSZ + r*144 + c*16,  Qlg + r*DHEAD + c*8);
    }

    auto load_kv = [&](int stg, int jt) {
        const uint32_t sb = su + 2*ATT_QSZ + (uint32_t)stg * ATT_STAGE;
#pragma unroll
        for (int j = 0; j < 2; j++) {
            int idx = t + j * 256;
            int r   = idx >> 3;
            int c   = idx & 7;
            const size_t ko = ((size_t)bh * SEQ + jt*64 + r) * DHEAD + c*8;
            cp_async16(sb +             r*144 + c*16, Kh_g + ko);
            cp_async16(sb + ATT_TSZ   + r*144 + c*16, Kl_g + ko);
            const size_t vo = ((size_t)bh * DHEAD + r) * SEQ + jt*64 + c*8;
            cp_async16(sb + 2*ATT_TSZ + r*144 + c*16, Vh_g + vo);
            cp_async16(sb + 3*ATT_TSZ + r*144 + c*16, Vl_g + vo);
        }
    };

    load_kv(0, 0);
    CP_COMMIT();

    float Of[8][4];
#pragma unroll
    for (int i = 0; i < 8; i++)
#pragma unroll
        for (int j = 0; j < 4; j++) Of[i][j] = 0.f;
    float m_a = -1e30f, m_b = -1e30f, l_a = 0.f, l_b = 0.f;

    uint32_t qh[4][4], ql[4][4];

    const int jt_end = 2*qt + 1;
    const int rga = qt*128 + w*16 + gid;
    const int rgb = rga + 8;

    for (int jt = 0; jt <= jt_end; jt++) {
        if (jt < jt_end) { load_kv((jt + 1) & 1, jt + 1); CP_COMMIT(); CP_WAIT1(); }
        else             { CP_WAIT0(); }
        __syncthreads();

        if (jt == 0) {
#pragma unroll
            for (int kk = 0; kk < 4; kk++) {
                ldsm_x4(qh[kk], su + aq_off + kk*32);
                ldsm_x4(ql[kk], su + ATT_QSZ + aq_off + kk*32);
            }
        }

        const uint32_t kb = su + 2*ATT_QSZ + (uint32_t)(jt & 1) * ATT_STAGE;

        // ---- S = Q K^T ----
        float Sf[8][4];
#pragma unroll
        for (int i = 0; i < 8; i++)
#pragma unroll
            for (int j = 0; j < 4; j++) Sf[i][j] = 0.f;

#pragma unroll
        for (int kk = 0; kk < 4; kk++) {
            uint32_t KH[16], KL[16];
#pragma unroll
            for (int ntp = 0; ntp < 4; ntp++) {
                ldsm_x4(KH + 4*ntp, kb + offb + (uint32_t)(ntp*2304 + kk*32));
                ldsm_x4(KL + 4*ntp, kb + ATT_TSZ + offb + (uint32_t)(ntp*2304 + kk*32));
            }
#pragma unroll
            for (int nt = 0; nt < 8; nt++)
                mma_bf16(Sf[nt], qh[kk], KH[2*nt], KH[2*nt+1]);
#pragma unroll
            for (int nt = 0; nt < 8; nt++)
                mma_bf16(Sf[nt], qh[kk], KL[2*nt], KL[2*nt+1]);
#pragma unroll
            for (int nt = 0; nt < 8; nt++)
                mma_bf16(Sf[nt], ql[kk], KH[2*nt], KH[2*nt+1]);
        }

        // ---- causal mask ----
        if (jt >= 2*qt) {
#pragma unroll
            for (int nt = 0; nt < 8; nt++) {
                const int cg = jt*64 + nt*8 + 2*tig;
                if (cg     > rga) Sf[nt][0] = -1e30f;
                if (cg + 1 > rga) Sf[nt][1] = -1e30f;
                if (cg     > rgb) Sf[nt][2] = -1e30f;
                if (cg + 1 > rgb) Sf[nt][3] = -1e30f;
            }
        }

        // ---- online softmax (base-2) ----
        float va = -1e30f, vb = -1e30f;
#pragma unroll
        for (int nt = 0; nt < 8; nt++) {
            va = fmaxf(va, fmaxf(Sf[nt][0], Sf[nt][1]));
            vb = fmaxf(vb, fmaxf(Sf[nt][2], Sf[nt][3]));
        }
        va = fmaxf(va, __shfl_xor_sync(0xffffffffu, va, 1));
        va = fmaxf(va, __shfl_xor_sync(0xffffffffu, va, 2));
        vb = fmaxf(vb, __shfl_xor_sync(0xffffffffu, vb, 1));
        vb = fmaxf(vb, __shfl_xor_sync(0xffffffffu, vb, 2));

        const float mna = fmaxf(m_a, va), mnb = fmaxf(m_b, vb);
        const float aa = fast_ex2(m_a - mna), ab = fast_ex2(m_b - mnb);
        float sa = 0.f, sb = 0.f;
#pragma unroll
        for (int nt = 0; nt < 8; nt++) {
            Sf[nt][0] = fast_ex2(Sf[nt][0] - mna);
            Sf[nt][1] = fast_ex2(Sf[nt][1] - mna);
            Sf[nt][2] = fast_ex2(Sf[nt][2] - mnb);
            Sf[nt][3] = fast_ex2(Sf[nt][3] - mnb);
            sa += Sf[nt][0] + Sf[nt][1];
            sb += Sf[nt][2] + Sf[nt][3];
        }
        sa += __shfl_xor_sync(0xffffffffu, sa, 1);
        sa += __shfl_xor_sync(0xffffffffu, sa, 2);
        sb += __shfl_xor_sync(0xffffffffu, sb, 1);
        sb += __shfl_xor_sync(0xffffffffu, sb, 2);
        l_a = l_a * aa + sa;
        l_b = l_b * ab + sb;
        m_a = mna; m_b = mnb;
#pragma unroll
        for (int nt = 0; nt < 8; nt++) {
            Of[nt][0] *= aa; Of[nt][1] *= aa;
            Of[nt][2] *= ab; Of[nt][3] *= ab;
        }

        // ---- O += P V ----
#pragma unroll
        for (int kk2 = 0; kk2 < 4; kk2++) {
            uint32_t pah[4], pal[4];
            pack_hl(Sf[2*kk2][0],   Sf[2*kk2][1],   &pah[0], &pal[0]);
            pack_hl(Sf[2*kk2][2],   Sf[2*kk2][3],   &pah[1], &pal[1]);
            pack_hl(Sf[2*kk2+1][0], Sf[2*kk2+1][1], &pah[2], &pal[2]);
            pack_hl(Sf[2*kk2+1][2], Sf[2*kk2+1][3], &pah[3], &pal[3]);

            uint32_t VH[16], VL[16];
#pragma unroll
            for (int ntp = 0; ntp < 4; ntp++) {
                ldsm_x4(VH + 4*ntp, kb + 2*ATT_TSZ + offb + (uint32_t)(ntp*2304 + kk2*32));
                ldsm_x4(VL + 4*ntp, kb + 3*ATT_TSZ + offb + (uint32_t)(ntp*2304 + kk2*32));
            }
#pragma unroll
            for (int nt = 0; nt < 8; nt++)
                mma_bf16(Of[nt], pah, VH[2*nt], VH[2*nt+1]);
#pragma unroll
            for (int nt = 0; nt < 8; nt++)
                mma_bf16(Of[nt], pah, VL[2*nt], VL[2*nt+1]);
#pragma unroll
            for (int nt = 0; nt < 8; nt++)
                mma_bf16(Of[nt], pal, VH[2*nt], VH[2*nt+1]);
        }
        __syncthreads();
    }

    // ---- epilogue ----
    const float inva = 1.f / l_a, invb = 1.f / l_b;
    const int sa_row = qt*128 + w*16 + gid;
    const size_t base_a = ((size_t)(bq*SEQ + sa_row)) * EMB + hq*DHEAD + 2*tig;
    const size_t base_b = base_a + (size_t)8 * EMB;
#pragma unroll
    for (int nt = 0; nt < 8; nt++) {
        uint32_t hh, ll;
        pack_hl(Of[nt][0]*inva, Of[nt][1]*inva, &hh, &ll);
        *(uint32_t*)&Oh_g[base_a + nt*8] = hh;
        *(uint32_t*)&Ol_g[base_a + nt*8] = ll;
        pack_hl(Of[nt][2]*invb, Of[nt][3]*invb, &hh, &ll);
        *(uint32_t*)&Oh_g[base_b + nt*8] = hh;
        *(uint32_t*)&Ol_g[base_b + nt*8] = ll;
    }
}

// ---------------- launch ----------------
extern "C" void kernel_launch(void* const* d_in, const int* in_sizes, int n_in,
                              void* d_out, int out_size)
{
    (void)in_sizes; (void)n_in; (void)out_size;
    const float* x  = (const float*)d_in[0];
    const float* wq = (const float*)d_in[2];
    const float* bq = (const float*)d_in[3];
    const float* wk = (const float*)d_in[4];
    const float* bk = (const float*)d_in[5];
    const float* wv = (const float*)d_in[6];
    const float* bv = (const float*)d_in[7];
    const float* wo = (const float*)d_in[8];
    const float* bo = (const float*)d_in[9];
    float* out = (float*)d_out;

    __nv_bfloat16 *xh, *xl, *oh, *ol, *wh, *wl, *qh, *ql, *kh, *kl, *vh, *vl;
    cudaGetSymbolAddress((void**)&xh, g_xh);
    cudaGetSymbolAddress((void**)&xl, g_xl);
    cudaGetSymbolAddress((void**)&oh, g_oh);
    cudaGetSymbolAddress((void**)&ol, g_ol);
    cudaGetSymbolAddress((void**)&wh, g_wh);
    cudaGetSymbolAddress((void**)&wl, g_wl);
    cudaGetSymbolAddress((void**)&qh, g_qh);
    cudaGetSymbolAddress((void**)&ql, g_ql);
    cudaGetSymbolAddress((void**)&kh, g_kh);
    cudaGetSymbolAddress((void**)&kl, g_kl);
    cudaGetSymbolAddress((void**)&vh, g_vh);
    cudaGetSymbolAddress((void**)&vl, g_vl);

    const int W = EMB*EMB;

    split_bf16<<<(MROWS*EMB/4)/256, 256>>>(x, xh, xl, MROWS*EMB/4);
    split_bf16_w<<<dim3((W/4)/256, 4), 256>>>(wq, wk, wv, wo, wh, wl);

    cudaFuncSetAttribute(mma_gemm, cudaFuncAttributeMaxDynamicSharedMemorySize, GEMM_SMEM_DYN);
    const dim3 gGrid(NDIM/128, MROWS/128);   // (8, 64)

    mma_gemm<<<gGrid, 256, GEMM_SMEM_DYN>>>(xh, xl, wh + 0*W, wl + 0*W, bq, qh, ql, QSCALE, MODE_QKBF);
    mma_gemm<<<gGrid, 256, GEMM_SMEM_DYN>>>(xh, xl, wh + 1*W, wl + 1*W, bk, kh, kl, 1.0f,   MODE_QKBF);
    mma_gemm<<<gGrid, 256, GEMM_SMEM_DYN>>>(xh, xl, wh + 2*W, wl + 2*W, bv, vh, vl, 1.0f,   MODE_VTBF);

    cudaFuncSetAttribute(attn_mma, cudaFuncAttributeMaxDynamicSharedMemorySize, ATT_SMEM);
    attn_mma<<<dim3(SEQ/128, BATCH*HEADS), 256, ATT_SMEM>>>(qh, ql, kh, kl, vh, vl, oh, ol);

    mma_gemm<<<gGrid, 256, GEMM_SMEM_DYN>>>(oh, ol, wh + 3*W, wl + 3*W, bo, out, nullptr, 1.0f, MODE_PLAIN);
}

// round 8
// speedup vs baseline: 2.9105x; 1.2609x over previous
#include <cuda_runtime.h>
#include <cuda_fp16.h>
#include <mma.h>
#include <math.h>
#include <stdint.h>

using namespace nvcuda;

// Problem constants
#define BATCH 4
#define SEQ   2048
#define EMB   1024
#define HEADS 16
#define DHEAD 64
#define MROWS (BATCH*SEQ)   // 8192
#define KDIM  1024
#define NDIM  1024

#define MODE_PLAIN 0   // fp32 [m][n]
#define MODE_QKBF  1   // fp16 hi/lo, [bh][s][d]
#define MODE_VTBF  2   // fp16 hi only, [bh][d][s]

// 0.125 (1/sqrt(D)) * log2(e): folded into Q so softmax uses ex2 directly
#define QSCALE 0.18033688011112042f

// ---------------- scratch (device globals per allocation rules) ----------------
__device__ __half g_xh[MROWS*EMB];
__device__ __half g_xl[MROWS*EMB];
__device__ __half g_oh[MROWS*EMB];
__device__ __half g_ol[MROWS*EMB];
__device__ __half g_wh[4][EMB*EMB];
__device__ __half g_wl[4][EMB*EMB];
__device__ __half g_qh[MROWS*EMB];  // [bh][s][d]
__device__ __half g_ql[MROWS*EMB];
__device__ __half g_kh[MROWS*EMB];  // [bh][s][d]
__device__ __half g_kl[MROWS*EMB];
__device__ __half g_vh[MROWS*EMB];  // [bh][d][s] (hi only)

// ---------------- helpers ----------------
__device__ __forceinline__ uint32_t smem_to_u32(const void* p) {
    uint32_t a;
    asm("{ .reg .u64 tmp; cvta.to.shared.u64 tmp, %1; cvt.u32.u64 %0, tmp; }"
        : "=r"(a) : "l"(p));
    return a;
}
__device__ __forceinline__ void cp_async16(uint32_t dst, const void* src) {
    asm volatile("cp.async.cg.shared.global [%0], [%1], 16;" :: "r"(dst), "l"(src));
}
#define CP_COMMIT() asm volatile("cp.async.commit_group;" ::: "memory")
#define CP_WAIT0()  asm volatile("cp.async.wait_group 0;" ::: "memory")
#define CP_WAIT1()  asm volatile("cp.async.wait_group 1;" ::: "memory")

__device__ __forceinline__ float fast_ex2(float x) {
    float y;
    asm("ex2.approx.ftz.f32 %0, %1;" : "=f"(y) : "f"(x));
    return y;
}

// ldmatrix x4
__device__ __forceinline__ void ldsm_x4(uint32_t* r, uint32_t addr) {
    asm volatile("ldmatrix.sync.aligned.m8n8.x4.shared.b16 {%0,%1,%2,%3}, [%4];"
        : "=r"(r[0]), "=r"(r[1]), "=r"(r[2]), "=r"(r[3]) : "r"(addr));
}

// mma.sync m16n8k16 row.col f32.f16.f16.f32, accumulating
__device__ __forceinline__ void mma_f16(float* c, const uint32_t* a, uint32_t b0, uint32_t b1) {
    asm volatile(
        "mma.sync.aligned.m16n8k16.row.col.f32.f16.f16.f32 "
        "{%0,%1,%2,%3},{%4,%5,%6,%7},{%8,%9},{%0,%1,%2,%3};"
        : "+f"(c[0]), "+f"(c[1]), "+f"(c[2]), "+f"(c[3])
        : "r"(a[0]), "r"(a[1]), "r"(a[2]), "r"(a[3]), "r"(b0), "r"(b1));
}

// fp32 pair -> fp16 hi pair + fp16 lo pair (packed u32, first element in low half)
__device__ __forceinline__ void pack_hl(float x, float y, uint32_t* h, uint32_t* l) {
    __half2 hh = __floats2half2_rn(x, y);
    float rx = x - __half2float(__low2half(hh));
    float ry = y - __half2float(__high2half(hh));
    __half2 ll = __floats2half2_rn(rx, ry);
    *h = *(uint32_t*)&hh;
    *l = *(uint32_t*)&ll;
}

// ---------------- fp32 -> fp16 hi/lo splits ----------------
__global__ void split_f16(const float* __restrict__ in, __half* __restrict__ hi,
                          __half* __restrict__ lo, int n4)
{
    int i = blockIdx.x * blockDim.x + threadIdx.x;
    if (i >= n4) return;
    float4 v = ((const float4*)in)[i];
    uint32_t h0, l0, h1, l1;
    pack_hl(v.x, v.y, &h0, &l0);
    pack_hl(v.z, v.w, &h1, &l1);
    ((uint32_t*)hi)[2*i]   = h0; ((uint32_t*)hi)[2*i+1] = h1;
    ((uint32_t*)lo)[2*i]   = l0; ((uint32_t*)lo)[2*i+1] = l1;
}

__global__ void split_f16_w(const float* __restrict__ w0, const float* __restrict__ w1,
                            const float* __restrict__ w2, const float* __restrict__ w3,
                            __half* __restrict__ hi, __half* __restrict__ lo)
{
    const float* srcs[4] = {w0, w1, w2, w3};
    const int ws = blockIdx.y;
    const float* in = srcs[ws];
    const size_t base = (size_t)ws * (EMB*EMB);
    int i = blockIdx.x * blockDim.x + threadIdx.x;
    float4 v = ((const float4*)in)[i];
    uint32_t h0, l0, h1, l1;
    pack_hl(v.x, v.y, &h0, &l0);
    pack_hl(v.z, v.w, &h1, &l1);
    ((uint32_t*)(hi + base))[2*i]   = h0; ((uint32_t*)(hi + base))[2*i+1] = h1;
    ((uint32_t*)(lo + base))[2*i]   = l0; ((uint32_t*)(lo + base))[2*i+1] = l1;
}

// ---------------- GEMM: C = ((Ah+Al) @ (Bh[+Bl])^T + bias) * cscale ----------------
// 256 threads (8 warps, warp tile 64x32), K-chunk 32, 2 CTAs/SM.
// nterms==3: Ah*Bh + Al*Bh + Ah*Bl.  nterms==2: Ah*Bh + Al*Bh (Bl unused).
#define LDP        40                      // padded row length (fp16), 80 B stride
#define TILE_P     (128*LDP*2)             // 10240 B
#define STAGE_P    (4*TILE_P)              // 40960 B
#define GEMM_SMEM_DYN (1024 + 2*STAGE_P)   // 82944 B  -> 2 CTAs per SM

__global__ void __launch_bounds__(256, 2)
mma_gemm(const __half* __restrict__ Ah, const __half* __restrict__ Al,
         const __half* __restrict__ Bh, const __half* __restrict__ Bl,
         const float* __restrict__ bias, void* __restrict__ C0, void* __restrict__ C1,
         float cscale, int mode, int nterms)
{
    extern __shared__ __align__(1024) char smem[];
    const uint32_t smem_u = smem_to_u32(smem);
    const int t   = threadIdx.x;
    const int bm  = blockIdx.y * 128;
    const int bn  = blockIdx.x * 128;

    const int wid = t >> 5;          // 0..7
    const int m0  = (wid >> 2) * 64; // 2 warp-rows
    const int n0  = (wid & 3) * 32;  // 4 warp-cols
    const int ntiles = (nterms == 3) ? 4 : 3;

    wmma::fragment<wmma::accumulator, 16, 16, 16, float> acc[4][2];
#pragma unroll
    for (int i = 0; i < 4; i++)
#pragma unroll
        for (int j = 0; j < 2; j++) wmma::fill_fragment(acc[i][j], 0.f);

    const __half* srcs[4] = {Ah, Al, Bh, Bl};
    const int r0s[4] = {bm, bm, bn, bn};

    // load one K-chunk (32 wide): ntiles tiles of 128x32 fp16 -> rows padded to 80 B
    auto load_stage = [&](int s, int ic) {
        const uint32_t sb = smem_u + 1024 + (uint32_t)s * STAGE_P;
        const int kc = ic * 32;
#pragma unroll
        for (int tl = 0; tl < 4; tl++) {
            if (tl >= ntiles) break;
            const __half* g = srcs[tl] + (size_t)r0s[tl] * KDIM + kc;
#pragma unroll
            for (int j = 0; j < 2; j++) {
                int idx = t + j * 256;            // 0..511
                int r   = idx >> 2;               // 0..127
                int c16 = idx & 3;                // 16B chunk within 64B row
                cp_async16(sb + (uint32_t)(tl*TILE_P + r*80 + c16*16),
                           g + (size_t)r * KDIM + c16*8);
            }
        }
        CP_COMMIT();
    };

    load_stage(0, 0);

    for (int ic = 0; ic < 32; ic++) {
        if (ic + 1 < 32) load_stage((ic + 1) & 1, ic + 1);
        if (ic + 1 < 32) { CP_WAIT1(); } else { CP_WAIT0(); }
        __syncthreads();

        const char* sb = smem + 1024 + (size_t)(ic & 1) * STAGE_P;
        const __half* Ahs = (const __half*)(sb);
        const __half* Als = (const __half*)(sb + TILE_P);
        const __half* Bhs = (const __half*)(sb + 2*TILE_P);
        const __half* Bls = (const __half*)(sb + 3*TILE_P);

#pragma unroll
        for (int k0 = 0; k0 < 32; k0 += 16) {
            wmma::fragment<wmma::matrix_a, 16, 16, 16, __half, wmma::row_major> aH[4], aL[4];
            wmma::fragment<wmma::matrix_b, 16, 16, 16, __half, wmma::col_major> bF[2];
#pragma unroll
            for (int i = 0; i < 4; i++)
                wmma::load_matrix_sync(aH[i], Ahs + (m0 + 16*i) * LDP + k0, LDP);
#pragma unroll
            for (int j = 0; j < 2; j++)
                wmma::load_matrix_sync(bF[j], Bhs + (n0 + 16*j) * LDP + k0, LDP);
            // hi * hi
#pragma unroll
            for (int i = 0; i < 4; i++)
#pragma unroll
                for (int j = 0; j < 2; j++)
                    wmma::mma_sync(acc[i][j], aH[i], bF[j], acc[i][j]);
            // lo * hi
#pragma unroll
            for (int i = 0; i < 4; i++)
                wmma::load_matrix_sync(aL[i], Als + (m0 + 16*i) * LDP + k0, LDP);
#pragma unroll
            for (int i = 0; i < 4; i++)
#pragma unroll
                for (int j = 0; j < 2; j++)
                    wmma::mma_sync(acc[i][j], aL[i], bF[j], acc[i][j]);
            // hi * lo (3-term only)
            if (nterms == 3) {
#pragma unroll
                for (int j = 0; j < 2; j++)
                    wmma::load_matrix_sync(bF[j], Bls + (n0 + 16*j) * LDP + k0, LDP);
#pragma unroll
                for (int i = 0; i < 4; i++)
#pragma unroll
                    for (int j = 0; j < 2; j++)
                        wmma::mma_sync(acc[i][j], aH[i], bF[j], acc[i][j]);
            }
        }
        __syncthreads();
    }

    // Stage full fp32 tile through smem (ld=132), then scatter per mode
    float* Cs = (float*)smem;
#pragma unroll
    for (int i = 0; i < 4; i++)
#pragma unroll
        for (int j = 0; j < 2; j++)
            wmma::store_matrix_sync(Cs + (m0 + 16*i) * 132 + n0 + 16*j, acc[i][j],
                                    132, wmma::mem_row_major);
    __syncthreads();

    if (mode == MODE_PLAIN) {
        const int r  = t >> 1;
        const int c0 = (t & 1) * 64;
        const int gm = bm + r;
        float* out = (float*)C0 + (size_t)gm * NDIM + bn + c0;
        const float* row = Cs + r * 132 + c0;
        const float* bp  = bias + bn + c0;
#pragma unroll
        for (int j = 0; j < 64; j += 4)
            *(float4*)(out + j) = make_float4(row[j]   + bp[j],
                                              row[j+1] + bp[j+1],
                                              row[j+2] + bp[j+2],
                                              row[j+3] + bp[j+3]);
    } else if (mode == MODE_QKBF) {
        const int r  = t >> 1;
        const int c0 = (t & 1) * 64;          // 64-col half = one head
        const int gm = bm + r;
        const int b  = gm >> 11, sq = gm & 2047;
        const int h  = (bn + c0) >> 6;
        __half* Oh = (__half*)C0 + (((size_t)(b*HEADS + h) * SEQ + sq) * DHEAD);
        __half* Ol = (__half*)C1 + (((size_t)(b*HEADS + h) * SEQ + sq) * DHEAD);
        const float* row = Cs + r * 132 + c0;
        const float* bp  = bias + bn + c0;
#pragma unroll
        for (int j = 0; j < 64; j += 2) {
            float v0 = (row[j]   + bp[j])   * cscale;
            float v1 = (row[j+1] + bp[j+1]) * cscale;
            uint32_t hh, ll;
            pack_hl(v0, v1, &hh, &ll);
            *(uint32_t*)(Oh + j) = hh;
            *(uint32_t*)(Ol + j) = ll;
        }
    } else { // MODE_VTBF: [bh][d][s], hi only
        const int n  = t >> 1;                 // tile-local col (head-dim idx)
        const int s0 = (t & 1) * 64;
        const int gn = bn + n, h = gn >> 6, d = gn & 63;
        const int gm0 = bm + s0;
        const int b = gm0 >> 11, sq0 = gm0 & 2047;
        const float bv = bias[gn];
        __half* Oh = (__half*)C0 + (((size_t)(b*HEADS + h) * DHEAD + d) * SEQ) + sq0;
#pragma unroll 4
        for (int r = 0; r < 64; r += 2) {
            float v0 = Cs[(s0 + r)     * 132 + n] + bv;
            float v1 = Cs[(s0 + r + 1) * 132 + n] + bv;
            __half2 hh = __floats2half2_rn(v0, v1);
            *(uint32_t*)(Oh + r) = *(uint32_t*)&hh;
        }
    }
}

// ---------------- Flash attention, mma.sync fp16, QK 3-term / PV 2-term ----------------
// Q,K: [bh][s][d] hi/lo.  V: [bh][d][s] hi only.  O -> g_oh/g_ol [b][s][e] hi/lo.
#define ATT_QSZ   (128*72*2)    // 18432 B per Q buffer
#define ATT_TSZ   (64*72*2)     // 9216 B per K/V tile
#define ATT_STAGE (3*ATT_TSZ)   // 27648 B (Kh, Kl, Vh)
#define ATT_SMEM  (2*ATT_QSZ + 2*ATT_STAGE)  // 92160 B

__global__ void __launch_bounds__(256, 1)
attn_mma(const __half* __restrict__ Qh_g, const __half* __restrict__ Ql_g,
         const __half* __restrict__ Kh_g, const __half* __restrict__ Kl_g,
         const __half* __restrict__ Vh_g,
         __half* __restrict__ Oh_g, __half* __restrict__ Ol_g)
{
    extern __shared__ __align__(128) char sm_[];
    const uint32_t su = smem_to_u32(sm_);
    const int t    = threadIdx.x;
    const int w    = t >> 5;
    const int lane = t & 31;
    const int gid  = lane >> 2;
    const int tig  = lane & 3;
    const int qt   = (gridDim.x - 1) - blockIdx.x;
    const int bh   = blockIdx.y;
    const int bq   = bh >> 4, hq = bh & 15;

    const uint32_t aq_off = (uint32_t)((w*16 + (lane & 15))*144 + ((lane >> 4) * 16));
    const uint32_t offb = (uint32_t)((((lane & 7) + ((lane >> 4) << 3)) * 144) + (((lane >> 3) & 1) * 16));

    const __half* Qhg = Qh_g + ((size_t)bh * SEQ + qt * 128) * DHEAD;
    const __half* Qlg = Ql_g + ((size_t)bh * SEQ + qt * 128) * DHEAD;

#pragma unroll
    for (int j = 0; j < 4; j++) {
        int idx = t + j * 256;
        int r   = idx >> 3;
        int c   = idx & 7;
        cp_async16(su + r*144 + c*16,            Qhg + r*DHEAD + c*8);
        cp_async16(su + ATT_QSZ + r*144 + c*16,  Qlg + r*DHEAD + c*8);
    }

    auto load_kv = [&](int stg, int jt) {
        const uint32_t sb = su + 2*ATT_QSZ + (uint32_t)stg * ATT_STAGE;
#pragma unroll
        for (int j = 0; j < 2; j++) {
            int idx = t + j * 256;
            int r   = idx >> 3;
            int c   = idx & 7;
            const size_t ko = ((size_t)bh * SEQ + jt*64 + r) * DHEAD + c*8;
            cp_async16(sb +             r*144 + c*16, Kh_g + ko);
            cp_async16(sb + ATT_TSZ   + r*144 + c*16, Kl_g + ko);
            const size_t vo = ((size_t)bh * DHEAD + r) * SEQ + jt*64 + c*8;
            cp_async16(sb + 2*ATT_TSZ + r*144 + c*16, Vh_g + vo);
        }
    };

    load_kv(0, 0);
    CP_COMMIT();

    float Of[8][4];
#pragma unroll
    for (int i = 0; i < 8; i++)
#pragma unroll
        for (int j = 0; j < 4; j++) Of[i][j] = 0.f;
    float m_a = -1e30f, m_b = -1e30f, l_a = 0.f, l_b = 0.f;

    uint32_t qh[4][4], ql[4][4];

    const int jt_end = 2*qt + 1;
    const int rga = qt*128 + w*16 + gid;
    const int rgb = rga + 8;

    for (int jt = 0; jt <= jt_end; jt++) {
        if (jt < jt_end) { load_kv((jt + 1) & 1, jt + 1); CP_COMMIT(); CP_WAIT1(); }
        else             { CP_WAIT0(); }
        __syncthreads();

        if (jt == 0) {
#pragma unroll
            for (int kk = 0; kk < 4; kk++) {
                ldsm_x4(qh[kk], su + aq_off + kk*32);
                ldsm_x4(ql[kk], su + ATT_QSZ + aq_off + kk*32);
            }
        }

        const uint32_t kb = su + 2*ATT_QSZ + (uint32_t)(jt & 1) * ATT_STAGE;

        // ---- S = Q K^T (3-term) ----
        float Sf[8][4];
#pragma unroll
        for (int i = 0; i < 8; i++)
#pragma unroll
            for (int j = 0; j < 4; j++) Sf[i][j] = 0.f;

#pragma unroll
        for (int kk = 0; kk < 4; kk++) {
            uint32_t KH[16], KL[16];
#pragma unroll
            for (int ntp = 0; ntp < 4; ntp++) {
                ldsm_x4(KH + 4*ntp, kb + offb + (uint32_t)(ntp*2304 + kk*32));
                ldsm_x4(KL + 4*ntp, kb + ATT_TSZ + offb + (uint32_t)(ntp*2304 + kk*32));
            }
#pragma unroll
            for (int nt = 0; nt < 8; nt++)
                mma_f16(Sf[nt], qh[kk], KH[2*nt], KH[2*nt+1]);
#pragma unroll
            for (int nt = 0; nt < 8; nt++)
                mma_f16(Sf[nt], qh[kk], KL[2*nt], KL[2*nt+1]);
#pragma unroll
            for (int nt = 0; nt < 8; nt++)
                mma_f16(Sf[nt], ql[kk], KH[2*nt], KH[2*nt+1]);
        }

        // ---- causal mask ----
        if (jt >= 2*qt) {
#pragma unroll
            for (int nt = 0; nt < 8; nt++) {
                const int cg = jt*64 + nt*8 + 2*tig;
                if (cg     > rga) Sf[nt][0] = -1e30f;
                if (cg + 1 > rga) Sf[nt][1] = -1e30f;
                if (cg     > rgb) Sf[nt][2] = -1e30f;
                if (cg + 1 > rgb) Sf[nt][3] = -1e30f;
            }
        }

        // ---- online softmax (base-2) ----
        float va = -1e30f, vb = -1e30f;
#pragma unroll
        for (int nt = 0; nt < 8; nt++) {
            va = fmaxf(va, fmaxf(Sf[nt][0], Sf[nt][1]));
            vb = fmaxf(vb, fmaxf(Sf[nt][2], Sf[nt][3]));
        }
        va = fmaxf(va, __shfl_xor_sync(0xffffffffu, va, 1));
        va = fmaxf(va, __shfl_xor_sync(0xffffffffu, va, 2));
        vb = fmaxf(vb, __shfl_xor_sync(0xffffffffu, vb, 1));
        vb = fmaxf(vb, __shfl_xor_sync(0xffffffffu, vb, 2));

        const float mna = fmaxf(m_a, va), mnb = fmaxf(m_b, vb);
        const float aa = fast_ex2(m_a - mna), ab = fast_ex2(m_b - mnb);
        float sa = 0.f, sb = 0.f;
#pragma unroll
        for (int nt = 0; nt < 8; nt++) {
            Sf[nt][0] = fast_ex2(Sf[nt][0] - mna);
            Sf[nt][1] = fast_ex2(Sf[nt][1] - mna);
            Sf[nt][2] = fast_ex2(Sf[nt][2] - mnb);
            Sf[nt][3] = fast_ex2(Sf[nt][3] - mnb);
            sa += Sf[nt][0] + Sf[nt][1];
            sb += Sf[nt][2] + Sf[nt][3];
        }
        sa += __shfl_xor_sync(0xffffffffu, sa, 1);
        sa += __shfl_xor_sync(0xffffffffu, sa, 2);
        sb += __shfl_xor_sync(0xffffffffu, sb, 1);
        sb += __shfl_xor_sync(0xffffffffu, sb, 2);
        l_a = l_a * aa + sa;
        l_b = l_b * ab + sb;
        m_a = mna; m_b = mnb;
#pragma unroll
        for (int nt = 0; nt < 8; nt++) {
            Of[nt][0] *= aa; Of[nt][1] *= aa;
            Of[nt][2] *= ab; Of[nt][3] *= ab;
        }

        // ---- O += P V (2-term: Ph*Vh + Pl*Vh) ----
#pragma unroll
        for (int kk2 = 0; kk2 < 4; kk2++) {
            uint32_t pah[4], pal[4];
            pack_hl(Sf[2*kk2][0],   Sf[2*kk2][1],   &pah[0], &pal[0]);
            pack_hl(Sf[2*kk2][2],   Sf[2*kk2][3],   &pah[1], &pal[1]);
            pack_hl(Sf[2*kk2+1][0], Sf[2*kk2+1][1], &pah[2], &pal[2]);
            pack_hl(Sf[2*kk2+1][2], Sf[2*kk2+1][3], &pah[3], &pal[3]);

            uint32_t VH[16];
#pragma unroll
            for (int ntp = 0; ntp < 4; ntp++)
                ldsm_x4(VH + 4*ntp, kb + 2*ATT_TSZ + offb + (uint32_t)(ntp*2304 + kk2*32));
#pragma unroll
            for (int nt = 0; nt < 8; nt++)
                mma_f16(Of[nt], pah, VH[2*nt], VH[2*nt+1]);
#pragma unroll
            for (int nt = 0; nt < 8; nt++)
                mma_f16(Of[nt], pal, VH[2*nt], VH[2*nt+1]);
        }
        __syncthreads();
    }

    // ---- epilogue ----
    const float inva = 1.f / l_a, invb = 1.f / l_b;
    const int sa_row = qt*128 + w*16 + gid;
    const size_t base_a = ((size_t)(bq*SEQ + sa_row)) * EMB + hq*DHEAD + 2*tig;
    const size_t base_b = base_a + (size_t)8 * EMB;
#pragma unroll
    for (int nt = 0; nt < 8; nt++) {
        uint32_t hh, ll;
        pack_hl(Of[nt][0]*inva, Of[nt][1]*inva, &hh, &ll);
        *(uint32_t*)&Oh_g[base_a + nt*8] = hh;
        *(uint32_t*)&Ol_g[base_a + nt*8] = ll;
        pack_hl(Of[nt][2]*invb, Of[nt][3]*invb, &hh, &ll);
        *(uint32_t*)&Oh_g[base_b + nt*8] = hh;
        *(uint32_t*)&Ol_g[base_b + nt*8] = ll;
    }
}

// ---------------- launch ----------------
extern "C" void kernel_launch(void* const* d_in, const int* in_sizes, int n_in,
                              void* d_out, int out_size)
{
    (void)in_sizes; (void)n_in; (void)out_size;
    const float* x  = (const float*)d_in[0];
    const float* wq = (const float*)d_in[2];
    const float* bq = (const float*)d_in[3];
    const float* wk = (const float*)d_in[4];
    const float* bk = (const float*)d_in[5];
    const float* wv = (const float*)d_in[6];
    const float* bv = (const float*)d_in[7];
    const float* wo = (const float*)d_in[8];
    const float* bo = (const float*)d_in[9];
    float* out = (float*)d_out;

    __half *xh, *xl, *oh, *ol, *wh, *wl, *qh, *ql, *kh, *kl, *vh;
    cudaGetSymbolAddress((void**)&xh, g_xh);
    cudaGetSymbolAddress((void**)&xl, g_xl);
    cudaGetSymbolAddress((void**)&oh, g_oh);
    cudaGetSymbolAddress((void**)&ol, g_ol);
    cudaGetSymbolAddress((void**)&wh, g_wh);
    cudaGetSymbolAddress((void**)&wl, g_wl);
    cudaGetSymbolAddress((void**)&qh, g_qh);
    cudaGetSymbolAddress((void**)&ql, g_ql);
    cudaGetSymbolAddress((void**)&kh, g_kh);
    cudaGetSymbolAddress((void**)&kl, g_kl);
    cudaGetSymbolAddress((void**)&vh, g_vh);

    const int W = EMB*EMB;

    split_f16<<<(MROWS*EMB/4)/256, 256>>>(x, xh, xl, MROWS*EMB/4);
    split_f16_w<<<dim3((W/4)/256, 4), 256>>>(wq, wk, wv, wo, wh, wl);

    cudaFuncSetAttribute(mma_gemm, cudaFuncAttributeMaxDynamicSharedMemorySize, GEMM_SMEM_DYN);
    const dim3 gGrid(NDIM/128, MROWS/128);   // (8, 64)

    // Q, K projections: 3-term (feed the softmax exponent). V: 2-term, hi-only out.
    mma_gemm<<<gGrid, 256, GEMM_SMEM_DYN>>>(xh, xl, wh + 0*W, wl + 0*W, bq, qh, ql, QSCALE, MODE_QKBF, 3);
    mma_gemm<<<gGrid, 256, GEMM_SMEM_DYN>>>(xh, xl, wh + 1*W, wl + 1*W, bk, kh, kl, 1.0f,   MODE_QKBF, 3);
    mma_gemm<<<gGrid, 256, GEMM_SMEM_DYN>>>(xh, xl, wh + 2*W, wl + 2*W, bv, vh, nullptr, 1.0f, MODE_VTBF, 2);

    cudaFuncSetAttribute(attn_mma, cudaFuncAttributeMaxDynamicSharedMemorySize, ATT_SMEM);
    attn_mma<<<dim3(SEQ/128, BATCH*HEADS), 256, ATT_SMEM>>>(qh, ql, kh, kl, vh, oh, ol);

    // out-projection: 2-term
    mma_gemm<<<gGrid, 256, GEMM_SMEM_DYN>>>(oh, ol, wh + 3*W, wl + 3*W, bo, out, nullptr, 1.0f, MODE_PLAIN, 2);
}

// round 9
// speedup vs baseline: 3.4773x; 1.1947x over previous
#include <cuda_runtime.h>
#include <cuda_fp16.h>
#include <mma.h>
#include <math.h>
#include <stdint.h>

using namespace nvcuda;

// Problem constants
#define BATCH 4
#define SEQ   2048
#define EMB   1024
#define HEADS 16
#define DHEAD 64
#define MROWS (BATCH*SEQ)   // 8192
#define KDIM  1024
#define NDIM  1024

#define MODE_PLAIN 0   // fp32 [m][n]
#define MODE_QKBF  1   // fp16 hi(/lo), [bh][s][d]
#define MODE_VTBF  2   // fp16 hi only, [bh][d][s]

// 0.125 (1/sqrt(D)) * log2(e): folded into Q so softmax uses ex2 directly
#define QSCALE 0.18033688011112042f

// ---------------- scratch (device globals per allocation rules) ----------------
__device__ __half g_xh[MROWS*EMB];
__device__ __half g_xl[MROWS*EMB];
__device__ __half g_oh[MROWS*EMB];
__device__ __half g_ol[MROWS*EMB];
__device__ __half g_wh[4][EMB*EMB];
__device__ __half g_wl[4][EMB*EMB];
__device__ __half g_qh[MROWS*EMB];  // [bh][s][d]
__device__ __half g_ql[MROWS*EMB];
__device__ __half g_kh[MROWS*EMB];  // [bh][s][d] (hi only)
__device__ __half g_vh[MROWS*EMB];  // [bh][d][s] (hi only)

// ---------------- helpers ----------------
__device__ __forceinline__ uint32_t smem_to_u32(const void* p) {
    uint32_t a;
    asm("{ .reg .u64 tmp; cvta.to.shared.u64 tmp, %1; cvt.u32.u64 %0, tmp; }"
        : "=r"(a) : "l"(p));
    return a;
}
__device__ __forceinline__ void cp_async16(uint32_t dst, const void* src) {
    asm volatile("cp.async.cg.shared.global [%0], [%1], 16;" :: "r"(dst), "l"(src));
}
#define CP_COMMIT() asm volatile("cp.async.commit_group;" ::: "memory")
#define CP_WAIT0()  asm volatile("cp.async.wait_group 0;" ::: "memory")
#define CP_WAIT1()  asm volatile("cp.async.wait_group 1;" ::: "memory")

__device__ __forceinline__ float fast_ex2(float x) {
    float y;
    asm("ex2.approx.ftz.f32 %0, %1;" : "=f"(y) : "f"(x));
    return y;
}

// ldmatrix x4
__device__ __forceinline__ void ldsm_x4(uint32_t* r, uint32_t addr) {
    asm volatile("ldmatrix.sync.aligned.m8n8.x4.shared.b16 {%0,%1,%2,%3}, [%4];"
        : "=r"(r[0]), "=r"(r[1]), "=r"(r[2]), "=r"(r[3]) : "r"(addr));
}

// mma.sync m16n8k16 row.col f32.f16.f16.f32, accumulating
__device__ __forceinline__ void mma_f16(float* c, const uint32_t* a, uint32_t b0, uint32_t b1) {
    asm volatile(
        "mma.sync.aligned.m16n8k16.row.col.f32.f16.f16.f32 "
        "{%0,%1,%2,%3},{%4,%5,%6,%7},{%8,%9},{%0,%1,%2,%3};"
        : "+f"(c[0]), "+f"(c[1]), "+f"(c[2]), "+f"(c[3])
        : "r"(a[0]), "r"(a[1]), "r"(a[2]), "r"(a[3]), "r"(b0), "r"(b1));
}

// fp32 pair -> fp16 hi pair + fp16 lo pair (packed u32, first element in low half)
__device__ __forceinline__ void pack_hl(float x, float y, uint32_t* h, uint32_t* l) {
    __half2 hh = __floats2half2_rn(x, y);
    float rx = x - __half2float(__low2half(hh));
    float ry = y - __half2float(__high2half(hh));
    __half2 ll = __floats2half2_rn(rx, ry);
    *h = *(uint32_t*)&hh;
    *l = *(uint32_t*)&ll;
}

// ---------------- fp32 -> fp16 hi/lo splits ----------------
__global__ void split_f16(const float* __restrict__ in, __half* __restrict__ hi,
                          __half* __restrict__ lo, int n4)
{
    int i = blockIdx.x * blockDim.x + threadIdx.x;
    if (i >= n4) return;
    float4 v = ((const float4*)in)[i];
    uint32_t h0, l0, h1, l1;
    pack_hl(v.x, v.y, &h0, &l0);
    pack_hl(v.z, v.w, &h1, &l1);
    ((uint32_t*)hi)[2*i]   = h0; ((uint32_t*)hi)[2*i+1] = h1;
    ((uint32_t*)lo)[2*i]   = l0; ((uint32_t*)lo)[2*i+1] = l1;
}

__global__ void split_f16_w(const float* __restrict__ w0, const float* __restrict__ w1,
                            const float* __restrict__ w2, const float* __restrict__ w3,
                            __half* __restrict__ hi, __half* __restrict__ lo)
{
    const float* srcs[4] = {w0, w1, w2, w3};
    const int ws = blockIdx.y;
    const float* in = srcs[ws];
    const size_t base = (size_t)ws * (EMB*EMB);
    int i = blockIdx.x * blockDim.x + threadIdx.x;
    float4 v = ((const float4*)in)[i];
    uint32_t h0, l0, h1, l1;
    pack_hl(v.x, v.y, &h0, &l0);
    pack_hl(v.z, v.w, &h1, &l1);
    ((uint32_t*)(hi + base))[2*i]   = h0; ((uint32_t*)(hi + base))[2*i+1] = h1;
    ((uint32_t*)(lo + base))[2*i]   = l0; ((uint32_t*)(lo + base))[2*i+1] = l1;
}

// ---------------- GEMM: C = ((Ah+Al) @ Bh^T + bias) * cscale  (2-term) ----------------
// 256 threads (8 warps, warp tile 64x32), K-chunk 32, 2 CTAs/SM. 3 smem tiles/stage.
#define LDP        40                      // padded row length (fp16), 80 B stride
#define TILE_P     (128*LDP*2)             // 10240 B
#define STAGE_P    (3*TILE_P)              // 30720 B (Ah, Al, Bh)
#define GEMM_SMEM_DYN 68608                // >= max(1024+2*STAGE_P=62464, epilogue 128*132*4=67584)

__global__ void __launch_bounds__(256, 2)
mma_gemm(const __half* __restrict__ Ah, const __half* __restrict__ Al,
         const __half* __restrict__ Bh,
         const float* __restrict__ bias, void* __restrict__ C0, void* __restrict__ C1,
         float cscale, int mode)
{
    extern __shared__ __align__(1024) char smem[];
    const uint32_t smem_u = smem_to_u32(smem);
    const int t   = threadIdx.x;
    const int bm  = blockIdx.y * 128;
    const int bn  = blockIdx.x * 128;

    const int wid = t >> 5;          // 0..7
    const int m0  = (wid >> 2) * 64; // 2 warp-rows
    const int n0  = (wid & 3) * 32;  // 4 warp-cols

    wmma::fragment<wmma::accumulator, 16, 16, 16, float> acc[4][2];
#pragma unroll
    for (int i = 0; i < 4; i++)
#pragma unroll
        for (int j = 0; j < 2; j++) wmma::fill_fragment(acc[i][j], 0.f);

    const __half* srcs[3] = {Ah, Al, Bh};
    const int r0s[3] = {bm, bm, bn};

    // load one K-chunk (32 wide): 3 tiles of 128x32 fp16 -> rows padded to 80 B
    auto load_stage = [&](int s, int ic) {
        const uint32_t sb = smem_u + 1024 + (uint32_t)s * STAGE_P;
        const int kc = ic * 32;
#pragma unroll
        for (int tl = 0; tl < 3; tl++) {
            const __half* g = srcs[tl] + (size_t)r0s[tl] * KDIM + kc;
#pragma unroll
            for (int j = 0; j < 2; j++) {
                int idx = t + j * 256;            // 0..511
                int r   = idx >> 2;               // 0..127
                int c16 = idx & 3;                // 16B chunk within 64B row
                cp_async16(sb + (uint32_t)(tl*TILE_P + r*80 + c16*16),
                           g + (size_t)r * KDIM + c16*8);
            }
        }
        CP_COMMIT();
    };

    load_stage(0, 0);

    for (int ic = 0; ic < 32; ic++) {
        if (ic + 1 < 32) load_stage((ic + 1) & 1, ic + 1);
        if (ic + 1 < 32) { CP_WAIT1(); } else { CP_WAIT0(); }
        __syncthreads();

        const char* sb = smem + 1024 + (size_t)(ic & 1) * STAGE_P;
        const __half* Ahs = (const __half*)(sb);
        const __half* Als = (const __half*)(sb + TILE_P);
        const __half* Bhs = (const __half*)(sb + 2*TILE_P);

#pragma unroll
        for (int k0 = 0; k0 < 32; k0 += 16) {
            wmma::fragment<wmma::matrix_a, 16, 16, 16, __half, wmma::row_major> aH[4], aL[4];
            wmma::fragment<wmma::matrix_b, 16, 16, 16, __half, wmma::col_major> bF[2];
#pragma unroll
            for (int i = 0; i < 4; i++)
                wmma::load_matrix_sync(aH[i], Ahs + (m0 + 16*i) * LDP + k0, LDP);
#pragma unroll
            for (int j = 0; j < 2; j++)
                wmma::load_matrix_sync(bF[j], Bhs + (n0 + 16*j) * LDP + k0, LDP);
            // hi * hi
#pragma unroll
            for (int i = 0; i < 4; i++)
#pragma unroll
                for (int j = 0; j < 2; j++)
                    wmma::mma_sync(acc[i][j], aH[i], bF[j], acc[i][j]);
            // lo * hi
#pragma unroll
            for (int i = 0; i < 4; i++)
                wmma::load_matrix_sync(aL[i], Als + (m0 + 16*i) * LDP + k0, LDP);
#pragma unroll
            for (int i = 0; i < 4; i++)
#pragma unroll
                for (int j = 0; j < 2; j++)
                    wmma::mma_sync(acc[i][j], aL[i], bF[j], acc[i][j]);
        }
        __syncthreads();
    }

    // Stage full fp32 tile through smem (ld=132), then scatter per mode
    float* Cs = (float*)smem;
#pragma unroll
    for (int i = 0; i < 4; i++)
#pragma unroll
        for (int j = 0; j < 2; j++)
            wmma::store_matrix_sync(Cs + (m0 + 16*i) * 132 + n0 + 16*j, acc[i][j],
                                    132, wmma::mem_row_major);
    __syncthreads();

    if (mode == MODE_PLAIN) {
        const int r  = t >> 1;
        const int c0 = (t & 1) * 64;
        const int gm = bm + r;
        float* out = (float*)C0 + (size_t)gm * NDIM + bn + c0;
        const float* row = Cs + r * 132 + c0;
        const float* bp  = bias + bn + c0;
#pragma unroll
        for (int j = 0; j < 64; j += 4)
            *(float4*)(out + j) = make_float4(row[j]   + bp[j],
                                              row[j+1] + bp[j+1],
                                              row[j+2] + bp[j+2],
                                              row[j+3] + bp[j+3]);
    } else if (mode == MODE_QKBF) {
        const int r  = t >> 1;
        const int c0 = (t & 1) * 64;          // 64-col half = one head
        const int gm = bm + r;
        const int b  = gm >> 11, sq = gm & 2047;
        const int h  = (bn + c0) >> 6;
        __half* Oh = (__half*)C0 + (((size_t)(b*HEADS + h) * SEQ + sq) * DHEAD);
        __half* Ol = (C1 != nullptr)
            ? (__half*)C1 + (((size_t)(b*HEADS + h) * SEQ + sq) * DHEAD) : nullptr;
        const float* row = Cs + r * 132 + c0;
        const float* bp  = bias + bn + c0;
#pragma unroll
        for (int j = 0; j < 64; j += 2) {
            float v0 = (row[j]   + bp[j])   * cscale;
            float v1 = (row[j+1] + bp[j+1]) * cscale;
            uint32_t hh, ll;
            pack_hl(v0, v1, &hh, &ll);
            *(uint32_t*)(Oh + j) = hh;
            if (Ol) *(uint32_t*)(Ol + j) = ll;
        }
    } else { // MODE_VTBF: [bh][d][s], hi only
        const int n  = t >> 1;                 // tile-local col (head-dim idx)
        const int s0 = (t & 1) * 64;
        const int gn = bn + n, h = gn >> 6, d = gn & 63;
        const int gm0 = bm + s0;
        const int b = gm0 >> 11, sq0 = gm0 & 2047;
        const float bv = bias[gn];
        __half* Oh = (__half*)C0 + (((size_t)(b*HEADS + h) * DHEAD + d) * SEQ) + sq0;
#pragma unroll 4
        for (int r = 0; r < 64; r += 2) {
            float v0 = Cs[(s0 + r)     * 132 + n] + bv;
            float v1 = Cs[(s0 + r + 1) * 132 + n] + bv;
            __half2 hh = __floats2half2_rn(v0, v1);
            *(uint32_t*)(Oh + r) = *(uint32_t*)&hh;
        }
    }
}

// ---------------- Flash attention, mma.sync fp16, QK 2-term / PV 2-term ----------------
// Q: [bh][s][d] hi/lo.  K: [bh][s][d] hi.  V: [bh][d][s] hi.  O -> g_oh/g_ol hi/lo.
#define ATT_QSZ   (128*72*2)    // 18432 B per Q buffer
#define ATT_TSZ   (64*72*2)     // 9216 B per K/V tile
#define ATT_STAGE (2*ATT_TSZ)   // 18432 B (Kh, Vh)
#define ATT_SMEM  (2*ATT_QSZ + 2*ATT_STAGE)  // 73728 B

__global__ void __launch_bounds__(256, 1)
attn_mma(const __half* __restrict__ Qh_g, const __half* __restrict__ Ql_g,
         const __half* __restrict__ Kh_g, const __half* __restrict__ Vh_g,
         __half* __restrict__ Oh_g, __half* __restrict__ Ol_g)
{
    extern __shared__ __align__(128) char sm_[];
    const uint32_t su = smem_to_u32(sm_);
    const int t    = threadIdx.x;
    const int w    = t >> 5;
    const int lane = t & 31;
    const int gid  = lane >> 2;
    const int tig  = lane & 3;
    const int qt   = (gridDim.x - 1) - blockIdx.x;
    const int bh   = blockIdx.y;
    const int bq   = bh >> 4, hq = bh & 15;

    const uint32_t aq_off = (uint32_t)((w*16 + (lane & 15))*144 + ((lane >> 4) * 16));
    const uint32_t offb = (uint32_t)((((lane & 7) + ((lane >> 4) << 3)) * 144) + (((lane >> 3) & 1) * 16));

    const __half* Qhg = Qh_g + ((size_t)bh * SEQ + qt * 128) * DHEAD;
    const __half* Qlg = Ql_g + ((size_t)bh * SEQ + qt * 128) * DHEAD;

#pragma unroll
    for (int j = 0; j < 4; j++) {
        int idx = t + j * 256;
        int r   = idx >> 3;
        int c   = idx & 7;
        cp_async16(su + r*144 + c*16,            Qhg + r*DHEAD + c*8);
        cp_async16(su + ATT_QSZ + r*144 + c*16,  Qlg + r*DHEAD + c*8);
    }

    auto load_kv = [&](int stg, int jt) {
        const uint32_t sb = su + 2*ATT_QSZ + (uint32_t)stg * ATT_STAGE;
#pragma unroll
        for (int j = 0; j < 2; j++) {
            int idx = t + j * 256;
            int r   = idx >> 3;
            int c   = idx & 7;
            const size_t ko = ((size_t)bh * SEQ + jt*64 + r) * DHEAD + c*8;
            cp_async16(sb +           r*144 + c*16, Kh_g + ko);
            const size_t vo = ((size_t)bh * DHEAD + r) * SEQ + jt*64 + c*8;
            cp_async16(sb + ATT_TSZ + r*144 + c*16, Vh_g + vo);
        }
    };

    load_kv(0, 0);
    CP_COMMIT();

    float Of[8][4];
#pragma unroll
    for (int i = 0; i < 8; i++)
#pragma unroll
        for (int j = 0; j < 4; j++) Of[i][j] = 0.f;
    float m_a = -1e30f, m_b = -1e30f, l_a = 0.f, l_b = 0.f;

    uint32_t qh[4][4], ql[4][4];

    const int jt_end = 2*qt + 1;
    const int rga = qt*128 + w*16 + gid;
    const int rgb = rga + 8;

    for (int jt = 0; jt <= jt_end; jt++) {
        if (jt < jt_end) { load_kv((jt + 1) & 1, jt + 1); CP_COMMIT(); CP_WAIT1(); }
        else             { CP_WAIT0(); }
        __syncthreads();

        if (jt == 0) {
#pragma unroll
            for (int kk = 0; kk < 4; kk++) {
                ldsm_x4(qh[kk], su + aq_off + kk*32);
                ldsm_x4(ql[kk], su + ATT_QSZ + aq_off + kk*32);
            }
        }

        const uint32_t kb = su + 2*ATT_QSZ + (uint32_t)(jt & 1) * ATT_STAGE;

        // ---- S = Q K^T (2-term: (qh+ql)·Kh) ----
        float Sf[8][4];
#pragma unroll
        for (int i = 0; i < 8; i++)
#pragma unroll
            for (int j = 0; j < 4; j++) Sf[i][j] = 0.f;

#pragma unroll
        for (int kk = 0; kk < 4; kk++) {
            uint32_t KH[16];
#pragma unroll
            for (int ntp = 0; ntp < 4; ntp++)
                ldsm_x4(KH + 4*ntp, kb + offb + (uint32_t)(ntp*2304 + kk*32));
#pragma unroll
            for (int nt = 0; nt < 8; nt++)
                mma_f16(Sf[nt], qh[kk], KH[2*nt], KH[2*nt+1]);
#pragma unroll
            for (int nt = 0; nt < 8; nt++)
                mma_f16(Sf[nt], ql[kk], KH[2*nt], KH[2*nt+1]);
        }

        // ---- causal mask ----
        if (jt >= 2*qt) {
#pragma unroll
            for (int nt = 0; nt < 8; nt++) {
                const int cg = jt*64 + nt*8 + 2*tig;
                if (cg     > rga) Sf[nt][0] = -1e30f;
                if (cg + 1 > rga) Sf[nt][1] = -1e30f;
                if (cg     > rgb) Sf[nt][2] = -1e30f;
                if (cg + 1 > rgb) Sf[nt][3] = -1e30f;
            }
        }

        // ---- online softmax (base-2) ----
        float va = -1e30f, vb = -1e30f;
#pragma unroll
        for (int nt = 0; nt < 8; nt++) {
            va = fmaxf(va, fmaxf(Sf[nt][0], Sf[nt][1]));
            vb = fmaxf(vb, fmaxf(Sf[nt][2], Sf[nt][3]));
        }
        va = fmaxf(va, __shfl_xor_sync(0xffffffffu, va, 1));
        va = fmaxf(va, __shfl_xor_sync(0xffffffffu, va, 2));
        vb = fmaxf(vb, __shfl_xor_sync(0xffffffffu, vb, 1));
        vb = fmaxf(vb, __shfl_xor_sync(0xffffffffu, vb, 2));

        const float mna = fmaxf(m_a, va), mnb = fmaxf(m_b, vb);
        const float aa = fast_ex2(m_a - mna), ab = fast_ex2(m_b - mnb);
        float sa = 0.f, sb = 0.f;
#pragma unroll
        for (int nt = 0; nt < 8; nt++) {
            Sf[nt][0] = fast_ex2(Sf[nt][0] - mna);
            Sf[nt][1] = fast_ex2(Sf[nt][1] - mna);
            Sf[nt][2] = fast_ex2(Sf[nt][2] - mnb);
            Sf[nt][3] = fast_ex2(Sf[nt][3] - mnb);
            sa += Sf[nt][0] + Sf[nt][1];
            sb += Sf[nt][2] + Sf[nt][3];
        }
        sa += __shfl_xor_sync(0xffffffffu, sa, 1);
        sa += __shfl_xor_sync(0xffffffffu, sa, 2);
        sb += __shfl_xor_sync(0xffffffffu, sb, 1);
        sb += __shfl_xor_sync(0xffffffffu, sb, 2);
        l_a = l_a * aa + sa;
        l_b = l_b * ab + sb;
        m_a = mna; m_b = mnb;
#pragma unroll
        for (int nt = 0; nt < 8; nt++) {
            Of[nt][0] *= aa; Of[nt][1] *= aa;
            Of[nt][2] *= ab; Of[nt][3] *= ab;
        }

        // ---- O += P V (2-term: (Ph+Pl)·Vh) ----
#pragma unroll
        for (int kk2 = 0; kk2 < 4; kk2++) {
            uint32_t pah[4], pal[4];
            pack_hl(Sf[2*kk2][0],   Sf[2*kk2][1],   &pah[0], &pal[0]);
            pack_hl(Sf[2*kk2][2],   Sf[2*kk2][3],   &pah[1], &pal[1]);
            pack_hl(Sf[2*kk2+1][0], Sf[2*kk2+1][1], &pah[2], &pal[2]);
            pack_hl(Sf[2*kk2+1][2], Sf[2*kk2+1][3], &pah[3], &pal[3]);

            uint32_t VH[16];
#pragma unroll
            for (int ntp = 0; ntp < 4; ntp++)
                ldsm_x4(VH + 4*ntp, kb + ATT_TSZ + offb + (uint32_t)(ntp*2304 + kk2*32));
#pragma unroll
            for (int nt = 0; nt < 8; nt++)
                mma_f16(Of[nt], pah, VH[2*nt], VH[2*nt+1]);
#pragma unroll
            for (int nt = 0; nt < 8; nt++)
                mma_f16(Of[nt], pal, VH[2*nt], VH[2*nt+1]);
        }
        __syncthreads();
    }

    // ---- epilogue ----
    const float inva = 1.f / l_a, invb = 1.f / l_b;
    const int sa_row = qt*128 + w*16 + gid;
    const size_t base_a = ((size_t)(bq*SEQ + sa_row)) * EMB + hq*DHEAD + 2*tig;
    const size_t base_b = base_a + (size_t)8 * EMB;
#pragma unroll
    for (int nt = 0; nt < 8; nt++) {
        uint32_t hh, ll;
        pack_hl(Of[nt][0]*inva, Of[nt][1]*inva, &hh, &ll);
        *(uint32_t*)&Oh_g[base_a + nt*8] = hh;
        *(uint32_t*)&Ol_g[base_a + nt*8] = ll;
        pack_hl(Of[nt][2]*invb, Of[nt][3]*invb, &hh, &ll);
        *(uint32_t*)&Oh_g[base_b + nt*8] = hh;
        *(uint32_t*)&Ol_g[base_b + nt*8] = ll;
    }
}

// ---------------- launch ----------------
extern "C" void kernel_launch(void* const* d_in, const int* in_sizes, int n_in,
                              void* d_out, int out_size)
{
    (void)in_sizes; (void)n_in; (void)out_size;
    const float* x  = (const float*)d_in[0];
    const float* wq = (const float*)d_in[2];
    const float* bq = (const float*)d_in[3];
    const float* wk = (const float*)d_in[4];
    const float* bk = (const float*)d_in[5];
    const float* wv = (const float*)d_in[6];
    const float* bv = (const float*)d_in[7];
    const float* wo = (const float*)d_in[8];
    const float* bo = (const float*)d_in[9];
    float* out = (float*)d_out;

    __half *xh, *xl, *oh, *ol, *wh, *wl, *qh, *ql, *kh, *vh;
    cudaGetSymbolAddress((void**)&xh, g_xh);
    cudaGetSymbolAddress((void**)&xl, g_xl);
    cudaGetSymbolAddress((void**)&oh, g_oh);
    cudaGetSymbolAddress((void**)&ol, g_ol);
    cudaGetSymbolAddress((void**)&wh, g_wh);
    cudaGetSymbolAddress((void**)&wl, g_wl);
    cudaGetSymbolAddress((void**)&qh, g_qh);
    cudaGetSymbolAddress((void**)&ql, g_ql);
    cudaGetSymbolAddress((void**)&kh, g_kh);
    cudaGetSymbolAddress((void**)&vh, g_vh);

    const int W = EMB*EMB;

    split_f16<<<(MROWS*EMB/4)/256, 256>>>(x, xh, xl, MROWS*EMB/4);
    split_f16_w<<<dim3((W/4)/256, 4), 256>>>(wq, wk, wv, wo, wh, wl);

    cudaFuncSetAttribute(mma_gemm, cudaFuncAttributeMaxDynamicSharedMemorySize, GEMM_SMEM_DYN);
    const dim3 gGrid(NDIM/128, MROWS/128);   // (8, 64)

    // All projections 2-term. Q keeps hi/lo (lo feeds QK); K, V hi-only.
    mma_gemm<<<gGrid, 256, GEMM_SMEM_DYN>>>(xh, xl, wh + 0*W, bq, qh, ql,      QSCALE, MODE_QKBF);
    mma_gemm<<<gGrid, 256, GEMM_SMEM_DYN>>>(xh, xl, wh + 1*W, bk, kh, nullptr, 1.0f,   MODE_QKBF);
    mma_gemm<<<gGrid, 256, GEMM_SMEM_DYN>>>(xh, xl, wh + 2*W, bv, vh, nullptr, 1.0f,   MODE_VTBF);

    cudaFuncSetAttribute(attn_mma, cudaFuncAttributeMaxDynamicSharedMemorySize, ATT_SMEM);
    attn_mma<<<dim3(SEQ/128, BATCH*HEADS), 256, ATT_SMEM>>>(qh, ql, kh, vh, oh, ol);

    // out-projection: 2-term
    mma_gemm<<<gGrid, 256, GEMM_SMEM_DYN>>>(oh, ol, wh + 3*W, bo, out, nullptr, 1.0f, MODE_PLAIN);
}